// round 1
// baseline (speedup 1.0000x reference)
#include <cuda_runtime.h>

#define BN 8
#define CIN 512
#define COUT 256
#define HW 64
#define OBR 129
#define OBP 132
#define FHW 128

// Scratch (no dynamic allocation allowed)
__device__ float g_s[BN * CIN];                          // modulation scales s[b][ic]
__device__ float g_w[(size_t)BN * COUT * CIN * 9];       // demodulated weights  (37.7 MB)
__device__ float g_ob[(size_t)BN * COUT * OBR * OBP];    // conv-transpose out   (139.5 MB)

// ---------------------------------------------------------------------------
// K0: s[b][ic] = (style[b] . mod_w[ic]) / sqrt(512) + mod_b[ic]
// ---------------------------------------------------------------------------
__global__ void k0_style(const float* __restrict__ style,
                         const float* __restrict__ mod_w,
                         const float* __restrict__ mod_b) {
    int b = blockIdx.x, ic = threadIdx.x;
    __shared__ float st[CIN];
    st[ic] = style[b * CIN + ic] * 0.04419417382415922f;  // 1/sqrt(512)
    __syncthreads();
    const float* mw = mod_w + (size_t)ic * CIN;
    float acc = 0.f;
#pragma unroll 8
    for (int j = 0; j < CIN; j++) acc += st[j] * mw[j];
    g_s[b * CIN + ic] = acc + mod_b[ic];
}

// ---------------------------------------------------------------------------
// K1: modulate + demodulate -> g_w[b][oc][ic][9]
// ---------------------------------------------------------------------------
__global__ void k1_mod(const float* __restrict__ weight) {
    int bo = blockIdx.x;
    int b = bo >> 8, oc = bo & 255;
    int ic = threadIdx.x;
    float sv = g_s[b * CIN + ic];
    const float sc = 0.014731391274719738f;  // 1/sqrt(512*9)
    float t[9], ss = 0.f;
    const float* wp = weight + ((size_t)oc * CIN + ic) * 9;
#pragma unroll
    for (int k = 0; k < 9; k++) { t[k] = sc * wp[k] * sv; ss += t[k] * t[k]; }
    __shared__ float red[CIN];
    red[ic] = ss;
    __syncthreads();
    for (int s = CIN / 2; s > 0; s >>= 1) {
        if (ic < s) red[ic] += red[ic + s];
        __syncthreads();
    }
    float dem = rsqrtf(red[0] + 1e-8f);
    float* out = g_w + (((size_t)b * COUT + oc) * CIN + ic) * 9;
#pragma unroll
    for (int k = 0; k < 9; k++) out[k] = t[k] * dem;
}

// ---------------------------------------------------------------------------
// K2 main: quad-decomposed conv_transpose (stride 2, K=3) for outputs [0,128)^2
// Block: 32x16 quads (64x32 outputs), 8 oc. Thread: 2 vertical quads x 8 oc.
// ---------------------------------------------------------------------------
__global__ __launch_bounds__(256) void k2_main(const float* __restrict__ x) {
    __shared__ float xs[8][33][24];                  // pitch 24 -> 2-row groups bank-disjoint
    __shared__ __align__(16) float ws[8 * 8 * 12];   // taps padded 9->12 for LDS.128
    int tid = threadIdx.x;
    int tx = tid & 15, ty = tid >> 4;
    int n0 = blockIdx.x * 16, m0 = blockIdx.y * 32;
    int b = blockIdx.z >> 5, oc0 = (blockIdx.z & 31) * 8;

    float acc[8][2][4];
#pragma unroll
    for (int o = 0; o < 8; o++)
#pragma unroll
        for (int q = 0; q < 2; q++) {
            acc[o][q][0] = 0.f; acc[o][q][1] = 0.f;
            acc[o][q][2] = 0.f; acc[o][q][3] = 0.f;
        }

    const size_t xbase = (size_t)b * CIN * HW * HW;
    for (int ic0 = 0; ic0 < CIN; ic0 += 8) {
        __syncthreads();
        // load x tile [8 ic][33 rows][17 cols], zero-padded at borders
        for (int idx = tid; idx < 8 * 33 * 17; idx += 256) {
            int icl = idx / 561;
            int rem = idx - icl * 561;
            int i = rem / 17, j = rem - i * 17;
            int gy = m0 - 1 + i, gx = n0 - 1 + j;
            float v = 0.f;
            if ((unsigned)gy < HW && (unsigned)gx < HW)
                v = x[xbase + ((size_t)(ic0 + icl) * HW + gy) * HW + gx];
            xs[icl][i][j] = v;
        }
        // load weights [8 ic][8 oc][9 taps]
        for (int idx = tid; idx < 576; idx += 256) {
            int o = idx / 72;
            int rem = idx - o * 72;
            int icl = rem / 9, tap = rem - icl * 9;
            ws[(icl * 8 + o) * 12 + tap] =
                g_w[(((size_t)b * COUT + oc0 + o) * CIN + ic0 + icl) * 9 + tap];
        }
        __syncthreads();
#pragma unroll
        for (int icl = 0; icl < 8; icl++) {
            int xr = 2 * ty;
            float xa0 = xs[icl][xr][tx + 1],     xa1 = xs[icl][xr][tx];
            float xb0 = xs[icl][xr + 1][tx + 1], xb1 = xs[icl][xr + 1][tx];
            float xc0 = xs[icl][xr + 2][tx + 1], xc1 = xs[icl][xr + 2][tx];
#pragma unroll
            for (int o = 0; o < 8; o++) {
                const float4* wp4 = (const float4*)&ws[(icl * 8 + o) * 12];
                float4 w0 = wp4[0];
                float4 w1 = wp4[1];
                float w22 = ws[(icl * 8 + o) * 12 + 8];
                // w(ky,kx): (0,0)=w0.x (0,1)=w0.y (0,2)=w0.z (1,0)=w0.w
                //           (1,1)=w1.x (1,2)=w1.y (2,0)=w1.z (2,1)=w1.w (2,2)=w22
                acc[o][0][0] += xb0 * w0.x + xb1 * w0.z + xa0 * w1.z + xa1 * w22;
                acc[o][0][1] += xb0 * w0.y + xa0 * w1.w;
                acc[o][0][2] += xb0 * w0.w + xb1 * w1.y;
                acc[o][0][3] += xb0 * w1.x;
                acc[o][1][0] += xc0 * w0.x + xc1 * w0.z + xb0 * w1.z + xb1 * w22;
                acc[o][1][1] += xc0 * w0.y + xb0 * w1.w;
                acc[o][1][2] += xc0 * w0.w + xc1 * w1.y;
                acc[o][1][3] += xc0 * w1.x;
            }
        }
    }
    int n = n0 + tx;
#pragma unroll
    for (int o = 0; o < 8; o++) {
        size_t cb = ((size_t)b * COUT + oc0 + o) * OBR;
#pragma unroll
        for (int q = 0; q < 2; q++) {
            int m = m0 + 2 * ty + q;
            size_t base = (cb + 2 * m) * OBP + 2 * n;
            *(float2*)&g_ob[base] = make_float2(acc[o][q][0], acc[o][q][1]);
            *(float2*)&g_ob[base + OBP] = make_float2(acc[o][q][2], acc[o][q][3]);
        }
    }
}

// ---------------------------------------------------------------------------
// K2 edge: outputs with oy==128 (e=0, p in [0,129)) or ox==128 (e=1, p in [0,128))
// 1-D transposed conv over x row/col 63 with the ky=2 / kx=2 weight slices.
// ---------------------------------------------------------------------------
__global__ __launch_bounds__(256) void k2_edge(const float* __restrict__ x) {
    int e = blockIdx.x;
    int oc0 = blockIdx.y * 32;
    int b = blockIdx.z;
    int tid = threadIdx.x;
    int tx = tid & 31, ty = tid >> 5;
    __shared__ float xl[16][64];
    __shared__ __align__(16) float ws[16 * 32 * 4];
    float acc[5][4];
#pragma unroll
    for (int g = 0; g < 5; g++)
#pragma unroll
        for (int u = 0; u < 4; u++) acc[g][u] = 0.f;
    int pmax = (e == 0) ? 129 : 128;
    bool even = !(tx & 1);

    for (int ic0 = 0; ic0 < CIN; ic0 += 16) {
        __syncthreads();
        for (int idx = tid; idx < 1024; idx += 256) {
            int icl = idx >> 6, j = idx & 63;
            size_t xi = (e == 0)
                ? ((size_t)(b * CIN + ic0 + icl) * HW + 63) * HW + j
                : ((size_t)(b * CIN + ic0 + icl) * HW + j) * HW + 63;
            xl[icl][j] = x[xi];
        }
        for (int idx = tid; idx < 16 * 32 * 3; idx += 256) {
            int icl = idx / 96;
            int rem = idx - icl * 96;
            int o = rem / 3, k = rem - o * 3;
            int tap = (e == 0) ? (6 + k) : (k * 3 + 2);
            ws[(icl * 32 + o) * 4 + k] =
                g_w[(((size_t)b * COUT + oc0 + o) * CIN + ic0 + icl) * 9 + tap];
        }
        __syncthreads();
#pragma unroll 4
        for (int icl = 0; icl < 16; icl++) {
            float xA[5], xB[5];
#pragma unroll
            for (int g = 0; g < 5; g++) {
                int p = tx + 32 * g;
                if (p < pmax) {
                    if (even) {
                        int j0 = p >> 1, j1 = j0 - 1;
                        xA[g] = (j0 < 64) ? xl[icl][j0] : 0.f;
                        xB[g] = (j1 >= 0) ? xl[icl][j1] : 0.f;
                    } else {
                        xA[g] = xl[icl][p >> 1];
                        xB[g] = 0.f;
                    }
                } else { xA[g] = 0.f; xB[g] = 0.f; }
            }
#pragma unroll
            for (int u = 0; u < 4; u++) {
                float4 wv = *(const float4*)&ws[(icl * 32 + ty * 4 + u) * 4];
                float wa = even ? wv.x : wv.y;
                float wb = even ? wv.z : 0.f;
#pragma unroll
                for (int g = 0; g < 5; g++) acc[g][u] += xA[g] * wa + xB[g] * wb;
            }
        }
    }
#pragma unroll
    for (int g = 0; g < 5; g++) {
        int p = tx + 32 * g;
        if (p < pmax) {
#pragma unroll
            for (int u = 0; u < 4; u++) {
                size_t cb = (size_t)(b * COUT + oc0 + ty * 4 + u) * OBR;
                size_t idx = (e == 0) ? (cb + 128) * OBP + p
                                      : (cb + (size_t)p) * OBP + 128;
                g_ob[idx] = acc[g][u];
            }
        }
    }
}

// ---------------------------------------------------------------------------
// K3: separable 4x4 blur (kc = [.25,.75,.75,.25] per axis) + noise + bias
//     + leaky_relu(0.2) * sqrt(2)
// ---------------------------------------------------------------------------
__global__ __launch_bounds__(256) void k3_blur(const float* __restrict__ noise,
                                               const float* __restrict__ noise_w,
                                               const float* __restrict__ act_b,
                                               float* __restrict__ out) {
    __shared__ float sb[35][36];
    __shared__ float tmp[35][32];
    int tid = threadIdx.x;
    int x0 = (blockIdx.x & 3) * 32, y0 = (blockIdx.x >> 2) * 32;
    int bc = blockIdx.z;
    int b = bc >> 8, oc = bc & 255;
    size_t obc = (size_t)bc * OBR;

    for (int idx = tid; idx < 35 * 35; idx += 256) {
        int i = idx / 35, j = idx - i * 35;
        int ry = y0 - 1 + i, rx = x0 - 1 + j;
        float v = 0.f;
        if ((unsigned)ry <= 128u && (unsigned)rx <= 128u)
            v = g_ob[(obc + ry) * OBP + rx];
        sb[i][j] = v;
    }
    __syncthreads();
    for (int idx = tid; idx < 35 * 32; idx += 256) {
        int i = idx >> 5, lx = idx & 31;
        tmp[i][lx] = 0.25f * sb[i][lx] + 0.75f * sb[i][lx + 1] +
                     0.75f * sb[i][lx + 2] + 0.25f * sb[i][lx + 3];
    }
    __syncthreads();
    float nw = noise_w[0];
    float ab = act_b[oc];
    int lx = tid & 31, tyg = tid >> 5;
#pragma unroll
    for (int r = 0; r < 4; r++) {
        int ly = tyg + 8 * r;
        float t = 0.25f * tmp[ly][lx] + 0.75f * tmp[ly + 1][lx] +
                  0.75f * tmp[ly + 2][lx] + 0.25f * tmp[ly + 3][lx];
        int y = y0 + ly, xg = x0 + lx;
        t += nw * noise[((size_t)b * FHW + y) * FHW + xg];
        t += ab;
        t = (t > 0.f ? t : 0.2f * t) * 1.4142135623730951f;
        out[((size_t)bc * FHW + y) * FHW + xg] = t;
    }
}

// ---------------------------------------------------------------------------
extern "C" void kernel_launch(void* const* d_in, const int* in_sizes, int n_in,
                              void* d_out, int out_size) {
    const float* x       = (const float*)d_in[0];
    const float* style   = (const float*)d_in[1];
    const float* noise   = (const float*)d_in[2];
    const float* weight  = (const float*)d_in[3];
    const float* mod_w   = (const float*)d_in[4];
    const float* mod_b   = (const float*)d_in[5];
    const float* noise_w = (const float*)d_in[6];
    const float* act_b   = (const float*)d_in[7];
    float* out = (float*)d_out;

    k0_style<<<BN, CIN>>>(style, mod_w, mod_b);
    k1_mod<<<BN * COUT, CIN>>>(weight);
    k2_main<<<dim3(4, 2, 256), 256>>>(x);
    k2_edge<<<dim3(2, 8, BN), 256>>>(x);
    k3_blur<<<dim3(16, 1, 2048), 256>>>(noise, noise_w, act_b, out);
}

// round 3
// speedup vs baseline: 1.7654x; 1.7654x over previous
#include <cuda_runtime.h>
#include <cuda_fp16.h>
#include <cstdint>

#define BN 8
#define CIN 512
#define COUT 256
#define HW 64
#define OBR 129
#define OBP 132
#define FHW 128

// ---------------- scratch (static device globals; no runtime alloc) ----------
__device__ float  g_s[BN * CIN];                           // modulation scales
__device__ __half g_xh[(size_t)BN * HW * HW * CIN];        // x [b][y][x][ic] fp16 (33.5MB)
__device__ __half g_wh[(size_t)BN * 9 * COUT * CIN];       // w [b][tap][oc][ic] fp16 (18.9MB)
__device__ float  g_ob[(size_t)BN * COUT * OBR * OBP];     // conv-transpose out (139.5MB)

// ---------------- helpers ----------------------------------------------------
__device__ __forceinline__ uint32_t smem_u32(const void* p) {
    uint32_t a;
    asm("{ .reg .u64 t; cvta.to.shared.u64 t, %1; cvt.u32.u64 %0, t; }" : "=r"(a) : "l"(p));
    return a;
}
__device__ __forceinline__ void cp16(uint32_t saddr, const void* g, uint32_t sz) {
    asm volatile("cp.async.cg.shared.global [%0], [%1], 16, %2;"
                 :: "r"(saddr), "l"(g), "r"(sz) : "memory");
}
__device__ __forceinline__ void ldsm4(uint32_t* r, uint32_t addr) {
    asm volatile("ldmatrix.sync.aligned.m8n8.x4.shared.b16 {%0,%1,%2,%3}, [%4];"
                 : "=r"(r[0]), "=r"(r[1]), "=r"(r[2]), "=r"(r[3]) : "r"(addr));
}
__device__ __forceinline__ void mma16816(float* d, const uint32_t* a, const uint32_t* b) {
    asm volatile("mma.sync.aligned.m16n8k16.row.col.f32.f16.f16.f32 "
                 "{%0,%1,%2,%3}, {%4,%5,%6,%7}, {%8,%9}, {%0,%1,%2,%3};"
                 : "+f"(d[0]), "+f"(d[1]), "+f"(d[2]), "+f"(d[3])
                 : "r"(a[0]), "r"(a[1]), "r"(a[2]), "r"(a[3]), "r"(b[0]), "r"(b[1]));
}

// ---------------------------------------------------------------------------
// K0: s[b][ic] = (style[b] . mod_w[ic]) / sqrt(512) + mod_b[ic]
// ---------------------------------------------------------------------------
__global__ void k0_style(const float* __restrict__ style,
                         const float* __restrict__ mod_w,
                         const float* __restrict__ mod_b) {
    int b = blockIdx.x, ic = threadIdx.x;
    __shared__ float st[CIN];
    st[ic] = style[b * CIN + ic] * 0.04419417382415922f;
    __syncthreads();
    const float* mw = mod_w + (size_t)ic * CIN;
    float acc = 0.f;
#pragma unroll 8
    for (int j = 0; j < CIN; j++) acc += st[j] * mw[j];
    g_s[b * CIN + ic] = acc + mod_b[ic];
}

// ---------------------------------------------------------------------------
// K1: modulate + demodulate -> g_wh[b][tap][oc][ic] fp16
// ---------------------------------------------------------------------------
__global__ void k1_mod(const float* __restrict__ weight) {
    int bo = blockIdx.x;
    int b = bo >> 8, oc = bo & 255;
    int ic = threadIdx.x;
    float sv = g_s[b * CIN + ic];
    const float sc = 0.014731391274719738f;  // 1/sqrt(512*9)
    float t[9], ss = 0.f;
    const float* wp = weight + ((size_t)oc * CIN + ic) * 9;
#pragma unroll
    for (int k = 0; k < 9; k++) { t[k] = sc * wp[k] * sv; ss += t[k] * t[k]; }
    __shared__ float red[CIN];
    red[ic] = ss;
    __syncthreads();
    for (int s = CIN / 2; s > 0; s >>= 1) {
        if (ic < s) red[ic] += red[ic + s];
        __syncthreads();
    }
    float dem = rsqrtf(red[0] + 1e-8f);
#pragma unroll
    for (int k = 0; k < 9; k++)
        g_wh[((size_t)(b * 9 + k) * COUT + oc) * CIN + ic] = __float2half_rn(t[k] * dem);
}

// ---------------------------------------------------------------------------
// KXT: transpose x [b][ic][y][x] -> g_xh [b][y][x][ic] fp16
// ---------------------------------------------------------------------------
__global__ __launch_bounds__(256) void k_xt(const float* __restrict__ x) {
    int y = blockIdx.x, b = blockIdx.y;
    int tid = threadIdx.x;
    __shared__ float t[32][65];
    for (int it = 0; it < 16; it++) {
        int ic0 = it * 32;
        __syncthreads();
        for (int idx = tid; idx < 2048; idx += 256) {
            int icl = idx >> 6, xx = idx & 63;
            t[icl][xx] = x[((size_t)(b * CIN + ic0 + icl) * HW + y) * HW + xx];
        }
        __syncthreads();
        for (int idx = tid; idx < 2048; idx += 256) {
            int xx = idx >> 5, icl = idx & 31;
            g_xh[((size_t)(b * HW + y) * HW + xx) * CIN + ic0 + icl] =
                __float2half_rn(t[icl][xx]);
        }
    }
}

// ---------------------------------------------------------------------------
// K2: implicit-GEMM conv-transpose on mma.sync (HMMA fp16, fp32 accum).
// D[oc=128, pos=32] per CTA; 9 taps -> 4 parity classes; K=512 in 16-chunks,
// double-buffered cp.async. Grid (9 xt, 17 yt, 16 b*ochalf).
// ---------------------------------------------------------------------------
#define K2_STAGE 38400     // 36864 B weights + 1536 B x per stage
#define K2_SMEM (2 * K2_STAGE)

// taps (ky,kx) row-major; cls = (ky&1)*2 + (kx&1); shift = (ky>>1, kx>>1)
__device__ __constant__ int c_cls[9] = {0, 1, 0, 2, 3, 2, 0, 1, 0};
__device__ __constant__ int c_shf[9] = {0, 0, 1, 0, 0, 1, 2, 2, 3};

__global__ __launch_bounds__(256, 2) void k2_mma() {
    extern __shared__ char smraw[];
    uint32_t sb = smem_u32(smraw);
    int tid = threadIdx.x;
    int wid = tid >> 5, lane = tid & 31;
    int warp_m = wid & 3;        // oc quarter (32 oc)
    int warp_n = wid >> 2;       // pos half (16 pos)
    int b = blockIdx.z >> 1;
    int oc0 = (blockIdx.z & 1) * 128;
    int x0 = blockIdx.x * 8, y0 = blockIdx.y * 4;

    float acc[4][2][2][4];
#pragma unroll
    for (int c = 0; c < 4; c++)
#pragma unroll
        for (int mf = 0; mf < 2; mf++)
#pragma unroll
            for (int nf = 0; nf < 2; nf++)
#pragma unroll
                for (int k = 0; k < 4; k++) acc[c][mf][nf][k] = 0.f;

    // B(x) ldmatrix lane mapping: groups (n0-7,k0-7)(n0-7,k8-15)(n8-15,k0-7)(n8-15,k8-15)
    int posB = (lane & 7) + ((lane >> 4) << 3);
    int kgB = (lane >> 3) & 1;
    // A(w) ldmatrix lane mapping: (m0-7,k0)(m8-15,k0)(m0-7,k1)(m8-15,k1)
    int ocA = lane & 15;
    int kgA = lane >> 4;

    // ---- async chunk loader: 2304 weight-16B + 90 x-16B units
    auto load_chunk = [&](int ch, int s) {
        uint32_t st = sb + s * K2_STAGE;
        int ic0 = ch * 16;
        for (int i = tid; i < 2394; i += 256) {
            if (i < 2304) {
                int tap = i >> 8;
                int rem = i & 255;
                int kg = rem >> 7, oc = rem & 127;
                uint32_t dst = st + (((tap * 2 + kg) << 7) + oc) * 16;
                const __half* src = g_wh +
                    (((size_t)(b * 9 + tap) * COUT + oc0 + oc) * CIN + ic0 + kg * 8);
                cp16(dst, src, 16);
            } else {
                int j = i - 2304;
                int kg = j / 45, pix = j - kg * 45;
                int py = pix / 9, px = pix - py * 9;
                int gy = y0 - 1 + py, gx = x0 - 1 + px;
                bool ok = ((unsigned)gy < 64u) && ((unsigned)gx < 64u);
                uint32_t dst = st + 36864 + (kg * 48 + pix) * 16;
                const __half* src = g_xh +
                    (((size_t)(b * HW + (ok ? gy : 0)) * HW + (ok ? gx : 0)) * CIN +
                     ic0 + kg * 8);
                cp16(dst, src, ok ? 16u : 0u);
            }
        }
        asm volatile("cp.async.commit_group;" ::: "memory");
    };

    load_chunk(0, 0);
    for (int ch = 0; ch < 32; ch++) {
        if (ch < 31) {
            load_chunk(ch + 1, (ch + 1) & 1);
            asm volatile("cp.async.wait_group 1;" ::: "memory");
        } else {
            asm volatile("cp.async.wait_group 0;" ::: "memory");
        }
        __syncthreads();
        uint32_t st = sb + (ch & 1) * K2_STAGE;
        uint32_t ax = st + 36864;

        // x fragments for the 4 shifts
        uint32_t bf[4][4];
#pragma unroll
        for (int s = 0; s < 4; s++) {
            int sy = s >> 1, sx = s & 1;
            int pos = warp_n * 16 + posB;
            int pix = (((pos >> 3) + 1 - sy) * 9) + ((pos & 7) + 1 - sx);
            ldsm4(bf[s], ax + (kgB * 48 + pix) * 16);
        }
        // weight fragments + mma, per tap
#pragma unroll
        for (int tap = 0; tap < 9; tap++) {
            int c = c_cls[tap], h = c_shf[tap];
            uint32_t af[2][4];
#pragma unroll
            for (int mf = 0; mf < 2; mf++)
                ldsm4(af[mf], st + (((tap * 2 + kgA) << 7) +
                                    warp_m * 32 + mf * 16 + ocA) * 16);
#pragma unroll
            for (int mf = 0; mf < 2; mf++)
#pragma unroll
                for (int nf = 0; nf < 2; nf++)
                    mma16816(acc[c][mf][nf], af[mf], &bf[h][nf * 2]);
        }
        __syncthreads();
    }

    // ---- epilogue: (cls0,cls1)->even rows, (cls2,cls3)->odd rows, float4 packed
    int r0 = lane >> 2, cb = lane & 3;
#pragma unroll
    for (int mf = 0; mf < 2; mf++)
#pragma unroll
        for (int rr = 0; rr < 2; rr++) {
            int oc = oc0 + warp_m * 32 + mf * 16 + rr * 8 + r0;
            size_t rowb = ((size_t)b * COUT + oc) * OBR;
#pragma unroll
            for (int nf = 0; nf < 2; nf++) {
                int m = y0 + warp_n * 2 + nf;
                int n = x0 + cb * 2;
                if (m <= 64 && n <= 64) {
                    float4 ve = make_float4(acc[0][mf][nf][rr * 2],
                                            acc[1][mf][nf][rr * 2],
                                            acc[0][mf][nf][rr * 2 + 1],
                                            acc[1][mf][nf][rr * 2 + 1]);
                    *(float4*)&g_ob[(rowb + 2 * m) * OBP + 2 * n] = ve;
                    if (m < 64) {
                        float4 vo = make_float4(acc[2][mf][nf][rr * 2],
                                                acc[3][mf][nf][rr * 2],
                                                acc[2][mf][nf][rr * 2 + 1],
                                                acc[3][mf][nf][rr * 2 + 1]);
                        *(float4*)&g_ob[(rowb + 2 * m + 1) * OBP + 2 * n] = vo;
                    }
                }
            }
        }
}

// ---------------------------------------------------------------------------
// K3: separable 4x4 blur + noise + bias + leaky_relu(0.2)*sqrt(2)
// ---------------------------------------------------------------------------
__global__ __launch_bounds__(256) void k3_blur(const float* __restrict__ noise,
                                               const float* __restrict__ noise_w,
                                               const float* __restrict__ act_b,
                                               float* __restrict__ out) {
    __shared__ float sb[35][36];
    __shared__ float tmp[35][32];
    int tid = threadIdx.x;
    int x0 = (blockIdx.x & 3) * 32, y0 = (blockIdx.x >> 2) * 32;
    int bc = blockIdx.z;
    int oc = bc & 255, b = bc >> 8;
    size_t obc = (size_t)bc * OBR;

    for (int idx = tid; idx < 35 * 35; idx += 256) {
        int i = idx / 35, j = idx - i * 35;
        int ry = y0 - 1 + i, rx = x0 - 1 + j;
        float v = 0.f;
        if ((unsigned)ry <= 128u && (unsigned)rx <= 128u)
            v = g_ob[(obc + ry) * OBP + rx];
        sb[i][j] = v;
    }
    __syncthreads();
    for (int idx = tid; idx < 35 * 32; idx += 256) {
        int i = idx >> 5, lx = idx & 31;
        tmp[i][lx] = 0.25f * sb[i][lx] + 0.75f * sb[i][lx + 1] +
                     0.75f * sb[i][lx + 2] + 0.25f * sb[i][lx + 3];
    }
    __syncthreads();
    float nw = noise_w[0];
    float ab = act_b[oc];
    int lx = tid & 31, tyg = tid >> 5;
#pragma unroll
    for (int r = 0; r < 4; r++) {
        int ly = tyg + 8 * r;
        float t = 0.25f * tmp[ly][lx] + 0.75f * tmp[ly + 1][lx] +
                  0.75f * tmp[ly + 2][lx] + 0.25f * tmp[ly + 3][lx];
        int y = y0 + ly, xg = x0 + lx;
        t += nw * noise[((size_t)b * FHW + y) * FHW + xg];
        t += ab;
        t = (t > 0.f ? t : 0.2f * t) * 1.4142135623730951f;
        out[((size_t)bc * FHW + y) * FHW + xg] = t;
    }
}

// ---------------------------------------------------------------------------
extern "C" void kernel_launch(void* const* d_in, const int* in_sizes, int n_in,
                              void* d_out, int out_size) {
    const float* x       = (const float*)d_in[0];
    const float* style   = (const float*)d_in[1];
    const float* noise   = (const float*)d_in[2];
    const float* weight  = (const float*)d_in[3];
    const float* mod_w   = (const float*)d_in[4];
    const float* mod_b   = (const float*)d_in[5];
    const float* noise_w = (const float*)d_in[6];
    const float* act_b   = (const float*)d_in[7];
    float* out = (float*)d_out;

    cudaFuncSetAttribute(k2_mma, cudaFuncAttributeMaxDynamicSharedMemorySize, K2_SMEM);

    k0_style<<<BN, CIN>>>(style, mod_w, mod_b);
    k1_mod<<<BN * COUT, CIN>>>(weight);
    k_xt<<<dim3(HW, BN), 256>>>(x);
    k2_mma<<<dim3(9, 17, 16), 256, K2_SMEM>>>();
    k3_blur<<<dim3(16, 1, 2048), 256>>>(noise, noise_w, act_b, out);
}

// round 5
// speedup vs baseline: 6.1731x; 3.4966x over previous
#include <cuda_runtime.h>
#include <cuda_fp16.h>
#include <cstdint>

#define BN 8
#define CIN 512
#define COUT 256
#define HW 64
#define OBR 129
#define OBP 132
#define FHW 128

// ---------------- scratch (static device globals; no runtime alloc) ----------
__device__ float  g_s[BN * CIN];                           // modulation scales
__device__ __half g_xh[(size_t)BN * HW * HW * CIN];        // x [b][y][x][ic] fp16
__device__ __half g_wh[(size_t)BN * 9 * COUT * CIN];       // w [b][tap][oc][ic] fp16
__device__ float  g_ob[(size_t)BN * COUT * OBR * OBP];     // conv-transpose out

// ---------------- helpers ----------------------------------------------------
__device__ __forceinline__ uint32_t smem_u32(const void* p) {
    uint32_t a;
    asm("{ .reg .u64 t; cvta.to.shared.u64 t, %1; cvt.u32.u64 %0, t; }" : "=r"(a) : "l"(p));
    return a;
}
__device__ __forceinline__ void cp16(uint32_t saddr, const void* g, uint32_t sz) {
    asm volatile("cp.async.cg.shared.global [%0], [%1], 16, %2;"
                 :: "r"(saddr), "l"(g), "r"(sz) : "memory");
}
__device__ __forceinline__ void ldsm4(uint32_t* r, uint32_t addr) {
    asm volatile("ldmatrix.sync.aligned.m8n8.x4.shared.b16 {%0,%1,%2,%3}, [%4];"
                 : "=r"(r[0]), "=r"(r[1]), "=r"(r[2]), "=r"(r[3]) : "r"(addr));
}
__device__ __forceinline__ void mma16816(float* d, const uint32_t* a, const uint32_t* b) {
    asm volatile("mma.sync.aligned.m16n8k16.row.col.f32.f16.f16.f32 "
                 "{%0,%1,%2,%3}, {%4,%5,%6,%7}, {%8,%9}, {%0,%1,%2,%3};"
                 : "+f"(d[0]), "+f"(d[1]), "+f"(d[2]), "+f"(d[3])
                 : "r"(a[0]), "r"(a[1]), "r"(a[2]), "r"(a[3]), "r"(b[0]), "r"(b[1]));
}

// ---------------------------------------------------------------------------
// K0: s[b][ic] = (style[b] . mod_w[ic]) / sqrt(512) + mod_b[ic]
// ---------------------------------------------------------------------------
__global__ void k0_style(const float* __restrict__ style,
                         const float* __restrict__ mod_w,
                         const float* __restrict__ mod_b) {
    int b = blockIdx.x, ic = threadIdx.x;
    __shared__ float st[CIN];
    st[ic] = style[b * CIN + ic] * 0.04419417382415922f;
    __syncthreads();
    const float* mw = mod_w + (size_t)ic * CIN;
    float acc = 0.f;
#pragma unroll 8
    for (int j = 0; j < CIN; j++) acc += st[j] * mw[j];
    g_s[b * CIN + ic] = acc + mod_b[ic];
}

// ---------------------------------------------------------------------------
// K1: modulate + demodulate -> g_wh[b][tap][oc][ic] fp16
// ---------------------------------------------------------------------------
__global__ void k1_mod(const float* __restrict__ weight) {
    int bo = blockIdx.x;
    int b = bo >> 8, oc = bo & 255;
    int ic = threadIdx.x;
    float sv = g_s[b * CIN + ic];
    const float sc = 0.014731391274719738f;  // 1/sqrt(512*9)
    float t[9], ss = 0.f;
    const float* wp = weight + ((size_t)oc * CIN + ic) * 9;
#pragma unroll
    for (int k = 0; k < 9; k++) { t[k] = sc * wp[k] * sv; ss += t[k] * t[k]; }
    __shared__ float red[CIN];
    red[ic] = ss;
    __syncthreads();
    for (int s = CIN / 2; s > 0; s >>= 1) {
        if (ic < s) red[ic] += red[ic + s];
        __syncthreads();
    }
    float dem = rsqrtf(red[0] + 1e-8f);
#pragma unroll
    for (int k = 0; k < 9; k++)
        g_wh[((size_t)(b * 9 + k) * COUT + oc) * CIN + ic] = __float2half_rn(t[k] * dem);
}

// ---------------------------------------------------------------------------
// KXT: transpose x [b][ic][y][x] -> g_xh [b][y][x][ic] fp16
// ---------------------------------------------------------------------------
__global__ __launch_bounds__(256) void k_xt(const float* __restrict__ x) {
    int y = blockIdx.x, b = blockIdx.y;
    int tid = threadIdx.x;
    __shared__ float t[32][65];
    for (int it = 0; it < 16; it++) {
        int ic0 = it * 32;
        __syncthreads();
        for (int idx = tid; idx < 2048; idx += 256) {
            int icl = idx >> 6, xx = idx & 63;
            t[icl][xx] = x[((size_t)(b * CIN + ic0 + icl) * HW + y) * HW + xx];
        }
        __syncthreads();
        for (int idx = tid; idx < 2048; idx += 256) {
            int xx = idx >> 5, icl = idx & 31;
            g_xh[((size_t)(b * HW + y) * HW + xx) * CIN + ic0 + icl] =
                __float2half_rn(t[icl][xx]);
        }
    }
}

// ---------------------------------------------------------------------------
// K2: implicit-GEMM conv-transpose, HMMA fp16/fp32.
// Pos tile 16x8=128, M=128 oc, 512 threads (warps 4x4: 32oc x 32pos).
// Two phases over disjoint tap sets: {cls0,cls1}=taps{0,1,2,6,7,8},
// {cls2,cls3}=taps{3,4,5}. 4-stage cp.async pipeline, 16-ic chunks.
// ---------------------------------------------------------------------------
#define XOFF 24576              // W region: 6 taps * 256 * 16B
#define XPITCH 160              // 16B units per kg (153 pix padded)
#define STAGE 29696             // 24576 + 2*160*16
#define K2_SMEM (4 * STAGE)

__device__ __constant__ int c_tap[9] = {0, 1, 2, 6, 7, 8, 3, 4, 5};

__device__ __forceinline__ void k2_load_slot(
    uint32_t stg, int p, int ch, int b, int oc0, int x0, int y0, int tid) {
    int ic0 = ch * 16;
    int nt = p ? 3 : 6;
    int tapbase = p ? 6 : 0;
    int nW = nt * 256;
    int total = nW + 306;
    for (int i = tid; i < total; i += 512) {
        if (i < nW) {
            int tapIdx = i >> 8;
            int rem = i & 255;
            int kg = rem >> 7, oc = rem & 127;
            uint32_t dst = stg + ((tapIdx * 2 + kg) * 128 + oc) * 16;
            const __half* src = g_wh +
                (((size_t)(b * 9 + c_tap[tapbase + tapIdx]) * COUT + oc0 + oc) * CIN +
                 ic0 + kg * 8);
            cp16(dst, src, 16);
        } else {
            int j = i - nW;
            int kg = (j >= 153);
            int pix = j - (kg ? 153 : 0);
            int py = pix / 17, px = pix - py * 17;
            int gy = y0 - 1 + py, gx = x0 - 1 + px;
            bool ok = ((unsigned)gy < 64u) && ((unsigned)gx < 64u);
            uint32_t dst = stg + XOFF + (kg * XPITCH + pix) * 16;
            const __half* src = g_xh +
                (((size_t)(b * HW + (ok ? gy : 0)) * HW + (ok ? gx : 0)) * CIN +
                 ic0 + kg * 8);
            cp16(dst, src, ok ? 16u : 0u);
        }
    }
}

template <int P>
__device__ __forceinline__ void k2_compute(
    uint32_t stg, int warp_m, int warp_n, int lane, float acc[2][2][4][4]) {
    constexpr int NT = P ? 3 : 6;
    constexpr int NS = P ? 2 : 4;
    const int TL_CL[2][6] = {{0, 1, 0, 0, 1, 0}, {0, 1, 0, 0, 0, 0}};
    const int TL_SF[2][6] = {{0, 0, 1, 2, 2, 3}, {0, 0, 1, 0, 0, 0}};

    int n_loc = (lane & 7) + ((lane >> 4) << 3);
    int kgB = (lane >> 3) & 1;
    int ocA = lane & 15;
    int kgA = lane >> 4;

    uint32_t bf[NS][2][4];
#pragma unroll
    for (int s = 0; s < NS; s++) {
        int sy = s >> 1, sx = s & 1;
#pragma unroll
        for (int t = 0; t < 2; t++) {
            int pnum = warp_n * 32 + t * 16 + n_loc;
            int pyo = pnum >> 4, pxo = pnum & 15;
            int pix = (pyo + 1 - sy) * 17 + (pxo + 1 - sx);
            ldsm4(bf[s][t], stg + XOFF + (kgB * XPITCH + pix) * 16);
        }
    }
#pragma unroll
    for (int ti = 0; ti < NT; ti++) {
        int cl = TL_CL[P][ti], h = TL_SF[P][ti];
        uint32_t af[2][4];
#pragma unroll
        for (int mf = 0; mf < 2; mf++)
            ldsm4(af[mf], stg + ((ti * 2 + kgA) * 128 + warp_m * 32 + mf * 16 + ocA) * 16);
#pragma unroll
        for (int mf = 0; mf < 2; mf++)
#pragma unroll
            for (int nf = 0; nf < 4; nf++)
                mma16816(acc[cl][mf][nf], af[mf], &bf[h][nf >> 1][(nf & 1) * 2]);
    }
}

__global__ __launch_bounds__(512, 1) void k2_mma() {
    extern __shared__ char smraw[];
    uint32_t sb = smem_u32(smraw);
    int tid = threadIdx.x;
    int wid = tid >> 5, lane = tid & 31;
    int warp_m = wid & 3;        // 32-oc slice
    int warp_n = wid >> 2;       // 32-pos slice
    int b = blockIdx.z >> 1;
    int oc0 = (blockIdx.z & 1) * 128;
    int x0 = blockIdx.x * 16, y0 = blockIdx.y * 8;

    float acc[2][2][4][4];
#pragma unroll
    for (int c = 0; c < 2; c++)
#pragma unroll
        for (int mf = 0; mf < 2; mf++)
#pragma unroll
            for (int nf = 0; nf < 4; nf++)
#pragma unroll
                for (int k = 0; k < 4; k++) acc[c][mf][nf][k] = 0.f;

    // prologue: prefetch slots 0..2
    for (int s = 0; s < 3; s++) {
        k2_load_slot(sb + (s & 3) * STAGE, s >> 5, s & 31, b, oc0, x0, y0, tid);
        asm volatile("cp.async.commit_group;" ::: "memory");
    }

    int r0 = lane >> 2, cq = lane & 3;

    for (int slot = 0; slot < 64; slot++) {
        int nx = slot + 3;
        if (nx < 64)
            k2_load_slot(sb + (nx & 3) * STAGE, nx >> 5, nx & 31, b, oc0, x0, y0, tid);
        asm volatile("cp.async.commit_group;" ::: "memory");
        asm volatile("cp.async.wait_group 3;" ::: "memory");
        __syncthreads();
        uint32_t stg = sb + (slot & 3) * STAGE;
        if (slot < 32) k2_compute<0>(stg, warp_m, warp_n, lane, acc);
        else           k2_compute<1>(stg, warp_m, warp_n, lane, acc);
        __syncthreads();

        if (slot == 31 || slot == 63) {
            int p = slot >> 5;   // phase: classes (2p, 2p+1), output row 2m+p
#pragma unroll
            for (int mf = 0; mf < 2; mf++)
#pragma unroll
                for (int rr = 0; rr < 2; rr++) {
                    int oc = oc0 + warp_m * 32 + mf * 16 + rr * 8 + r0;
                    size_t rowb = ((size_t)b * COUT + oc) * OBR;
#pragma unroll
                    for (int nf = 0; nf < 4; nf++) {
                        int m = y0 + warp_n * 2 + (nf >> 1);
                        int n = x0 + (nf & 1) * 8 + cq * 2;
                        int row = 2 * m + p;
                        if (row <= 128 && n <= 64) {
                            float4 v = make_float4(acc[0][mf][nf][rr * 2],
                                                   acc[1][mf][nf][rr * 2],
                                                   acc[0][mf][nf][rr * 2 + 1],
                                                   acc[1][mf][nf][rr * 2 + 1]);
                            *(float4*)&g_ob[(rowb + row) * OBP + 2 * n] = v;
                        }
                    }
                }
            if (slot == 31) {
#pragma unroll
                for (int c = 0; c < 2; c++)
#pragma unroll
                    for (int mf = 0; mf < 2; mf++)
#pragma unroll
                        for (int nf = 0; nf < 4; nf++)
#pragma unroll
                            for (int k = 0; k < 4; k++) acc[c][mf][nf][k] = 0.f;
            }
        }
    }
}

// ---------------------------------------------------------------------------
// K3: separable 4x4 blur + noise + bias + leaky_relu(0.2)*sqrt(2)
// ---------------------------------------------------------------------------
__global__ __launch_bounds__(256) void k3_blur(const float* __restrict__ noise,
                                               const float* __restrict__ noise_w,
                                               const float* __restrict__ act_b,
                                               float* __restrict__ out) {
    __shared__ float sb[35][36];
    __shared__ float tmp[35][32];
    int tid = threadIdx.x;
    int x0 = (blockIdx.x & 3) * 32, y0 = (blockIdx.x >> 2) * 32;
    int bc = blockIdx.z;
    int oc = bc & 255, b = bc >> 8;
    size_t obc = (size_t)bc * OBR;

    for (int idx = tid; idx < 35 * 35; idx += 256) {
        int i = idx / 35, j = idx - i * 35;
        int ry = y0 - 1 + i, rx = x0 - 1 + j;
        float v = 0.f;
        if ((unsigned)ry <= 128u && (unsigned)rx <= 128u)
            v = g_ob[(obc + ry) * OBP + rx];
        sb[i][j] = v;
    }
    __syncthreads();
    for (int idx = tid; idx < 35 * 32; idx += 256) {
        int i = idx >> 5, lx = idx & 31;
        tmp[i][lx] = 0.25f * sb[i][lx] + 0.75f * sb[i][lx + 1] +
                     0.75f * sb[i][lx + 2] + 0.25f * sb[i][lx + 3];
    }
    __syncthreads();
    float nw = noise_w[0];
    float ab = act_b[oc];
    int lx = tid & 31, tyg = tid >> 5;
#pragma unroll
    for (int r = 0; r < 4; r++) {
        int ly = tyg + 8 * r;
        float t = 0.25f * tmp[ly][lx] + 0.75f * tmp[ly + 1][lx] +
                  0.75f * tmp[ly + 2][lx] + 0.25f * tmp[ly + 3][lx];
        int y = y0 + ly, xg = x0 + lx;
        t += nw * noise[((size_t)b * FHW + y) * FHW + xg];
        t += ab;
        t = (t > 0.f ? t : 0.2f * t) * 1.4142135623730951f;
        out[((size_t)bc * FHW + y) * FHW + xg] = t;
    }
}

// ---------------------------------------------------------------------------
extern "C" void kernel_launch(void* const* d_in, const int* in_sizes, int n_in,
                              void* d_out, int out_size) {
    const float* x       = (const float*)d_in[0];
    const float* style   = (const float*)d_in[1];
    const float* noise   = (const float*)d_in[2];
    const float* weight  = (const float*)d_in[3];
    const float* mod_w   = (const float*)d_in[4];
    const float* mod_b   = (const float*)d_in[5];
    const float* noise_w = (const float*)d_in[6];
    const float* act_b   = (const float*)d_in[7];
    float* out = (float*)d_out;

    cudaFuncSetAttribute(k2_mma, cudaFuncAttributeMaxDynamicSharedMemorySize, K2_SMEM);

    k0_style<<<BN, CIN>>>(style, mod_w, mod_b);
    k1_mod<<<BN * COUT, CIN>>>(weight);
    k_xt<<<dim3(HW, BN), 256>>>(x);
    k2_mma<<<dim3(5, 9, 16), 512, K2_SMEM>>>();
    k3_blur<<<dim3(16, 1, 2048), 256>>>(noise, noise_w, act_b, out);
}

// round 7
// speedup vs baseline: 7.3711x; 1.1941x over previous
#include <cuda_runtime.h>
#include <cuda_fp16.h>
#include <cstdint>

#define BN 8
#define CIN 512
#define COUT 256
#define HW 64
#define OBR 129
#define OBP 132
#define FHW 128

// ---------------- scratch (static device globals; no runtime alloc) ----------
__device__ float  g_s[BN * CIN];                           // modulation scales
__device__ __half g_xh[(size_t)BN * HW * HW * CIN];        // x [b][y][x][ic] fp16
__device__ __half g_wh[(size_t)BN * 9 * COUT * CIN];       // w [b][tap][oc][ic] fp16
__device__ __half g_obh[(size_t)BN * COUT * OBR * OBP];    // conv-transpose out fp16

// ---------------- helpers ----------------------------------------------------
__device__ __forceinline__ uint32_t smem_u32(const void* p) {
    uint32_t a;
    asm("{ .reg .u64 t; cvta.to.shared.u64 t, %1; cvt.u32.u64 %0, t; }" : "=r"(a) : "l"(p));
    return a;
}
__device__ __forceinline__ void cp16(uint32_t saddr, const void* g, uint32_t sz) {
    asm volatile("cp.async.cg.shared.global [%0], [%1], 16, %2;"
                 :: "r"(saddr), "l"(g), "r"(sz) : "memory");
}
__device__ __forceinline__ void ldsm4(uint32_t* r, uint32_t addr) {
    asm volatile("ldmatrix.sync.aligned.m8n8.x4.shared.b16 {%0,%1,%2,%3}, [%4];"
                 : "=r"(r[0]), "=r"(r[1]), "=r"(r[2]), "=r"(r[3]) : "r"(addr));
}
__device__ __forceinline__ void mma16816(float* d, const uint32_t* a, const uint32_t* b) {
    asm volatile("mma.sync.aligned.m16n8k16.row.col.f32.f16.f16.f32 "
                 "{%0,%1,%2,%3}, {%4,%5,%6,%7}, {%8,%9}, {%0,%1,%2,%3};"
                 : "+f"(d[0]), "+f"(d[1]), "+f"(d[2]), "+f"(d[3])
                 : "r"(a[0]), "r"(a[1]), "r"(a[2]), "r"(a[3]), "r"(b[0]), "r"(b[1]));
}

// ---------------------------------------------------------------------------
// K0: s[b][ic] = (style[b] . mod_w[ic]) / sqrt(512) + mod_b[ic]
// ---------------------------------------------------------------------------
__global__ void k0_style(const float* __restrict__ style,
                         const float* __restrict__ mod_w,
                         const float* __restrict__ mod_b) {
    int b = blockIdx.x, ic = threadIdx.x;
    __shared__ float st[CIN];
    st[ic] = style[b * CIN + ic] * 0.04419417382415922f;
    __syncthreads();
    const float* mw = mod_w + (size_t)ic * CIN;
    float acc = 0.f;
#pragma unroll 8
    for (int j = 0; j < CIN; j++) acc += st[j] * mw[j];
    g_s[b * CIN + ic] = acc + mod_b[ic];
}

// ---------------------------------------------------------------------------
// K1: modulate + demodulate -> g_wh[b][tap][oc][ic] fp16 (shfl reduction)
// ---------------------------------------------------------------------------
__global__ void k1_mod(const float* __restrict__ weight) {
    int bo = blockIdx.x;
    int b = bo >> 8, oc = bo & 255;
    int ic = threadIdx.x;
    float sv = g_s[b * CIN + ic];
    const float sc = 0.014731391274719738f;  // 1/sqrt(512*9)
    float t[9], ss = 0.f;
    const float* wp = weight + ((size_t)oc * CIN + ic) * 9;
#pragma unroll
    for (int k = 0; k < 9; k++) { t[k] = sc * wp[k] * sv; ss += t[k] * t[k]; }
#pragma unroll
    for (int o = 16; o; o >>= 1) ss += __shfl_xor_sync(0xFFFFFFFFu, ss, o);
    __shared__ float red[16];
    if ((ic & 31) == 0) red[ic >> 5] = ss;
    __syncthreads();
    if (ic < 32) {
        float v = (ic < 16) ? red[ic] : 0.f;
#pragma unroll
        for (int o = 8; o; o >>= 1) v += __shfl_xor_sync(0xFFFFFFFFu, v, o);
        if (ic == 0) red[0] = v;
    }
    __syncthreads();
    float dem = rsqrtf(red[0] + 1e-8f);
#pragma unroll
    for (int k = 0; k < 9; k++)
        g_wh[((size_t)(b * 9 + k) * COUT + oc) * CIN + ic] = __float2half_rn(t[k] * dem);
}

// ---------------------------------------------------------------------------
// KXT: transpose x [b][ic][y][x] -> g_xh [b][y][x][ic] fp16
// ---------------------------------------------------------------------------
__global__ __launch_bounds__(256) void k_xt(const float* __restrict__ x) {
    int y = blockIdx.x, b = blockIdx.y;
    int tid = threadIdx.x;
    __shared__ float t[32][65];
    for (int it = 0; it < 16; it++) {
        int ic0 = it * 32;
        __syncthreads();
        for (int idx = tid; idx < 2048; idx += 256) {
            int icl = idx >> 6, xx = idx & 63;
            t[icl][xx] = x[((size_t)(b * CIN + ic0 + icl) * HW + y) * HW + xx];
        }
        __syncthreads();
        for (int idx = tid; idx < 2048; idx += 256) {
            int xx = idx >> 5, icl = idx & 31;
            g_xh[((size_t)(b * HW + y) * HW + xx) * CIN + ic0 + icl] =
                __float2half_rn(t[icl][xx]);
        }
    }
}

// ---------------------------------------------------------------------------
// K2: implicit-GEMM conv-transpose, HMMA fp16/fp32.
// Pos tile 16x8=128, M=128 oc, 512 threads. Two phases over disjoint taps.
// 32-ic chunks (K=32/slot), 3-stage cp.async pipeline, ONE barrier per slot.
// ---------------------------------------------------------------------------
#define XOFF 49152              // W region: 6 taps * 4 kg * 128 oc * 16B
#define XPITCH 160              // 16B units per kg (153 pix padded)
#define STAGE 59392             // 49152 + 4*160*16
#define K2_SMEM (3 * STAGE)     // 178176

__device__ __constant__ int c_tap[9] = {0, 1, 2, 6, 7, 8, 3, 4, 5};

__device__ __forceinline__ void k2_load_slot(
    uint32_t stg, int p, int ch, int b, int oc0, int x0, int y0, int tid) {
    int ic0 = ch * 32;
    int nt = p ? 3 : 6;
    int tapbase = p ? 6 : 0;
    int nW = nt * 512;                 // taps * 4kg * 128oc
    int total = nW + 612;              // + 4kg * 153 pix
    for (int i = tid; i < total; i += 512) {
        if (i < nW) {
            int tapIdx = i >> 9;
            int rem = i & 511;
            int kg = rem >> 7, oc = rem & 127;
            uint32_t dst = stg + ((tapIdx * 4 + kg) * 128 + oc) * 16;
            const __half* src = g_wh +
                (((size_t)(b * 9 + c_tap[tapbase + tapIdx]) * COUT + oc0 + oc) * CIN +
                 ic0 + kg * 8);
            cp16(dst, src, 16);
        } else {
            int j = i - nW;
            int kg = j / 153;
            int pix = j - kg * 153;
            int py = pix / 17, px = pix - py * 17;
            int gy = y0 - 1 + py, gx = x0 - 1 + px;
            bool ok = ((unsigned)gy < 64u) && ((unsigned)gx < 64u);
            uint32_t dst = stg + XOFF + (kg * XPITCH + pix) * 16;
            const __half* src = g_xh +
                (((size_t)(b * HW + (ok ? gy : 0)) * HW + (ok ? gx : 0)) * CIN +
                 ic0 + kg * 8);
            cp16(dst, src, ok ? 16u : 0u);
        }
    }
}

template <int P>
__device__ __forceinline__ void k2_compute(
    uint32_t stg, int warp_m, int warp_n, int lane, float acc[2][2][4][4]) {
    constexpr int NT = P ? 3 : 6;
    constexpr int NS = P ? 2 : 4;
    const int TL_CL[2][6] = {{0, 1, 0, 0, 1, 0}, {0, 1, 0, 0, 0, 0}};
    const int TL_SF[2][6] = {{0, 0, 1, 2, 2, 3}, {0, 0, 1, 0, 0, 0}};

    int n_loc = (lane & 7) + ((lane >> 4) << 3);
    int kgB = (lane >> 3) & 1;
    int ocA = lane & 15;
    int kgA = lane >> 4;

#pragma unroll
    for (int kgp = 0; kgp < 2; kgp++) {
        uint32_t bf[NS][2][4];
#pragma unroll
        for (int s = 0; s < NS; s++) {
            int sy = s >> 1, sx = s & 1;
#pragma unroll
            for (int t = 0; t < 2; t++) {
                int pnum = warp_n * 32 + t * 16 + n_loc;
                int pyo = pnum >> 4, pxo = pnum & 15;
                int pix = (pyo + 1 - sy) * 17 + (pxo + 1 - sx);
                ldsm4(bf[s][t], stg + XOFF + ((kgp * 2 + kgB) * XPITCH + pix) * 16);
            }
        }
#pragma unroll
        for (int ti = 0; ti < NT; ti++) {
            int cl = TL_CL[P][ti], h = TL_SF[P][ti];
            uint32_t af[2][4];
#pragma unroll
            for (int mf = 0; mf < 2; mf++)
                ldsm4(af[mf], stg + ((ti * 4 + kgp * 2 + kgA) * 128 +
                                     warp_m * 32 + mf * 16 + ocA) * 16);
#pragma unroll
            for (int mf = 0; mf < 2; mf++)
#pragma unroll
                for (int nf = 0; nf < 4; nf++)
                    mma16816(acc[cl][mf][nf], af[mf], &bf[h][nf >> 1][(nf & 1) * 2]);
        }
    }
}

__global__ __launch_bounds__(512, 1) void k2_mma() {
    extern __shared__ char smraw[];
    uint32_t sb = smem_u32(smraw);
    int tid = threadIdx.x;
    int wid = tid >> 5, lane = tid & 31;
    int warp_m = wid & 3;        // 32-oc slice
    int warp_n = wid >> 2;       // 32-pos slice
    int b = blockIdx.z >> 1;
    int oc0 = (blockIdx.z & 1) * 128;
    int x0 = blockIdx.x * 16, y0 = blockIdx.y * 8;

    float acc[2][2][4][4];
#pragma unroll
    for (int c = 0; c < 2; c++)
#pragma unroll
        for (int mf = 0; mf < 2; mf++)
#pragma unroll
            for (int nf = 0; nf < 4; nf++)
#pragma unroll
                for (int k = 0; k < 4; k++) acc[c][mf][nf][k] = 0.f;

    // prologue: prefetch slots 0,1
    for (int s = 0; s < 2; s++) {
        k2_load_slot(sb + s * STAGE, 0, s, b, oc0, x0, y0, tid);
        asm volatile("cp.async.commit_group;" ::: "memory");
    }

    int r0 = lane >> 2, cq = lane & 3;

    for (int slot = 0; slot < 32; slot++) {
        asm volatile("cp.async.wait_group 1;" ::: "memory");
        __syncthreads();
        uint32_t stg = sb + (slot % 3) * STAGE;
        if (slot < 16) k2_compute<0>(stg, warp_m, warp_n, lane, acc);
        else           k2_compute<1>(stg, warp_m, warp_n, lane, acc);

        if (slot == 15 || slot == 31) {
            int p = slot >> 4;   // phase: classes (2p, 2p+1), output row 2m+p
#pragma unroll
            for (int mf = 0; mf < 2; mf++)
#pragma unroll
                for (int rr = 0; rr < 2; rr++) {
                    int oc = oc0 + warp_m * 32 + mf * 16 + rr * 8 + r0;
                    size_t rowb = ((size_t)b * COUT + oc) * OBR;
#pragma unroll
                    for (int nf = 0; nf < 4; nf++) {
                        int m = y0 + warp_n * 2 + (nf >> 1);
                        int n = x0 + (nf & 1) * 8 + cq * 2;
                        int row = 2 * m + p;
                        if (row <= 128 && n <= 64) {
                            __half2 lo = __floats2half2_rn(acc[0][mf][nf][rr * 2],
                                                           acc[1][mf][nf][rr * 2]);
                            __half2 hi = __floats2half2_rn(acc[0][mf][nf][rr * 2 + 1],
                                                           acc[1][mf][nf][rr * 2 + 1]);
                            uint2 v = make_uint2(*(uint32_t*)&lo, *(uint32_t*)&hi);
                            *(uint2*)&g_obh[(rowb + row) * OBP + 2 * n] = v;
                        }
                    }
                }
            if (slot == 15) {
#pragma unroll
                for (int c = 0; c < 2; c++)
#pragma unroll
                    for (int mf = 0; mf < 2; mf++)
#pragma unroll
                        for (int nf = 0; nf < 4; nf++)
#pragma unroll
                            for (int k = 0; k < 4; k++) acc[c][mf][nf][k] = 0.f;
            }
        }

        int nx = slot + 2;
        if (nx < 32)
            k2_load_slot(sb + (nx % 3) * STAGE, nx >> 4, nx & 15, b, oc0, x0, y0, tid);
        asm volatile("cp.async.commit_group;" ::: "memory");
    }
}

// ---------------------------------------------------------------------------
// K3: separable 4x4 blur + noise + bias + leaky_relu(0.2)*sqrt(2)
// ---------------------------------------------------------------------------
__global__ __launch_bounds__(256) void k3_blur(const float* __restrict__ noise,
                                               const float* __restrict__ noise_w,
                                               const float* __restrict__ act_b,
                                               float* __restrict__ out) {
    __shared__ float sb[35][36];
    __shared__ float tmp[35][32];
    int tid = threadIdx.x;
    int x0 = (blockIdx.x & 3) * 32, y0 = (blockIdx.x >> 2) * 32;
    int bc = blockIdx.z;
    int oc = bc & 255, b = bc >> 8;
    size_t obc = (size_t)bc * OBR;

    for (int idx = tid; idx < 35 * 35; idx += 256) {
        int i = idx / 35, j = idx - i * 35;
        int ry = y0 - 1 + i, rx = x0 - 1 + j;
        float v = 0.f;
        if ((unsigned)ry <= 128u && (unsigned)rx <= 128u)
            v = __half2float(g_obh[(obc + ry) * OBP + rx]);
        sb[i][j] = v;
    }
    __syncthreads();
    for (int idx = tid; idx < 35 * 32; idx += 256) {
        int i = idx >> 5, lx = idx & 31;
        tmp[i][lx] = 0.25f * sb[i][lx] + 0.75f * sb[i][lx + 1] +
                     0.75f * sb[i][lx + 2] + 0.25f * sb[i][lx + 3];
    }
    __syncthreads();
    float nw = noise_w[0];
    float ab = act_b[oc];
    int lx = tid & 31, tyg = tid >> 5;
#pragma unroll
    for (int r = 0; r < 4; r++) {
        int ly = tyg + 8 * r;
        float t = 0.25f * tmp[ly][lx] + 0.75f * tmp[ly + 1][lx] +
                  0.75f * tmp[ly + 2][lx] + 0.25f * tmp[ly + 3][lx];
        int y = y0 + ly, xg = x0 + lx;
        t += nw * noise[((size_t)b * FHW + y) * FHW + xg];
        t += ab;
        t = (t > 0.f ? t : 0.2f * t) * 1.4142135623730951f;
        out[((size_t)bc * FHW + y) * FHW + xg] = t;
    }
}

// ---------------------------------------------------------------------------
extern "C" void kernel_launch(void* const* d_in, const int* in_sizes, int n_in,
                              void* d_out, int out_size) {
    const float* x       = (const float*)d_in[0];
    const float* style   = (const float*)d_in[1];
    const float* noise   = (const float*)d_in[2];
    const float* weight  = (const float*)d_in[3];
    const float* mod_w   = (const float*)d_in[4];
    const float* mod_b   = (const float*)d_in[5];
    const float* noise_w = (const float*)d_in[6];
    const float* act_b   = (const float*)d_in[7];
    float* out = (float*)d_out;

    cudaFuncSetAttribute(k2_mma, cudaFuncAttributeMaxDynamicSharedMemorySize, K2_SMEM);

    k0_style<<<BN, CIN>>>(style, mod_w, mod_b);
    k1_mod<<<BN * COUT, CIN>>>(weight);
    k_xt<<<dim3(HW, BN), 256>>>(x);
    k2_mma<<<dim3(5, 9, 16), 512, K2_SMEM>>>();
    k3_blur<<<dim3(16, 1, 2048), 256>>>(noise, noise_w, act_b, out);
}

// round 8
// speedup vs baseline: 8.2397x; 1.1178x over previous
#include <cuda_runtime.h>
#include <cuda_fp16.h>
#include <cstdint>

#define BN 8
#define CIN 512
#define COUT 256
#define HW 64
#define OBR 129
#define OBP 132
#define FHW 128

// ---------------- scratch (static device globals; no runtime alloc) ----------
__device__ float  g_s[BN * CIN];                           // modulation scales
__device__ __half g_xh[(size_t)BN * HW * HW * CIN];        // x [b][y][x][ic] fp16
__device__ __half g_wh[(size_t)BN * 9 * COUT * CIN];       // w [b][tap][oc][ic] fp16
__device__ __half g_obh[(size_t)BN * COUT * OBR * OBP];    // conv-transpose out fp16

// ---------------- helpers ----------------------------------------------------
__device__ __forceinline__ uint32_t smem_u32(const void* p) {
    uint32_t a;
    asm("{ .reg .u64 t; cvta.to.shared.u64 t, %1; cvt.u32.u64 %0, t; }" : "=r"(a) : "l"(p));
    return a;
}
__device__ __forceinline__ void cp16(uint32_t saddr, const void* g, uint32_t sz) {
    asm volatile("cp.async.cg.shared.global [%0], [%1], 16, %2;"
                 :: "r"(saddr), "l"(g), "r"(sz) : "memory");
}
__device__ __forceinline__ void ldsm4(uint32_t* r, uint32_t addr) {
    asm volatile("ldmatrix.sync.aligned.m8n8.x4.shared.b16 {%0,%1,%2,%3}, [%4];"
                 : "=r"(r[0]), "=r"(r[1]), "=r"(r[2]), "=r"(r[3]) : "r"(addr));
}
__device__ __forceinline__ void mma16816(float* d, const uint32_t* a, const uint32_t* b) {
    asm volatile("mma.sync.aligned.m16n8k16.row.col.f32.f16.f16.f32 "
                 "{%0,%1,%2,%3}, {%4,%5,%6,%7}, {%8,%9}, {%0,%1,%2,%3};"
                 : "+f"(d[0]), "+f"(d[1]), "+f"(d[2]), "+f"(d[3])
                 : "r"(a[0]), "r"(a[1]), "r"(a[2]), "r"(a[3]), "r"(b[0]), "r"(b[1]));
}

// ---------------------------------------------------------------------------
// K0: s[b][ic] = (style[b] . mod_w[ic]) / sqrt(512) + mod_b[ic]
// ---------------------------------------------------------------------------
__global__ void k0_style(const float* __restrict__ style,
                         const float* __restrict__ mod_w,
                         const float* __restrict__ mod_b) {
    int b = blockIdx.x, ic = threadIdx.x;
    __shared__ float st[CIN];
    st[ic] = style[b * CIN + ic] * 0.04419417382415922f;
    __syncthreads();
    const float* mw = mod_w + (size_t)ic * CIN;
    float acc = 0.f;
#pragma unroll 8
    for (int j = 0; j < CIN; j++) acc += st[j] * mw[j];
    g_s[b * CIN + ic] = acc + mod_b[ic];
}

// ---------------------------------------------------------------------------
// K1: modulate + demodulate -> g_wh[b][tap][oc][ic] fp16 (shfl reduction)
// ---------------------------------------------------------------------------
__global__ void k1_mod(const float* __restrict__ weight) {
    int bo = blockIdx.x;
    int b = bo >> 8, oc = bo & 255;
    int ic = threadIdx.x;
    float sv = g_s[b * CIN + ic];
    const float sc = 0.014731391274719738f;  // 1/sqrt(512*9)
    float t[9], ss = 0.f;
    const float* wp = weight + ((size_t)oc * CIN + ic) * 9;
#pragma unroll
    for (int k = 0; k < 9; k++) { t[k] = sc * wp[k] * sv; ss += t[k] * t[k]; }
#pragma unroll
    for (int o = 16; o; o >>= 1) ss += __shfl_xor_sync(0xFFFFFFFFu, ss, o);
    __shared__ float red[16];
    if ((ic & 31) == 0) red[ic >> 5] = ss;
    __syncthreads();
    if (ic < 32) {
        float v = (ic < 16) ? red[ic] : 0.f;
#pragma unroll
        for (int o = 8; o; o >>= 1) v += __shfl_xor_sync(0xFFFFFFFFu, v, o);
        if (ic == 0) red[0] = v;
    }
    __syncthreads();
    float dem = rsqrtf(red[0] + 1e-8f);
#pragma unroll
    for (int k = 0; k < 9; k++)
        g_wh[((size_t)(b * 9 + k) * COUT + oc) * CIN + ic] = __float2half_rn(t[k] * dem);
}

// ---------------------------------------------------------------------------
// KXT: transpose x [b][ic][y][x] -> g_xh [b][y][x][ic] fp16
// grid (64 y, 16 icg, 8 b): one 32ic x 64x tile per block, 1 sync.
// ---------------------------------------------------------------------------
__global__ __launch_bounds__(256) void k_xt(const float* __restrict__ x) {
    int y = blockIdx.x, icg = blockIdx.y, b = blockIdx.z;
    int ic0 = icg * 32;
    int tid = threadIdx.x;
    __shared__ float t[32][65];
    for (int idx = tid; idx < 2048; idx += 256) {
        int icl = idx >> 6, xx = idx & 63;
        t[icl][xx] = x[((size_t)(b * CIN + ic0 + icl) * HW + y) * HW + xx];
    }
    __syncthreads();
    for (int idx = tid; idx < 1024; idx += 256) {
        int xx = idx >> 4, icp = idx & 15;
        __half2 v = __floats2half2_rn(t[icp * 2][xx], t[icp * 2 + 1][xx]);
        *(__half2*)&g_xh[((size_t)(b * HW + y) * HW + xx) * CIN + ic0 + icp * 2] = v;
    }
}

// ---------------------------------------------------------------------------
// K2: implicit-GEMM conv-transpose, HMMA fp16/fp32.
// blockIdx.x<32: main 16x8 pos tiles covering m,n in [0,64)^2 (exact).
// blockIdx.x in {32,33}: edge strips (out row 128 / col 128), 3-tap 1-D GEMM.
// ---------------------------------------------------------------------------
#define XOFF 49152              // W region: 6 taps * 4 kg * 128 oc * 16B
#define XPITCH 160              // 16B units per kg (153 pix padded)
#define STAGE 59392             // 49152 + 4*160*16
#define K2_SMEM (3 * STAGE)     // 178176

#define E_XOFF 24576            // edge W region: 3 taps * 4 kg * 128 oc * 16B
#define E_STAGE 28928           // 24576 + 4*68*16

__device__ __constant__ int c_tap[9] = {0, 1, 2, 6, 7, 8, 3, 4, 5};
__device__ __constant__ int c_etap[2][3] = {{6, 7, 8}, {2, 5, 8}};

__device__ __forceinline__ void k2_load_slot(
    uint32_t stg, int p, int ch, int b, int oc0, int x0, int y0, int tid) {
    int ic0 = ch * 32;
    int nt = p ? 3 : 6;
    int tapbase = p ? 6 : 0;
    int nW = nt * 512;
    int total = nW + 612;
    for (int i = tid; i < total; i += 512) {
        if (i < nW) {
            int tapIdx = i >> 9;
            int rem = i & 511;
            int kg = rem >> 7, oc = rem & 127;
            uint32_t dst = stg + ((tapIdx * 4 + kg) * 128 + oc) * 16;
            const __half* src = g_wh +
                (((size_t)(b * 9 + c_tap[tapbase + tapIdx]) * COUT + oc0 + oc) * CIN +
                 ic0 + kg * 8);
            cp16(dst, src, 16);
        } else {
            int j = i - nW;
            int kg = j / 153;
            int pix = j - kg * 153;
            int py = pix / 17, px = pix - py * 17;
            int gy = y0 - 1 + py, gx = x0 - 1 + px;
            bool ok = ((unsigned)gy < 64u) && ((unsigned)gx < 64u);
            uint32_t dst = stg + XOFF + (kg * XPITCH + pix) * 16;
            const __half* src = g_xh +
                (((size_t)(b * HW + (ok ? gy : 0)) * HW + (ok ? gx : 0)) * CIN +
                 ic0 + kg * 8);
            cp16(dst, src, ok ? 16u : 0u);
        }
    }
}

template <int P>
__device__ __forceinline__ void k2_compute(
    uint32_t stg, int warp_m, int warp_n, int lane, float acc[2][2][4][4]) {
    constexpr int NT = P ? 3 : 6;
    constexpr int NS = P ? 2 : 4;
    const int TL_CL[2][6] = {{0, 1, 0, 0, 1, 0}, {0, 1, 0, 0, 0, 0}};
    const int TL_SF[2][6] = {{0, 0, 1, 2, 2, 3}, {0, 0, 1, 0, 0, 0}};

    int n_loc = (lane & 7) + ((lane >> 4) << 3);
    int kgB = (lane >> 3) & 1;
    int ocA = lane & 15;
    int kgA = lane >> 4;

#pragma unroll
    for (int kgp = 0; kgp < 2; kgp++) {
        uint32_t bf[NS][2][4];
#pragma unroll
        for (int s = 0; s < NS; s++) {
            int sy = s >> 1, sx = s & 1;
#pragma unroll
            for (int t = 0; t < 2; t++) {
                int pnum = warp_n * 32 + t * 16 + n_loc;
                int pyo = pnum >> 4, pxo = pnum & 15;
                int pix = (pyo + 1 - sy) * 17 + (pxo + 1 - sx);
                ldsm4(bf[s][t], stg + XOFF + ((kgp * 2 + kgB) * XPITCH + pix) * 16);
            }
        }
#pragma unroll
        for (int ti = 0; ti < NT; ti++) {
            int cl = TL_CL[P][ti], h = TL_SF[P][ti];
            uint32_t af[2][4];
#pragma unroll
            for (int mf = 0; mf < 2; mf++)
                ldsm4(af[mf], stg + ((ti * 4 + kgp * 2 + kgA) * 128 +
                                     warp_m * 32 + mf * 16 + ocA) * 16);
#pragma unroll
            for (int mf = 0; mf < 2; mf++)
#pragma unroll
                for (int nf = 0; nf < 4; nf++)
                    mma16816(acc[cl][mf][nf], af[mf], &bf[h][nf >> 1][(nf & 1) * 2]);
        }
    }
}

// ---- edge strip loader: 3 taps, 1-D pixel strip of 68 slots (66..67 zero)
__device__ __forceinline__ void k2e_load_slot(
    uint32_t stg, int strip, int ch, int b, int oc0, int tid) {
    int ic0 = ch * 32;
    for (int i = tid; i < 1808; i += 512) {
        if (i < 1536) {
            int tapIdx = i >> 9;
            int rem = i & 511;
            int kg = rem >> 7, oc = rem & 127;
            uint32_t dst = stg + ((tapIdx * 4 + kg) * 128 + oc) * 16;
            const __half* src = g_wh +
                (((size_t)(b * 9 + c_etap[strip][tapIdx]) * COUT + oc0 + oc) * CIN +
                 ic0 + kg * 8);
            cp16(dst, src, 16);
        } else {
            int j = i - 1536;              // 0..271 = 4 kg * 68 slots
            int kg = j / 68;
            int slot = j - kg * 68;
            int ix = slot - 1;
            bool ok = ((unsigned)ix < 64u) && (slot < 66);
            size_t xi = (strip == 0)
                ? ((size_t)(b * HW + 63) * HW + (ok ? ix : 0))
                : ((size_t)(b * HW + (ok ? ix : 0)) * HW + 63);
            uint32_t dst = stg + E_XOFF + (kg * 68 + slot) * 16;
            cp16(dst, g_xh + xi * CIN + ic0 + kg * 8, ok ? 16u : 0u);
        }
    }
}

__device__ __forceinline__ void k2e_compute(
    uint32_t stg, int warp_m, int warp_n, int lane, float acc[2][2][4][4]) {
    const int CL[3] = {0, 1, 0}, SF[3] = {0, 0, 1};
    int n_loc = (lane & 7) + ((lane >> 4) << 3);
    int kgB = (lane >> 3) & 1;
    int ocA = lane & 15;
    int kgA = lane >> 4;
#pragma unroll
    for (int kgp = 0; kgp < 2; kgp++) {
        uint32_t bf[2][2][4];
#pragma unroll
        for (int s = 0; s < 2; s++) {
#pragma unroll
            for (int t = 0; t < 2; t++) {
                int p = warp_n * 32 + t * 16 + n_loc;
                int slot = ((p <= 64) ? p : 65) + 1 - s;
                ldsm4(bf[s][t], stg + E_XOFF + ((kgp * 2 + kgB) * 68 + slot) * 16);
            }
        }
#pragma unroll
        for (int ti = 0; ti < 3; ti++) {
            uint32_t af[2][4];
#pragma unroll
            for (int mf = 0; mf < 2; mf++)
                ldsm4(af[mf], stg + ((ti * 4 + kgp * 2 + kgA) * 128 +
                                     warp_m * 32 + mf * 16 + ocA) * 16);
#pragma unroll
            for (int mf = 0; mf < 2; mf++)
#pragma unroll
                for (int nf = 0; nf < 4; nf++)
                    mma16816(acc[CL[ti]][mf][nf], af[mf], &bf[SF[ti]][nf >> 1][(nf & 1) * 2]);
        }
    }
}

__global__ __launch_bounds__(512, 1) void k2_mma() {
    extern __shared__ char smraw[];
    uint32_t sb = smem_u32(smraw);
    int tid = threadIdx.x;
    int wid = tid >> 5, lane = tid & 31;
    int warp_m = wid & 3;
    int warp_n = wid >> 2;
    int b = blockIdx.z;
    int oc0 = blockIdx.y * 128;
    int bx = blockIdx.x;
    int r0 = lane >> 2, cq = lane & 3;

    float acc[2][2][4][4];
#pragma unroll
    for (int c = 0; c < 2; c++)
#pragma unroll
        for (int mf = 0; mf < 2; mf++)
#pragma unroll
            for (int nf = 0; nf < 4; nf++)
#pragma unroll
                for (int k = 0; k < 4; k++) acc[c][mf][nf][k] = 0.f;

    if (bx < 32) {
        // ---------------- main tiles: exact m,n in [0,64)^2 ----------------
        int x0 = (bx & 3) * 16, y0 = (bx >> 2) * 8;
        for (int s = 0; s < 2; s++) {
            k2_load_slot(sb + s * STAGE, 0, s, b, oc0, x0, y0, tid);
            asm volatile("cp.async.commit_group;" ::: "memory");
        }
        for (int slot = 0; slot < 32; slot++) {
            asm volatile("cp.async.wait_group 1;" ::: "memory");
            __syncthreads();
            uint32_t stg = sb + (slot % 3) * STAGE;
            if (slot < 16) k2_compute<0>(stg, warp_m, warp_n, lane, acc);
            else           k2_compute<1>(stg, warp_m, warp_n, lane, acc);

            if (slot == 15 || slot == 31) {
                int p = slot >> 4;
#pragma unroll
                for (int mf = 0; mf < 2; mf++)
#pragma unroll
                    for (int rr = 0; rr < 2; rr++) {
                        int oc = oc0 + warp_m * 32 + mf * 16 + rr * 8 + r0;
                        size_t rowb = ((size_t)b * COUT + oc) * OBR;
#pragma unroll
                        for (int nf = 0; nf < 4; nf++) {
                            int m = y0 + warp_n * 2 + (nf >> 1);
                            int n = x0 + (nf & 1) * 8 + cq * 2;
                            int row = 2 * m + p;
                            __half2 lo = __floats2half2_rn(acc[0][mf][nf][rr * 2],
                                                           acc[1][mf][nf][rr * 2]);
                            __half2 hi = __floats2half2_rn(acc[0][mf][nf][rr * 2 + 1],
                                                           acc[1][mf][nf][rr * 2 + 1]);
                            uint2 v = make_uint2(*(uint32_t*)&lo, *(uint32_t*)&hi);
                            *(uint2*)&g_obh[(rowb + row) * OBP + 2 * n] = v;
                        }
                    }
                if (slot == 15) {
#pragma unroll
                    for (int c = 0; c < 2; c++)
#pragma unroll
                        for (int mf = 0; mf < 2; mf++)
#pragma unroll
                            for (int nf = 0; nf < 4; nf++)
#pragma unroll
                                for (int k = 0; k < 4; k++) acc[c][mf][nf][k] = 0.f;
                }
            }
            int nx = slot + 2;
            if (nx < 32)
                k2_load_slot(sb + (nx % 3) * STAGE, nx >> 4, nx & 15, b, oc0, x0, y0, tid);
            asm volatile("cp.async.commit_group;" ::: "memory");
        }
    } else {
        // ---------------- edge strips: out row 128 (strip 0), col 128 (strip 1)
        int strip = bx - 32;
        for (int s = 0; s < 2; s++) {
            k2e_load_slot(sb + s * E_STAGE, strip, s, b, oc0, tid);
            asm volatile("cp.async.commit_group;" ::: "memory");
        }
        for (int slot = 0; slot < 16; slot++) {
            asm volatile("cp.async.wait_group 1;" ::: "memory");
            __syncthreads();
            k2e_compute(sb + (slot % 3) * E_STAGE, warp_m, warp_n, lane, acc);
            int nx = slot + 2;
            if (nx < 16)
                k2e_load_slot(sb + (nx % 3) * E_STAGE, strip, nx, b, oc0, tid);
            asm volatile("cp.async.commit_group;" ::: "memory");
        }
#pragma unroll
        for (int mf = 0; mf < 2; mf++)
#pragma unroll
            for (int rr = 0; rr < 2; rr++) {
                int oc = oc0 + warp_m * 32 + mf * 16 + rr * 8 + r0;
                size_t rowb = ((size_t)b * COUT + oc) * OBR;
#pragma unroll
                for (int nf = 0; nf < 4; nf++) {
#pragma unroll
                    for (int kk = 0; kk < 2; kk++) {
                        int p = warp_n * 32 + (nf >> 1) * 16 + (nf & 1) * 8 + cq * 2 + kk;
#pragma unroll
                        for (int cls = 0; cls < 2; cls++) {
                            float val = acc[cls][mf][nf][rr * 2 + kk];
                            if (strip == 0) {
                                int col = 2 * p + cls;
                                if (col <= 128)
                                    g_obh[(rowb + 128) * OBP + col] = __float2half_rn(val);
                            } else {
                                if (p <= 63)
                                    g_obh[(rowb + 2 * p + cls) * OBP + 128] =
                                        __float2half_rn(val);
                            }
                        }
                    }
                }
            }
    }
}

// ---------------------------------------------------------------------------
// K3: separable 4x4 blur + noise + bias + leaky_relu(0.2)*sqrt(2)
// ---------------------------------------------------------------------------
__global__ __launch_bounds__(256) void k3_blur(const float* __restrict__ noise,
                                               const float* __restrict__ noise_w,
                                               const float* __restrict__ act_b,
                                               float* __restrict__ out) {
    __shared__ float sb[35][36];
    __shared__ float tmp[35][32];
    int tid = threadIdx.x;
    int x0 = (blockIdx.x & 3) * 32, y0 = (blockIdx.x >> 2) * 32;
    int bc = blockIdx.z;
    int oc = bc & 255, b = bc >> 8;
    size_t obc = (size_t)bc * OBR;

    for (int idx = tid; idx < 35 * 35; idx += 256) {
        int i = idx / 35, j = idx - i * 35;
        int ry = y0 - 1 + i, rx = x0 - 1 + j;
        float v = 0.f;
        if ((unsigned)ry <= 128u && (unsigned)rx <= 128u)
            v = __half2float(g_obh[(obc + ry) * OBP + rx]);
        sb[i][j] = v;
    }
    __syncthreads();
    for (int idx = tid; idx < 35 * 32; idx += 256) {
        int i = idx >> 5, lx = idx & 31;
        tmp[i][lx] = 0.25f * sb[i][lx] + 0.75f * sb[i][lx + 1] +
                     0.75f * sb[i][lx + 2] + 0.25f * sb[i][lx + 3];
    }
    __syncthreads();
    float nw = noise_w[0];
    float ab = act_b[oc];
    int lx = tid & 31, tyg = tid >> 5;
#pragma unroll
    for (int r = 0; r < 4; r++) {
        int ly = tyg + 8 * r;
        float t = 0.25f * tmp[ly][lx] + 0.75f * tmp[ly + 1][lx] +
                  0.75f * tmp[ly + 2][lx] + 0.25f * tmp[ly + 3][lx];
        int y = y0 + ly, xg = x0 + lx;
        t += nw * noise[((size_t)b * FHW + y) * FHW + xg];
        t += ab;
        t = (t > 0.f ? t : 0.2f * t) * 1.4142135623730951f;
        out[((size_t)bc * FHW + y) * FHW + xg] = t;
    }
}

// ---------------------------------------------------------------------------
extern "C" void kernel_launch(void* const* d_in, const int* in_sizes, int n_in,
                              void* d_out, int out_size) {
    const float* x       = (const float*)d_in[0];
    const float* style   = (const float*)d_in[1];
    const float* noise   = (const float*)d_in[2];
    const float* weight  = (const float*)d_in[3];
    const float* mod_w   = (const float*)d_in[4];
    const float* mod_b   = (const float*)d_in[5];
    const float* noise_w = (const float*)d_in[6];
    const float* act_b   = (const float*)d_in[7];
    float* out = (float*)d_out;

    cudaFuncSetAttribute(k2_mma, cudaFuncAttributeMaxDynamicSharedMemorySize, K2_SMEM);

    k0_style<<<BN, CIN>>>(style, mod_w, mod_b);
    k1_mod<<<BN * COUT, CIN>>>(weight);
    k_xt<<<dim3(HW, 16, BN), 256>>>(x);
    k2_mma<<<dim3(34, 2, BN), 512, K2_SMEM>>>();
    k3_blur<<<dim3(16, 1, 2048), 256>>>(noise, noise_w, act_b, out);
}

// round 9
// speedup vs baseline: 8.7932x; 1.0672x over previous
#include <cuda_runtime.h>
#include <cuda_fp16.h>
#include <cstdint>

#define BN 8
#define CIN 512
#define COUT 256
#define HW 64
#define OBR 129
#define OBP 132
#define FHW 128

// ---------------- scratch (static device globals; no runtime alloc) ----------
__device__ float  g_s[BN * CIN];                           // modulation scales
__device__ __half g_xh[(size_t)BN * HW * HW * CIN];        // x [b][y][x][ic] fp16
__device__ __half g_wh[(size_t)BN * 9 * COUT * CIN];       // w [b][tap][oc][ic] fp16
__device__ __half g_obh[(size_t)BN * COUT * OBR * OBP];    // conv-transpose out fp16

// ---------------- helpers ----------------------------------------------------
__device__ __forceinline__ uint32_t smem_u32(const void* p) {
    uint32_t a;
    asm("{ .reg .u64 t; cvta.to.shared.u64 t, %1; cvt.u32.u64 %0, t; }" : "=r"(a) : "l"(p));
    return a;
}
__device__ __forceinline__ void cp16(uint32_t saddr, const void* g, uint32_t sz) {
    asm volatile("cp.async.cg.shared.global [%0], [%1], 16, %2;"
                 :: "r"(saddr), "l"(g), "r"(sz) : "memory");
}
__device__ __forceinline__ void ldsm4(uint32_t* r, uint32_t addr) {
    asm volatile("ldmatrix.sync.aligned.m8n8.x4.shared.b16 {%0,%1,%2,%3}, [%4];"
                 : "=r"(r[0]), "=r"(r[1]), "=r"(r[2]), "=r"(r[3]) : "r"(addr));
}
__device__ __forceinline__ void mma16816(float* d, const uint32_t* a, const uint32_t* b) {
    asm volatile("mma.sync.aligned.m16n8k16.row.col.f32.f16.f16.f32 "
                 "{%0,%1,%2,%3}, {%4,%5,%6,%7}, {%8,%9}, {%0,%1,%2,%3};"
                 : "+f"(d[0]), "+f"(d[1]), "+f"(d[2]), "+f"(d[3])
                 : "r"(a[0]), "r"(a[1]), "r"(a[2]), "r"(a[3]), "r"(b[0]), "r"(b[1]));
}

// ---------------------------------------------------------------------------
// K0: s[b][ic] = (style[b] . mod_w[ic]) / sqrt(512) + mod_b[ic]
// ---------------------------------------------------------------------------
__global__ void k0_style(const float* __restrict__ style,
                         const float* __restrict__ mod_w,
                         const float* __restrict__ mod_b) {
    int b = blockIdx.x, ic = threadIdx.x;
    __shared__ float st[CIN];
    st[ic] = style[b * CIN + ic] * 0.04419417382415922f;
    __syncthreads();
    const float* mw = mod_w + (size_t)ic * CIN;
    float acc = 0.f;
#pragma unroll 8
    for (int j = 0; j < CIN; j++) acc += st[j] * mw[j];
    g_s[b * CIN + ic] = acc + mod_b[ic];
}

// ---------------------------------------------------------------------------
// K1: modulate + demodulate -> g_wh[b][tap][oc][ic] fp16 (shfl reduction)
// ---------------------------------------------------------------------------
__global__ void k1_mod(const float* __restrict__ weight) {
    int bo = blockIdx.x;
    int b = bo >> 8, oc = bo & 255;
    int ic = threadIdx.x;
    float sv = g_s[b * CIN + ic];
    const float sc = 0.014731391274719738f;  // 1/sqrt(512*9)
    float t[9], ss = 0.f;
    const float* wp = weight + ((size_t)oc * CIN + ic) * 9;
#pragma unroll
    for (int k = 0; k < 9; k++) { t[k] = sc * wp[k] * sv; ss += t[k] * t[k]; }
#pragma unroll
    for (int o = 16; o; o >>= 1) ss += __shfl_xor_sync(0xFFFFFFFFu, ss, o);
    __shared__ float red[16];
    if ((ic & 31) == 0) red[ic >> 5] = ss;
    __syncthreads();
    if (ic < 32) {
        float v = (ic < 16) ? red[ic] : 0.f;
#pragma unroll
        for (int o = 8; o; o >>= 1) v += __shfl_xor_sync(0xFFFFFFFFu, v, o);
        if (ic == 0) red[0] = v;
    }
    __syncthreads();
    float dem = rsqrtf(red[0] + 1e-8f);
#pragma unroll
    for (int k = 0; k < 9; k++)
        g_wh[((size_t)(b * 9 + k) * COUT + oc) * CIN + ic] = __float2half_rn(t[k] * dem);
}

// ---------------------------------------------------------------------------
// KXT: transpose x [b][ic][y][x] -> g_xh [b][y][x][ic] fp16
// ---------------------------------------------------------------------------
__global__ __launch_bounds__(256) void k_xt(const float* __restrict__ x) {
    int y = blockIdx.x, icg = blockIdx.y, b = blockIdx.z;
    int ic0 = icg * 32;
    int tid = threadIdx.x;
    __shared__ float t[32][65];
    for (int idx = tid; idx < 2048; idx += 256) {
        int icl = idx >> 6, xx = idx & 63;
        t[icl][xx] = x[((size_t)(b * CIN + ic0 + icl) * HW + y) * HW + xx];
    }
    __syncthreads();
    for (int idx = tid; idx < 1024; idx += 256) {
        int xx = idx >> 4, icp = idx & 15;
        __half2 v = __floats2half2_rn(t[icp * 2][xx], t[icp * 2 + 1][xx]);
        *(__half2*)&g_xh[((size_t)(b * HW + y) * HW + xx) * CIN + ic0 + icp * 2] = v;
    }
}

// ---------------------------------------------------------------------------
// K2: implicit-GEMM conv-transpose, HMMA fp16/fp32. (unchanged from R7)
// ---------------------------------------------------------------------------
#define XOFF 49152
#define XPITCH 160
#define STAGE 59392
#define K2_SMEM (3 * STAGE)

#define E_XOFF 24576
#define E_STAGE 28928

__device__ __constant__ int c_tap[9] = {0, 1, 2, 6, 7, 8, 3, 4, 5};
__device__ __constant__ int c_etap[2][3] = {{6, 7, 8}, {2, 5, 8}};

__device__ __forceinline__ void k2_load_slot(
    uint32_t stg, int p, int ch, int b, int oc0, int x0, int y0, int tid) {
    int ic0 = ch * 32;
    int nt = p ? 3 : 6;
    int tapbase = p ? 6 : 0;
    int nW = nt * 512;
    int total = nW + 612;
    for (int i = tid; i < total; i += 512) {
        if (i < nW) {
            int tapIdx = i >> 9;
            int rem = i & 511;
            int kg = rem >> 7, oc = rem & 127;
            uint32_t dst = stg + ((tapIdx * 4 + kg) * 128 + oc) * 16;
            const __half* src = g_wh +
                (((size_t)(b * 9 + c_tap[tapbase + tapIdx]) * COUT + oc0 + oc) * CIN +
                 ic0 + kg * 8);
            cp16(dst, src, 16);
        } else {
            int j = i - nW;
            int kg = j / 153;
            int pix = j - kg * 153;
            int py = pix / 17, px = pix - py * 17;
            int gy = y0 - 1 + py, gx = x0 - 1 + px;
            bool ok = ((unsigned)gy < 64u) && ((unsigned)gx < 64u);
            uint32_t dst = stg + XOFF + (kg * XPITCH + pix) * 16;
            const __half* src = g_xh +
                (((size_t)(b * HW + (ok ? gy : 0)) * HW + (ok ? gx : 0)) * CIN +
                 ic0 + kg * 8);
            cp16(dst, src, ok ? 16u : 0u);
        }
    }
}

template <int P>
__device__ __forceinline__ void k2_compute(
    uint32_t stg, int warp_m, int warp_n, int lane, float acc[2][2][4][4]) {
    constexpr int NT = P ? 3 : 6;
    constexpr int NS = P ? 2 : 4;
    const int TL_CL[2][6] = {{0, 1, 0, 0, 1, 0}, {0, 1, 0, 0, 0, 0}};
    const int TL_SF[2][6] = {{0, 0, 1, 2, 2, 3}, {0, 0, 1, 0, 0, 0}};

    int n_loc = (lane & 7) + ((lane >> 4) << 3);
    int kgB = (lane >> 3) & 1;
    int ocA = lane & 15;
    int kgA = lane >> 4;

#pragma unroll
    for (int kgp = 0; kgp < 2; kgp++) {
        uint32_t bf[NS][2][4];
#pragma unroll
        for (int s = 0; s < NS; s++) {
            int sy = s >> 1, sx = s & 1;
#pragma unroll
            for (int t = 0; t < 2; t++) {
                int pnum = warp_n * 32 + t * 16 + n_loc;
                int pyo = pnum >> 4, pxo = pnum & 15;
                int pix = (pyo + 1 - sy) * 17 + (pxo + 1 - sx);
                ldsm4(bf[s][t], stg + XOFF + ((kgp * 2 + kgB) * XPITCH + pix) * 16);
            }
        }
#pragma unroll
        for (int ti = 0; ti < NT; ti++) {
            int cl = TL_CL[P][ti], h = TL_SF[P][ti];
            uint32_t af[2][4];
#pragma unroll
            for (int mf = 0; mf < 2; mf++)
                ldsm4(af[mf], stg + ((ti * 4 + kgp * 2 + kgA) * 128 +
                                     warp_m * 32 + mf * 16 + ocA) * 16);
#pragma unroll
            for (int mf = 0; mf < 2; mf++)
#pragma unroll
                for (int nf = 0; nf < 4; nf++)
                    mma16816(acc[cl][mf][nf], af[mf], &bf[h][nf >> 1][(nf & 1) * 2]);
        }
    }
}

__device__ __forceinline__ void k2e_load_slot(
    uint32_t stg, int strip, int ch, int b, int oc0, int tid) {
    int ic0 = ch * 32;
    for (int i = tid; i < 1808; i += 512) {
        if (i < 1536) {
            int tapIdx = i >> 9;
            int rem = i & 511;
            int kg = rem >> 7, oc = rem & 127;
            uint32_t dst = stg + ((tapIdx * 4 + kg) * 128 + oc) * 16;
            const __half* src = g_wh +
                (((size_t)(b * 9 + c_etap[strip][tapIdx]) * COUT + oc0 + oc) * CIN +
                 ic0 + kg * 8);
            cp16(dst, src, 16);
        } else {
            int j = i - 1536;
            int kg = j / 68;
            int slot = j - kg * 68;
            int ix = slot - 1;
            bool ok = ((unsigned)ix < 64u) && (slot < 66);
            size_t xi = (strip == 0)
                ? ((size_t)(b * HW + 63) * HW + (ok ? ix : 0))
                : ((size_t)(b * HW + (ok ? ix : 0)) * HW + 63);
            uint32_t dst = stg + E_XOFF + (kg * 68 + slot) * 16;
            cp16(dst, g_xh + xi * CIN + ic0 + kg * 8, ok ? 16u : 0u);
        }
    }
}

__device__ __forceinline__ void k2e_compute(
    uint32_t stg, int warp_m, int warp_n, int lane, float acc[2][2][4][4]) {
    const int CL[3] = {0, 1, 0}, SF[3] = {0, 0, 1};
    int n_loc = (lane & 7) + ((lane >> 4) << 3);
    int kgB = (lane >> 3) & 1;
    int ocA = lane & 15;
    int kgA = lane >> 4;
#pragma unroll
    for (int kgp = 0; kgp < 2; kgp++) {
        uint32_t bf[2][2][4];
#pragma unroll
        for (int s = 0; s < 2; s++) {
#pragma unroll
            for (int t = 0; t < 2; t++) {
                int p = warp_n * 32 + t * 16 + n_loc;
                int slot = ((p <= 64) ? p : 65) + 1 - s;
                ldsm4(bf[s][t], stg + E_XOFF + ((kgp * 2 + kgB) * 68 + slot) * 16);
            }
        }
#pragma unroll
        for (int ti = 0; ti < 3; ti++) {
            uint32_t af[2][4];
#pragma unroll
            for (int mf = 0; mf < 2; mf++)
                ldsm4(af[mf], stg + ((ti * 4 + kgp * 2 + kgA) * 128 +
                                     warp_m * 32 + mf * 16 + ocA) * 16);
#pragma unroll
            for (int mf = 0; mf < 2; mf++)
#pragma unroll
                for (int nf = 0; nf < 4; nf++)
                    mma16816(acc[CL[ti]][mf][nf], af[mf], &bf[SF[ti]][nf >> 1][(nf & 1) * 2]);
        }
    }
}

__global__ __launch_bounds__(512, 1) void k2_mma() {
    extern __shared__ char smraw[];
    uint32_t sb = smem_u32(smraw);
    int tid = threadIdx.x;
    int wid = tid >> 5, lane = tid & 31;
    int warp_m = wid & 3;
    int warp_n = wid >> 2;
    int b = blockIdx.z;
    int oc0 = blockIdx.y * 128;
    int bx = blockIdx.x;
    int r0 = lane >> 2, cq = lane & 3;

    float acc[2][2][4][4];
#pragma unroll
    for (int c = 0; c < 2; c++)
#pragma unroll
        for (int mf = 0; mf < 2; mf++)
#pragma unroll
            for (int nf = 0; nf < 4; nf++)
#pragma unroll
                for (int k = 0; k < 4; k++) acc[c][mf][nf][k] = 0.f;

    if (bx < 32) {
        int x0 = (bx & 3) * 16, y0 = (bx >> 2) * 8;
        for (int s = 0; s < 2; s++) {
            k2_load_slot(sb + s * STAGE, 0, s, b, oc0, x0, y0, tid);
            asm volatile("cp.async.commit_group;" ::: "memory");
        }
        for (int slot = 0; slot < 32; slot++) {
            asm volatile("cp.async.wait_group 1;" ::: "memory");
            __syncthreads();
            uint32_t stg = sb + (slot % 3) * STAGE;
            if (slot < 16) k2_compute<0>(stg, warp_m, warp_n, lane, acc);
            else           k2_compute<1>(stg, warp_m, warp_n, lane, acc);

            if (slot == 15 || slot == 31) {
                int p = slot >> 4;
#pragma unroll
                for (int mf = 0; mf < 2; mf++)
#pragma unroll
                    for (int rr = 0; rr < 2; rr++) {
                        int oc = oc0 + warp_m * 32 + mf * 16 + rr * 8 + r0;
                        size_t rowb = ((size_t)b * COUT + oc) * OBR;
#pragma unroll
                        for (int nf = 0; nf < 4; nf++) {
                            int m = y0 + warp_n * 2 + (nf >> 1);
                            int n = x0 + (nf & 1) * 8 + cq * 2;
                            int row = 2 * m + p;
                            __half2 lo = __floats2half2_rn(acc[0][mf][nf][rr * 2],
                                                           acc[1][mf][nf][rr * 2]);
                            __half2 hi = __floats2half2_rn(acc[0][mf][nf][rr * 2 + 1],
                                                           acc[1][mf][nf][rr * 2 + 1]);
                            uint2 v = make_uint2(*(uint32_t*)&lo, *(uint32_t*)&hi);
                            *(uint2*)&g_obh[(rowb + row) * OBP + 2 * n] = v;
                        }
                    }
                if (slot == 15) {
#pragma unroll
                    for (int c = 0; c < 2; c++)
#pragma unroll
                        for (int mf = 0; mf < 2; mf++)
#pragma unroll
                            for (int nf = 0; nf < 4; nf++)
#pragma unroll
                                for (int k = 0; k < 4; k++) acc[c][mf][nf][k] = 0.f;
                }
            }
            int nx = slot + 2;
            if (nx < 32)
                k2_load_slot(sb + (nx % 3) * STAGE, nx >> 4, nx & 15, b, oc0, x0, y0, tid);
            asm volatile("cp.async.commit_group;" ::: "memory");
        }
    } else {
        int strip = bx - 32;
        for (int s = 0; s < 2; s++) {
            k2e_load_slot(sb + s * E_STAGE, strip, s, b, oc0, tid);
            asm volatile("cp.async.commit_group;" ::: "memory");
        }
        for (int slot = 0; slot < 16; slot++) {
            asm volatile("cp.async.wait_group 1;" ::: "memory");
            __syncthreads();
            k2e_compute(sb + (slot % 3) * E_STAGE, warp_m, warp_n, lane, acc);
            int nx = slot + 2;
            if (nx < 16)
                k2e_load_slot(sb + (nx % 3) * E_STAGE, strip, nx, b, oc0, tid);
            asm volatile("cp.async.commit_group;" ::: "memory");
        }
#pragma unroll
        for (int mf = 0; mf < 2; mf++)
#pragma unroll
            for (int rr = 0; rr < 2; rr++) {
                int oc = oc0 + warp_m * 32 + mf * 16 + rr * 8 + r0;
                size_t rowb = ((size_t)b * COUT + oc) * OBR;
#pragma unroll
                for (int nf = 0; nf < 4; nf++) {
#pragma unroll
                    for (int kk = 0; kk < 2; kk++) {
                        int p = warp_n * 32 + (nf >> 1) * 16 + (nf & 1) * 8 + cq * 2 + kk;
#pragma unroll
                        for (int cls = 0; cls < 2; cls++) {
                            float val = acc[cls][mf][nf][rr * 2 + kk];
                            if (strip == 0) {
                                int col = 2 * p + cls;
                                if (col <= 128)
                                    g_obh[(rowb + 128) * OBP + col] = __float2half_rn(val);
                            } else {
                                if (p <= 63)
                                    g_obh[(rowb + 2 * p + cls) * OBP + 128] =
                                        __float2half_rn(val);
                            }
                        }
                    }
                }
            }
    }
}

// ---------------------------------------------------------------------------
// K3: separable 4x4 blur + noise + bias + leaky_relu(0.2)*sqrt(2).
// Full-width 128x32 tiles: coalesced uint32 row loads (g_obh rows contiguous),
// float4 vertical pass, float4 stores. Grid (4 ybands, 2048 bc).
// ---------------------------------------------------------------------------
__global__ __launch_bounds__(256) void k3_blur(const float* __restrict__ noise,
                                               const float* __restrict__ noise_w,
                                               const float* __restrict__ act_b,
                                               float* __restrict__ out) {
    __shared__ __half sraw[35][136];   // half idx = rx + 2 (rx = -1..131)
    __shared__ float tmp[35][128];
    int tid = threadIdx.x;
    int y0 = blockIdx.x * 32;
    int bc = blockIdx.y;
    int oc = bc & 255, b = bc >> 8;
    size_t obc = (size_t)bc * OBR;

    // zero left pad (rx=-1 -> idx1; idx0 unused but zero it too)
    if (tid < 35) *(uint32_t*)&sraw[tid][0] = 0;

    // raw rows: 35 rows x 66 uint32 (halves rx = 2j, 2j+1)
    for (int idx = tid; idx < 35 * 66; idx += 256) {
        int i = idx / 66, j = idx - i * 66;
        int ry = y0 - 1 + i;
        uint32_t v = 0;
        if ((unsigned)ry <= 128u && j < 65) {
            v = *(const uint32_t*)&g_obh[(obc + ry) * OBP + 2 * j];
            if (j == 64) v &= 0xFFFFu;   // rx=128 keep, rx=129 (poison pad) -> 0
        }
        *(uint32_t*)&sraw[i][2 + 2 * j] = v;
    }
    __syncthreads();

    // horizontal: out col x <- rx = x-1..x+2 = sraw idx x+1..x+4
    for (int idx = tid; idx < 35 * 128; idx += 256) {
        int i = idx >> 7, x = idx & 127;
        tmp[i][x] = 0.25f * __half2float(sraw[i][x + 1]) +
                    0.75f * __half2float(sraw[i][x + 2]) +
                    0.75f * __half2float(sraw[i][x + 3]) +
                    0.25f * __half2float(sraw[i][x + 4]);
    }
    __syncthreads();

    float nw = noise_w[0];
    float ab = act_b[oc];
    int xq = (tid & 31) * 4, tyg = tid >> 5;
#pragma unroll
    for (int r = 0; r < 4; r++) {
        int ly = tyg + 8 * r;
        float4 t0 = *(const float4*)&tmp[ly][xq];
        float4 t1 = *(const float4*)&tmp[ly + 1][xq];
        float4 t2 = *(const float4*)&tmp[ly + 2][xq];
        float4 t3 = *(const float4*)&tmp[ly + 3][xq];
        int y = y0 + ly;
        float4 nz = *(const float4*)&noise[((size_t)b * FHW + y) * FHW + xq];
        float4 o;
        o.x = 0.25f * t0.x + 0.75f * t1.x + 0.75f * t2.x + 0.25f * t3.x + nw * nz.x + ab;
        o.y = 0.25f * t0.y + 0.75f * t1.y + 0.75f * t2.y + 0.25f * t3.y + nw * nz.y + ab;
        o.z = 0.25f * t0.z + 0.75f * t1.z + 0.75f * t2.z + 0.25f * t3.z + nw * nz.z + ab;
        o.w = 0.25f * t0.w + 0.75f * t1.w + 0.75f * t2.w + 0.25f * t3.w + nw * nz.w + ab;
        o.x = (o.x > 0.f ? o.x : 0.2f * o.x) * 1.4142135623730951f;
        o.y = (o.y > 0.f ? o.y : 0.2f * o.y) * 1.4142135623730951f;
        o.z = (o.z > 0.f ? o.z : 0.2f * o.z) * 1.4142135623730951f;
        o.w = (o.w > 0.f ? o.w : 0.2f * o.w) * 1.4142135623730951f;
        *(float4*)&out[((size_t)bc * FHW + y) * FHW + xq] = o;
    }
}

// ---------------------------------------------------------------------------
extern "C" void kernel_launch(void* const* d_in, const int* in_sizes, int n_in,
                              void* d_out, int out_size) {
    const float* x       = (const float*)d_in[0];
    const float* style   = (const float*)d_in[1];
    const float* noise   = (const float*)d_in[2];
    const float* weight  = (const float*)d_in[3];
    const float* mod_w   = (const float*)d_in[4];
    const float* mod_b   = (const float*)d_in[5];
    const float* noise_w = (const float*)d_in[6];
    const float* act_b   = (const float*)d_in[7];
    float* out = (float*)d_out;

    cudaFuncSetAttribute(k2_mma, cudaFuncAttributeMaxDynamicSharedMemorySize, K2_SMEM);

    k0_style<<<BN, CIN>>>(style, mod_w, mod_b);
    k1_mod<<<BN * COUT, CIN>>>(weight);
    k_xt<<<dim3(HW, 16, BN), 256>>>(x);
    k2_mma<<<dim3(34, 2, BN), 512, K2_SMEM>>>();
    k3_blur<<<dim3(4, 2048), 256>>>(noise, noise_w, act_b, out);
}

// round 10
// speedup vs baseline: 9.1156x; 1.0367x over previous
#include <cuda_runtime.h>
#include <cuda_fp16.h>
#include <cstdint>

#define BN 8
#define CIN 512
#define COUT 256
#define HW 64
#define OBR 129
#define OBP 132
#define FHW 128

// ---------------- scratch (static device globals; no runtime alloc) ----------
__device__ float  g_s[BN * CIN];                           // modulation scales
__device__ __half g_xh[(size_t)BN * HW * HW * CIN];        // x [b][y][x][ic] fp16
__device__ __half g_wh[(size_t)BN * 9 * COUT * CIN];       // w [b][tap][oc][ic] fp16
__device__ __half g_obh[(size_t)BN * COUT * OBR * OBP];    // conv-transpose out fp16

// ---------------- helpers ----------------------------------------------------
__device__ __forceinline__ uint32_t smem_u32(const void* p) {
    uint32_t a;
    asm("{ .reg .u64 t; cvta.to.shared.u64 t, %1; cvt.u32.u64 %0, t; }" : "=r"(a) : "l"(p));
    return a;
}
__device__ __forceinline__ void cp16(uint32_t saddr, const void* g, uint32_t sz) {
    asm volatile("cp.async.cg.shared.global [%0], [%1], 16, %2;"
                 :: "r"(saddr), "l"(g), "r"(sz) : "memory");
}
__device__ __forceinline__ void ldsm4(uint32_t* r, uint32_t addr) {
    asm volatile("ldmatrix.sync.aligned.m8n8.x4.shared.b16 {%0,%1,%2,%3}, [%4];"
                 : "=r"(r[0]), "=r"(r[1]), "=r"(r[2]), "=r"(r[3]) : "r"(addr));
}
__device__ __forceinline__ void mma16816(float* d, const uint32_t* a, const uint32_t* b) {
    asm volatile("mma.sync.aligned.m16n8k16.row.col.f32.f16.f16.f32 "
                 "{%0,%1,%2,%3}, {%4,%5,%6,%7}, {%8,%9}, {%0,%1,%2,%3};"
                 : "+f"(d[0]), "+f"(d[1]), "+f"(d[2]), "+f"(d[3])
                 : "r"(a[0]), "r"(a[1]), "r"(a[2]), "r"(a[3]), "r"(b[0]), "r"(b[1]));
}

// ---------------------------------------------------------------------------
// K0: s[b][ic] = (style[b] . mod_w[ic]) / sqrt(512) + mod_b[ic]
// ---------------------------------------------------------------------------
__global__ void k0_style(const float* __restrict__ style,
                         const float* __restrict__ mod_w,
                         const float* __restrict__ mod_b) {
    int b = blockIdx.x, ic = threadIdx.x;
    __shared__ float st[CIN];
    st[ic] = style[b * CIN + ic] * 0.04419417382415922f;
    __syncthreads();
    const float* mw = mod_w + (size_t)ic * CIN;
    float acc = 0.f;
#pragma unroll 8
    for (int j = 0; j < CIN; j++) acc += st[j] * mw[j];
    g_s[b * CIN + ic] = acc + mod_b[ic];
}

// ---------------------------------------------------------------------------
// K1: modulate + demodulate -> g_wh[b][tap][oc][ic] fp16 (shfl reduction)
// ---------------------------------------------------------------------------
__global__ void k1_mod(const float* __restrict__ weight) {
    int bo = blockIdx.x;
    int b = bo >> 8, oc = bo & 255;
    int ic = threadIdx.x;
    float sv = g_s[b * CIN + ic];
    const float sc = 0.014731391274719738f;  // 1/sqrt(512*9)
    float t[9], ss = 0.f;
    const float* wp = weight + ((size_t)oc * CIN + ic) * 9;
#pragma unroll
    for (int k = 0; k < 9; k++) { t[k] = sc * wp[k] * sv; ss += t[k] * t[k]; }
#pragma unroll
    for (int o = 16; o; o >>= 1) ss += __shfl_xor_sync(0xFFFFFFFFu, ss, o);
    __shared__ float red[16];
    if ((ic & 31) == 0) red[ic >> 5] = ss;
    __syncthreads();
    if (ic < 32) {
        float v = (ic < 16) ? red[ic] : 0.f;
#pragma unroll
        for (int o = 8; o; o >>= 1) v += __shfl_xor_sync(0xFFFFFFFFu, v, o);
        if (ic == 0) red[0] = v;
    }
    __syncthreads();
    float dem = rsqrtf(red[0] + 1e-8f);
#pragma unroll
    for (int k = 0; k < 9; k++)
        g_wh[((size_t)(b * 9 + k) * COUT + oc) * CIN + ic] = __float2half_rn(t[k] * dem);
}

// ---------------------------------------------------------------------------
// KXT: transpose x [b][ic][y][x] -> g_xh [b][y][x][ic] fp16
// ---------------------------------------------------------------------------
__global__ __launch_bounds__(256) void k_xt(const float* __restrict__ x) {
    int y = blockIdx.x, icg = blockIdx.y, b = blockIdx.z;
    int ic0 = icg * 32;
    int tid = threadIdx.x;
    __shared__ float t[32][65];
    for (int idx = tid; idx < 2048; idx += 256) {
        int icl = idx >> 6, xx = idx & 63;
        t[icl][xx] = x[((size_t)(b * CIN + ic0 + icl) * HW + y) * HW + xx];
    }
    __syncthreads();
    for (int idx = tid; idx < 1024; idx += 256) {
        int xx = idx >> 4, icp = idx & 15;
        __half2 v = __floats2half2_rn(t[icp * 2][xx], t[icp * 2 + 1][xx]);
        *(__half2*)&g_xh[((size_t)(b * HW + y) * HW + xx) * CIN + ic0 + icp * 2] = v;
    }
}

// ---------------------------------------------------------------------------
// K2: implicit-GEMM conv-transpose, HMMA fp16/fp32.
// 256-thread CTAs (8 warps: 2 warp_m x 4 warp_n), M=64 oc, N=128 pos.
// 2 CTAs/SM (independent barrier domains hide ldsm/mma latency + bar skew).
// blockIdx.x<32: main 16x8 pos tiles; 32/33: edge strips. oc quarters via y.
// ---------------------------------------------------------------------------
#define XOFF 24576              // W region: 6 taps * 4 kg * 64 oc * 16B
#define XPITCH 160              // 16B units per kg (153 pix padded)
#define STAGE 34816             // 24576 + 4*160*16
#define K2_SMEM (3 * STAGE)     // 104448

#define E_XOFF 12288            // edge W region: 3 taps * 4 kg * 64 oc * 16B
#define E_STAGE 16640           // 12288 + 4*68*16

__device__ __constant__ int c_tap[9] = {0, 1, 2, 6, 7, 8, 3, 4, 5};
__device__ __constant__ int c_etap[2][3] = {{6, 7, 8}, {2, 5, 8}};

__device__ __forceinline__ void k2_load_slot(
    uint32_t stg, int p, int ch, int b, int oc0, int x0, int y0, int tid) {
    int ic0 = ch * 32;
    int nt = p ? 3 : 6;
    int tapbase = p ? 6 : 0;
    int nW = nt * 256;                 // taps * 4kg * 64oc
    int total = nW + 612;
    for (int i = tid; i < total; i += 256) {
        if (i < nW) {
            int tapIdx = i >> 8;
            int rem = i & 255;
            int kg = rem >> 6, oc = rem & 63;
            uint32_t dst = stg + ((tapIdx * 4 + kg) * 64 + oc) * 16;
            const __half* src = g_wh +
                (((size_t)(b * 9 + c_tap[tapbase + tapIdx]) * COUT + oc0 + oc) * CIN +
                 ic0 + kg * 8);
            cp16(dst, src, 16);
        } else {
            int j = i - nW;
            int kg = j / 153;
            int pix = j - kg * 153;
            int py = pix / 17, px = pix - py * 17;
            int gy = y0 - 1 + py, gx = x0 - 1 + px;
            bool ok = ((unsigned)gy < 64u) && ((unsigned)gx < 64u);
            uint32_t dst = stg + XOFF + (kg * XPITCH + pix) * 16;
            const __half* src = g_xh +
                (((size_t)(b * HW + (ok ? gy : 0)) * HW + (ok ? gx : 0)) * CIN +
                 ic0 + kg * 8);
            cp16(dst, src, ok ? 16u : 0u);
        }
    }
}

template <int P>
__device__ __forceinline__ void k2_compute(
    uint32_t stg, int warp_m, int warp_n, int lane, float acc[2][2][4][4]) {
    constexpr int NT = P ? 3 : 6;
    constexpr int NS = P ? 2 : 4;
    const int TL_CL[2][6] = {{0, 1, 0, 0, 1, 0}, {0, 1, 0, 0, 0, 0}};
    const int TL_SF[2][6] = {{0, 0, 1, 2, 2, 3}, {0, 0, 1, 0, 0, 0}};

    int n_loc = (lane & 7) + ((lane >> 4) << 3);
    int kgB = (lane >> 3) & 1;
    int ocA = lane & 15;
    int kgA = lane >> 4;

#pragma unroll
    for (int kgp = 0; kgp < 2; kgp++) {
        uint32_t bf[NS][2][4];
#pragma unroll
        for (int s = 0; s < NS; s++) {
            int sy = s >> 1, sx = s & 1;
#pragma unroll
            for (int t = 0; t < 2; t++) {
                int pnum = warp_n * 32 + t * 16 + n_loc;
                int pyo = pnum >> 4, pxo = pnum & 15;
                int pix = (pyo + 1 - sy) * 17 + (pxo + 1 - sx);
                ldsm4(bf[s][t], stg + XOFF + ((kgp * 2 + kgB) * XPITCH + pix) * 16);
            }
        }
#pragma unroll
        for (int ti = 0; ti < NT; ti++) {
            int cl = TL_CL[P][ti], h = TL_SF[P][ti];
            uint32_t af[2][4];
#pragma unroll
            for (int mf = 0; mf < 2; mf++)
                ldsm4(af[mf], stg + ((ti * 4 + kgp * 2 + kgA) * 64 +
                                     warp_m * 32 + mf * 16 + ocA) * 16);
#pragma unroll
            for (int mf = 0; mf < 2; mf++)
#pragma unroll
                for (int nf = 0; nf < 4; nf++)
                    mma16816(acc[cl][mf][nf], af[mf], &bf[h][nf >> 1][(nf & 1) * 2]);
        }
    }
}

__device__ __forceinline__ void k2e_load_slot(
    uint32_t stg, int strip, int ch, int b, int oc0, int tid) {
    int ic0 = ch * 32;
    for (int i = tid; i < 1040; i += 256) {
        if (i < 768) {
            int tapIdx = i >> 8;
            int rem = i & 255;
            int kg = rem >> 6, oc = rem & 63;
            uint32_t dst = stg + ((tapIdx * 4 + kg) * 64 + oc) * 16;
            const __half* src = g_wh +
                (((size_t)(b * 9 + c_etap[strip][tapIdx]) * COUT + oc0 + oc) * CIN +
                 ic0 + kg * 8);
            cp16(dst, src, 16);
        } else {
            int j = i - 768;
            int kg = j / 68;
            int slot = j - kg * 68;
            int ix = slot - 1;
            bool ok = ((unsigned)ix < 64u) && (slot < 66);
            size_t xi = (strip == 0)
                ? ((size_t)(b * HW + 63) * HW + (ok ? ix : 0))
                : ((size_t)(b * HW + (ok ? ix : 0)) * HW + 63);
            uint32_t dst = stg + E_XOFF + (kg * 68 + slot) * 16;
            cp16(dst, g_xh + xi * CIN + ic0 + kg * 8, ok ? 16u : 0u);
        }
    }
}

__device__ __forceinline__ void k2e_compute(
    uint32_t stg, int warp_m, int warp_n, int lane, float acc[2][2][4][4]) {
    const int CL[3] = {0, 1, 0}, SF[3] = {0, 0, 1};
    int n_loc = (lane & 7) + ((lane >> 4) << 3);
    int kgB = (lane >> 3) & 1;
    int ocA = lane & 15;
    int kgA = lane >> 4;
#pragma unroll
    for (int kgp = 0; kgp < 2; kgp++) {
        uint32_t bf[2][2][4];
#pragma unroll
        for (int s = 0; s < 2; s++) {
#pragma unroll
            for (int t = 0; t < 2; t++) {
                int p = warp_n * 32 + t * 16 + n_loc;
                int slot = ((p <= 64) ? p : 65) + 1 - s;
                ldsm4(bf[s][t], stg + E_XOFF + ((kgp * 2 + kgB) * 68 + slot) * 16);
            }
        }
#pragma unroll
        for (int ti = 0; ti < 3; ti++) {
            uint32_t af[2][4];
#pragma unroll
            for (int mf = 0; mf < 2; mf++)
                ldsm4(af[mf], stg + ((ti * 4 + kgp * 2 + kgA) * 64 +
                                     warp_m * 32 + mf * 16 + ocA) * 16);
#pragma unroll
            for (int mf = 0; mf < 2; mf++)
#pragma unroll
                for (int nf = 0; nf < 4; nf++)
                    mma16816(acc[CL[ti]][mf][nf], af[mf], &bf[SF[ti]][nf >> 1][(nf & 1) * 2]);
        }
    }
}

__global__ __launch_bounds__(256, 2) void k2_mma() {
    extern __shared__ char smraw[];
    uint32_t sb = smem_u32(smraw);
    int tid = threadIdx.x;
    int wid = tid >> 5, lane = tid & 31;
    int warp_m = wid & 1;        // 32-oc slice (M=64)
    int warp_n = wid >> 1;       // 32-pos slice (N=128)
    int b = blockIdx.z;
    int oc0 = blockIdx.y * 64;
    int bx = blockIdx.x;
    int r0 = lane >> 2, cq = lane & 3;

    float acc[2][2][4][4];
#pragma unroll
    for (int c = 0; c < 2; c++)
#pragma unroll
        for (int mf = 0; mf < 2; mf++)
#pragma unroll
            for (int nf = 0; nf < 4; nf++)
#pragma unroll
                for (int k = 0; k < 4; k++) acc[c][mf][nf][k] = 0.f;

    if (bx < 32) {
        int x0 = (bx & 3) * 16, y0 = (bx >> 2) * 8;
        for (int s = 0; s < 2; s++) {
            k2_load_slot(sb + s * STAGE, 0, s, b, oc0, x0, y0, tid);
            asm volatile("cp.async.commit_group;" ::: "memory");
        }
        for (int slot = 0; slot < 32; slot++) {
            asm volatile("cp.async.wait_group 1;" ::: "memory");
            __syncthreads();
            uint32_t stg = sb + (slot % 3) * STAGE;
            if (slot < 16) k2_compute<0>(stg, warp_m, warp_n, lane, acc);
            else           k2_compute<1>(stg, warp_m, warp_n, lane, acc);

            if (slot == 15 || slot == 31) {
                int p = slot >> 4;
#pragma unroll
                for (int mf = 0; mf < 2; mf++)
#pragma unroll
                    for (int rr = 0; rr < 2; rr++) {
                        int oc = oc0 + warp_m * 32 + mf * 16 + rr * 8 + r0;
                        size_t rowb = ((size_t)b * COUT + oc) * OBR;
#pragma unroll
                        for (int nf = 0; nf < 4; nf++) {
                            int m = y0 + warp_n * 2 + (nf >> 1);
                            int n = x0 + (nf & 1) * 8 + cq * 2;
                            int row = 2 * m + p;
                            __half2 lo = __floats2half2_rn(acc[0][mf][nf][rr * 2],
                                                           acc[1][mf][nf][rr * 2]);
                            __half2 hi = __floats2half2_rn(acc[0][mf][nf][rr * 2 + 1],
                                                           acc[1][mf][nf][rr * 2 + 1]);
                            uint2 v = make_uint2(*(uint32_t*)&lo, *(uint32_t*)&hi);
                            *(uint2*)&g_obh[(rowb + row) * OBP + 2 * n] = v;
                        }
                    }
                if (slot == 15) {
#pragma unroll
                    for (int c = 0; c < 2; c++)
#pragma unroll
                        for (int mf = 0; mf < 2; mf++)
#pragma unroll
                            for (int nf = 0; nf < 4; nf++)
#pragma unroll
                                for (int k = 0; k < 4; k++) acc[c][mf][nf][k] = 0.f;
                }
            }
            int nx = slot + 2;
            if (nx < 32)
                k2_load_slot(sb + (nx % 3) * STAGE, nx >> 4, nx & 15, b, oc0, x0, y0, tid);
            asm volatile("cp.async.commit_group;" ::: "memory");
        }
    } else {
        int strip = bx - 32;
        for (int s = 0; s < 2; s++) {
            k2e_load_slot(sb + s * E_STAGE, strip, s, b, oc0, tid);
            asm volatile("cp.async.commit_group;" ::: "memory");
        }
        for (int slot = 0; slot < 16; slot++) {
            asm volatile("cp.async.wait_group 1;" ::: "memory");
            __syncthreads();
            k2e_compute(sb + (slot % 3) * E_STAGE, warp_m, warp_n, lane, acc);
            int nx = slot + 2;
            if (nx < 16)
                k2e_load_slot(sb + (nx % 3) * E_STAGE, strip, nx, b, oc0, tid);
            asm volatile("cp.async.commit_group;" ::: "memory");
        }
#pragma unroll
        for (int mf = 0; mf < 2; mf++)
#pragma unroll
            for (int rr = 0; rr < 2; rr++) {
                int oc = oc0 + warp_m * 32 + mf * 16 + rr * 8 + r0;
                size_t rowb = ((size_t)b * COUT + oc) * OBR;
#pragma unroll
                for (int nf = 0; nf < 4; nf++) {
#pragma unroll
                    for (int kk = 0; kk < 2; kk++) {
                        int p = warp_n * 32 + (nf >> 1) * 16 + (nf & 1) * 8 + cq * 2 + kk;
#pragma unroll
                        for (int cls = 0; cls < 2; cls++) {
                            float val = acc[cls][mf][nf][rr * 2 + kk];
                            if (strip == 0) {
                                int col = 2 * p + cls;
                                if (col <= 128)
                                    g_obh[(rowb + 128) * OBP + col] = __float2half_rn(val);
                            } else {
                                if (p <= 63)
                                    g_obh[(rowb + 2 * p + cls) * OBP + 128] =
                                        __float2half_rn(val);
                            }
                        }
                    }
                }
            }
    }
}

// ---------------------------------------------------------------------------
// K3: separable 4x4 blur + noise + bias + leaky_relu(0.2)*sqrt(2).
// ---------------------------------------------------------------------------
__global__ __launch_bounds__(256) void k3_blur(const float* __restrict__ noise,
                                               const float* __restrict__ noise_w,
                                               const float* __restrict__ act_b,
                                               float* __restrict__ out) {
    __shared__ __half sraw[35][136];
    __shared__ float tmp[35][128];
    int tid = threadIdx.x;
    int y0 = blockIdx.x * 32;
    int bc = blockIdx.y;
    int oc = bc & 255, b = bc >> 8;
    size_t obc = (size_t)bc * OBR;

    if (tid < 35) *(uint32_t*)&sraw[tid][0] = 0;

    for (int idx = tid; idx < 35 * 66; idx += 256) {
        int i = idx / 66, j = idx - i * 66;
        int ry = y0 - 1 + i;
        uint32_t v = 0;
        if ((unsigned)ry <= 128u && j < 65) {
            v = *(const uint32_t*)&g_obh[(obc + ry) * OBP + 2 * j];
            if (j == 64) v &= 0xFFFFu;
        }
        *(uint32_t*)&sraw[i][2 + 2 * j] = v;
    }
    __syncthreads();

    for (int idx = tid; idx < 35 * 128; idx += 256) {
        int i = idx >> 7, x = idx & 127;
        tmp[i][x] = 0.25f * __half2float(sraw[i][x + 1]) +
                    0.75f * __half2float(sraw[i][x + 2]) +
                    0.75f * __half2float(sraw[i][x + 3]) +
                    0.25f * __half2float(sraw[i][x + 4]);
    }
    __syncthreads();

    float nw = noise_w[0];
    float ab = act_b[oc];
    int xq = (tid & 31) * 4, tyg = tid >> 5;
#pragma unroll
    for (int r = 0; r < 4; r++) {
        int ly = tyg + 8 * r;
        float4 t0 = *(const float4*)&tmp[ly][xq];
        float4 t1 = *(const float4*)&tmp[ly + 1][xq];
        float4 t2 = *(const float4*)&tmp[ly + 2][xq];
        float4 t3 = *(const float4*)&tmp[ly + 3][xq];
        int y = y0 + ly;
        float4 nz = *(const float4*)&noise[((size_t)b * FHW + y) * FHW + xq];
        float4 o;
        o.x = 0.25f * t0.x + 0.75f * t1.x + 0.75f * t2.x + 0.25f * t3.x + nw * nz.x + ab;
        o.y = 0.25f * t0.y + 0.75f * t1.y + 0.75f * t2.y + 0.25f * t3.y + nw * nz.y + ab;
        o.z = 0.25f * t0.z + 0.75f * t1.z + 0.75f * t2.z + 0.25f * t3.z + nw * nz.z + ab;
        o.w = 0.25f * t0.w + 0.75f * t1.w + 0.75f * t2.w + 0.25f * t3.w + nw * nz.w + ab;
        o.x = (o.x > 0.f ? o.x : 0.2f * o.x) * 1.4142135623730951f;
        o.y = (o.y > 0.f ? o.y : 0.2f * o.y) * 1.4142135623730951f;
        o.z = (o.z > 0.f ? o.z : 0.2f * o.z) * 1.4142135623730951f;
        o.w = (o.w > 0.f ? o.w : 0.2f * o.w) * 1.4142135623730951f;
        *(float4*)&out[((size_t)bc * FHW + y) * FHW + xq] = o;
    }
}

// ---------------------------------------------------------------------------
extern "C" void kernel_launch(void* const* d_in, const int* in_sizes, int n_in,
                              void* d_out, int out_size) {
    const float* x       = (const float*)d_in[0];
    const float* style   = (const float*)d_in[1];
    const float* noise   = (const float*)d_in[2];
    const float* weight  = (const float*)d_in[3];
    const float* mod_w   = (const float*)d_in[4];
    const float* mod_b   = (const float*)d_in[5];
    const float* noise_w = (const float*)d_in[6];
    const float* act_b   = (const float*)d_in[7];
    float* out = (float*)d_out;

    cudaFuncSetAttribute(k2_mma, cudaFuncAttributeMaxDynamicSharedMemorySize, K2_SMEM);

    k0_style<<<BN, CIN>>>(style, mod_w, mod_b);
    k1_mod<<<BN * COUT, CIN>>>(weight);
    k_xt<<<dim3(HW, 16, BN), 256>>>(x);
    k2_mma<<<dim3(34, 4, BN), 256, K2_SMEM>>>();
    k3_blur<<<dim3(4, 2048), 256>>>(noise, noise_w, act_b, out);
}

// round 11
// speedup vs baseline: 9.3219x; 1.0226x over previous
#include <cuda_runtime.h>
#include <cuda_fp16.h>
#include <cstdint>

#define BN 8
#define CIN 512
#define COUT 256
#define HW 64
#define OBR 129
#define OBP 132
#define FHW 128

// ---------------- scratch (static device globals; no runtime alloc) ----------
__device__ float  g_s[BN * CIN];                           // modulation scales
__device__ __half g_xh[(size_t)BN * HW * HW * CIN];        // x [b][y][x][ic] fp16
__device__ __half g_wh[(size_t)BN * 9 * COUT * CIN];       // w [b][tap][oc][ic] fp16
__device__ __half g_obh[(size_t)BN * COUT * OBR * OBP];    // conv-transpose out fp16

// ---------------- helpers ----------------------------------------------------
__device__ __forceinline__ uint32_t smem_u32(const void* p) {
    uint32_t a;
    asm("{ .reg .u64 t; cvta.to.shared.u64 t, %1; cvt.u32.u64 %0, t; }" : "=r"(a) : "l"(p));
    return a;
}
__device__ __forceinline__ void cp16(uint32_t saddr, const void* g, uint32_t sz) {
    asm volatile("cp.async.cg.shared.global [%0], [%1], 16, %2;"
                 :: "r"(saddr), "l"(g), "r"(sz) : "memory");
}
__device__ __forceinline__ void ldsm4(uint32_t* r, uint32_t addr) {
    asm volatile("ldmatrix.sync.aligned.m8n8.x4.shared.b16 {%0,%1,%2,%3}, [%4];"
                 : "=r"(r[0]), "=r"(r[1]), "=r"(r[2]), "=r"(r[3]) : "r"(addr));
}
__device__ __forceinline__ void mma16816(float* d, const uint32_t* a, const uint32_t* b) {
    asm volatile("mma.sync.aligned.m16n8k16.row.col.f32.f16.f16.f32 "
                 "{%0,%1,%2,%3}, {%4,%5,%6,%7}, {%8,%9}, {%0,%1,%2,%3};"
                 : "+f"(d[0]), "+f"(d[1]), "+f"(d[2]), "+f"(d[3])
                 : "r"(a[0]), "r"(a[1]), "r"(a[2]), "r"(a[3]), "r"(b[0]), "r"(b[1]));
}

// ---------------------------------------------------------------------------
// K0: s[b][ic] = (style[b] . mod_w[ic]) / sqrt(512) + mod_b[ic]
// ---------------------------------------------------------------------------
__global__ void k0_style(const float* __restrict__ style,
                         const float* __restrict__ mod_w,
                         const float* __restrict__ mod_b) {
    int b = blockIdx.x, ic = threadIdx.x;
    __shared__ float st[CIN];
    st[ic] = style[b * CIN + ic] * 0.04419417382415922f;
    __syncthreads();
    const float* mw = mod_w + (size_t)ic * CIN;
    float acc = 0.f;
#pragma unroll 8
    for (int j = 0; j < CIN; j++) acc += st[j] * mw[j];
    g_s[b * CIN + ic] = acc + mod_b[ic];
}

// ---------------------------------------------------------------------------
// K_PREP: merged k1 (modulate+demodulate, blocks [0,2048)) and
//         k_xt (x transpose->fp16, blocks [2048,10240)). 512 threads.
// ---------------------------------------------------------------------------
__global__ __launch_bounds__(512) void k_prep(const float* __restrict__ weight,
                                              const float* __restrict__ x) {
    int blk = blockIdx.x;
    if (blk < 2048) {
        // ---- k1: one (b, oc) per block, thread = ic
        int b = blk >> 8, oc = blk & 255;
        int ic = threadIdx.x;
        float sv = g_s[b * CIN + ic];
        const float sc = 0.014731391274719738f;  // 1/sqrt(512*9)
        float t[9], ss = 0.f;
        const float* wp = weight + ((size_t)oc * CIN + ic) * 9;
#pragma unroll
        for (int k = 0; k < 9; k++) { t[k] = sc * wp[k] * sv; ss += t[k] * t[k]; }
#pragma unroll
        for (int o = 16; o; o >>= 1) ss += __shfl_xor_sync(0xFFFFFFFFu, ss, o);
        __shared__ float red[16];
        if ((ic & 31) == 0) red[ic >> 5] = ss;
        __syncthreads();
        if (ic < 32) {
            float v = (ic < 16) ? red[ic] : 0.f;
#pragma unroll
            for (int o = 8; o; o >>= 1) v += __shfl_xor_sync(0xFFFFFFFFu, v, o);
            if (ic == 0) red[0] = v;
        }
        __syncthreads();
        float dem = rsqrtf(red[0] + 1e-8f);
#pragma unroll
        for (int k = 0; k < 9; k++)
            g_wh[((size_t)(b * 9 + k) * COUT + oc) * CIN + ic] =
                __float2half_rn(t[k] * dem);
    } else {
        // ---- k_xt: one (b, icg, y) 32ic x 64x tile per block
        int bo = blk - 2048;
        int y = bo & 63, icg = (bo >> 6) & 15, b = bo >> 10;
        int ic0 = icg * 32;
        int tid = threadIdx.x;
        __shared__ float t[32][65];
        {
            int icl = tid >> 4, v = tid & 15;   // 512 threads = 32 ic x 16 float4
            float4 w4 = *(const float4*)&x[((size_t)(b * CIN + ic0 + icl) * HW + y) * HW + v * 4];
            t[icl][v * 4 + 0] = w4.x;
            t[icl][v * 4 + 1] = w4.y;
            t[icl][v * 4 + 2] = w4.z;
            t[icl][v * 4 + 3] = w4.w;
        }
        __syncthreads();
        for (int idx = tid; idx < 1024; idx += 512) {
            int xx = idx >> 4, icp = idx & 15;
            __half2 v = __floats2half2_rn(t[icp * 2][xx], t[icp * 2 + 1][xx]);
            *(__half2*)&g_xh[((size_t)(b * HW + y) * HW + xx) * CIN + ic0 + icp * 2] = v;
        }
    }
}

// ---------------------------------------------------------------------------
// K2: implicit-GEMM conv-transpose, HMMA fp16/fp32.
// 256-thread CTAs (8 warps: 2 warp_m x 4 warp_n), M=64 oc, N=128 pos,
// 2 CTAs/SM. Next-slot load issued BEFORE compute (deep prefetch).
// ---------------------------------------------------------------------------
#define XOFF 24576              // W region: 6 taps * 4 kg * 64 oc * 16B
#define XPITCH 160              // 16B units per kg (153 pix padded)
#define STAGE 34816             // 24576 + 4*160*16
#define K2_SMEM (3 * STAGE)     // 104448

#define E_XOFF 12288            // edge W region: 3 taps * 4 kg * 64 oc * 16B
#define E_STAGE 16640           // 12288 + 4*68*16

__device__ __constant__ int c_tap[9] = {0, 1, 2, 6, 7, 8, 3, 4, 5};
__device__ __constant__ int c_etap[2][3] = {{6, 7, 8}, {2, 5, 8}};

__device__ __forceinline__ void k2_load_slot(
    uint32_t stg, int p, int ch, int b, int oc0, int x0, int y0, int tid) {
    int ic0 = ch * 32;
    int nt = p ? 3 : 6;
    int tapbase = p ? 6 : 0;
    int nW = nt * 256;                 // taps * 4kg * 64oc
    int total = nW + 612;
    for (int i = tid; i < total; i += 256) {
        if (i < nW) {
            int tapIdx = i >> 8;
            int rem = i & 255;
            int kg = rem >> 6, oc = rem & 63;
            uint32_t dst = stg + ((tapIdx * 4 + kg) * 64 + oc) * 16;
            const __half* src = g_wh +
                (((size_t)(b * 9 + c_tap[tapbase + tapIdx]) * COUT + oc0 + oc) * CIN +
                 ic0 + kg * 8);
            cp16(dst, src, 16);
        } else {
            int j = i - nW;
            int kg = j / 153;
            int pix = j - kg * 153;
            int py = pix / 17, px = pix - py * 17;
            int gy = y0 - 1 + py, gx = x0 - 1 + px;
            bool ok = ((unsigned)gy < 64u) && ((unsigned)gx < 64u);
            uint32_t dst = stg + XOFF + (kg * XPITCH + pix) * 16;
            const __half* src = g_xh +
                (((size_t)(b * HW + (ok ? gy : 0)) * HW + (ok ? gx : 0)) * CIN +
                 ic0 + kg * 8);
            cp16(dst, src, ok ? 16u : 0u);
        }
    }
}

template <int P>
__device__ __forceinline__ void k2_compute(
    uint32_t stg, int warp_m, int warp_n, int lane, float acc[2][2][4][4]) {
    constexpr int NT = P ? 3 : 6;
    constexpr int NS = P ? 2 : 4;
    const int TL_CL[2][6] = {{0, 1, 0, 0, 1, 0}, {0, 1, 0, 0, 0, 0}};
    const int TL_SF[2][6] = {{0, 0, 1, 2, 2, 3}, {0, 0, 1, 0, 0, 0}};

    int n_loc = (lane & 7) + ((lane >> 4) << 3);
    int kgB = (lane >> 3) & 1;
    int ocA = lane & 15;
    int kgA = lane >> 4;

#pragma unroll
    for (int kgp = 0; kgp < 2; kgp++) {
        uint32_t bf[NS][2][4];
#pragma unroll
        for (int s = 0; s < NS; s++) {
            int sy = s >> 1, sx = s & 1;
#pragma unroll
            for (int t = 0; t < 2; t++) {
                int pnum = warp_n * 32 + t * 16 + n_loc;
                int pyo = pnum >> 4, pxo = pnum & 15;
                int pix = (pyo + 1 - sy) * 17 + (pxo + 1 - sx);
                ldsm4(bf[s][t], stg + XOFF + ((kgp * 2 + kgB) * XPITCH + pix) * 16);
            }
        }
#pragma unroll
        for (int ti = 0; ti < NT; ti++) {
            int cl = TL_CL[P][ti], h = TL_SF[P][ti];
            uint32_t af[2][4];
#pragma unroll
            for (int mf = 0; mf < 2; mf++)
                ldsm4(af[mf], stg + ((ti * 4 + kgp * 2 + kgA) * 64 +
                                     warp_m * 32 + mf * 16 + ocA) * 16);
#pragma unroll
            for (int mf = 0; mf < 2; mf++)
#pragma unroll
                for (int nf = 0; nf < 4; nf++)
                    mma16816(acc[cl][mf][nf], af[mf], &bf[h][nf >> 1][(nf & 1) * 2]);
        }
    }
}

__device__ __forceinline__ void k2e_load_slot(
    uint32_t stg, int strip, int ch, int b, int oc0, int tid) {
    int ic0 = ch * 32;
    for (int i = tid; i < 1040; i += 256) {
        if (i < 768) {
            int tapIdx = i >> 8;
            int rem = i & 255;
            int kg = rem >> 6, oc = rem & 63;
            uint32_t dst = stg + ((tapIdx * 4 + kg) * 64 + oc) * 16;
            const __half* src = g_wh +
                (((size_t)(b * 9 + c_etap[strip][tapIdx]) * COUT + oc0 + oc) * CIN +
                 ic0 + kg * 8);
            cp16(dst, src, 16);
        } else {
            int j = i - 768;
            int kg = j / 68;
            int slot = j - kg * 68;
            int ix = slot - 1;
            bool ok = ((unsigned)ix < 64u) && (slot < 66);
            size_t xi = (strip == 0)
                ? ((size_t)(b * HW + 63) * HW + (ok ? ix : 0))
                : ((size_t)(b * HW + (ok ? ix : 0)) * HW + 63);
            uint32_t dst = stg + E_XOFF + (kg * 68 + slot) * 16;
            cp16(dst, g_xh + xi * CIN + ic0 + kg * 8, ok ? 16u : 0u);
        }
    }
}

__device__ __forceinline__ void k2e_compute(
    uint32_t stg, int warp_m, int warp_n, int lane, float acc[2][2][4][4]) {
    const int CL[3] = {0, 1, 0}, SF[3] = {0, 0, 1};
    int n_loc = (lane & 7) + ((lane >> 4) << 3);
    int kgB = (lane >> 3) & 1;
    int ocA = lane & 15;
    int kgA = lane >> 4;
#pragma unroll
    for (int kgp = 0; kgp < 2; kgp++) {
        uint32_t bf[2][2][4];
#pragma unroll
        for (int s = 0; s < 2; s++) {
#pragma unroll
            for (int t = 0; t < 2; t++) {
                int p = warp_n * 32 + t * 16 + n_loc;
                int slot = ((p <= 64) ? p : 65) + 1 - s;
                ldsm4(bf[s][t], stg + E_XOFF + ((kgp * 2 + kgB) * 68 + slot) * 16);
            }
        }
#pragma unroll
        for (int ti = 0; ti < 3; ti++) {
            uint32_t af[2][4];
#pragma unroll
            for (int mf = 0; mf < 2; mf++)
                ldsm4(af[mf], stg + ((ti * 4 + kgp * 2 + kgA) * 64 +
                                     warp_m * 32 + mf * 16 + ocA) * 16);
#pragma unroll
            for (int mf = 0; mf < 2; mf++)
#pragma unroll
                for (int nf = 0; nf < 4; nf++)
                    mma16816(acc[CL[ti]][mf][nf], af[mf], &bf[SF[ti]][nf >> 1][(nf & 1) * 2]);
        }
    }
}

__global__ __launch_bounds__(256, 2) void k2_mma() {
    extern __shared__ char smraw[];
    uint32_t sb = smem_u32(smraw);
    int tid = threadIdx.x;
    int wid = tid >> 5, lane = tid & 31;
    int warp_m = wid & 1;        // 32-oc slice (M=64)
    int warp_n = wid >> 1;       // 32-pos slice (N=128)
    int b = blockIdx.z;
    int oc0 = blockIdx.y * 64;
    int bx = blockIdx.x;
    int r0 = lane >> 2, cq = lane & 3;

    float acc[2][2][4][4];
#pragma unroll
    for (int c = 0; c < 2; c++)
#pragma unroll
        for (int mf = 0; mf < 2; mf++)
#pragma unroll
            for (int nf = 0; nf < 4; nf++)
#pragma unroll
                for (int k = 0; k < 4; k++) acc[c][mf][nf][k] = 0.f;

    if (bx < 32) {
        int x0 = (bx & 3) * 16, y0 = (bx >> 2) * 8;
        for (int s = 0; s < 2; s++) {
            k2_load_slot(sb + s * STAGE, 0, s, b, oc0, x0, y0, tid);
            asm volatile("cp.async.commit_group;" ::: "memory");
        }
        for (int slot = 0; slot < 32; slot++) {
            asm volatile("cp.async.wait_group 1;" ::: "memory");
            __syncthreads();
            // deep prefetch: buffer (slot+2)%3 is free after this barrier
            // (its last reader was compute(slot-1)); load it BEFORE compute.
            int nx = slot + 2;
            if (nx < 32)
                k2_load_slot(sb + (nx % 3) * STAGE, nx >> 4, nx & 15, b, oc0, x0, y0, tid);
            asm volatile("cp.async.commit_group;" ::: "memory");

            uint32_t stg = sb + (slot % 3) * STAGE;
            if (slot < 16) k2_compute<0>(stg, warp_m, warp_n, lane, acc);
            else           k2_compute<1>(stg, warp_m, warp_n, lane, acc);

            if (slot == 15 || slot == 31) {
                int p = slot >> 4;
#pragma unroll
                for (int mf = 0; mf < 2; mf++)
#pragma unroll
                    for (int rr = 0; rr < 2; rr++) {
                        int oc = oc0 + warp_m * 32 + mf * 16 + rr * 8 + r0;
                        size_t rowb = ((size_t)b * COUT + oc) * OBR;
#pragma unroll
                        for (int nf = 0; nf < 4; nf++) {
                            int m = y0 + warp_n * 2 + (nf >> 1);
                            int n = x0 + (nf & 1) * 8 + cq * 2;
                            int row = 2 * m + p;
                            __half2 lo = __floats2half2_rn(acc[0][mf][nf][rr * 2],
                                                           acc[1][mf][nf][rr * 2]);
                            __half2 hi = __floats2half2_rn(acc[0][mf][nf][rr * 2 + 1],
                                                           acc[1][mf][nf][rr * 2 + 1]);
                            uint2 v = make_uint2(*(uint32_t*)&lo, *(uint32_t*)&hi);
                            *(uint2*)&g_obh[(rowb + row) * OBP + 2 * n] = v;
                        }
                    }
                if (slot == 15) {
#pragma unroll
                    for (int c = 0; c < 2; c++)
#pragma unroll
                        for (int mf = 0; mf < 2; mf++)
#pragma unroll
                            for (int nf = 0; nf < 4; nf++)
#pragma unroll
                                for (int k = 0; k < 4; k++) acc[c][mf][nf][k] = 0.f;
                }
            }
        }
    } else {
        int strip = bx - 32;
        for (int s = 0; s < 2; s++) {
            k2e_load_slot(sb + s * E_STAGE, strip, s, b, oc0, tid);
            asm volatile("cp.async.commit_group;" ::: "memory");
        }
        for (int slot = 0; slot < 16; slot++) {
            asm volatile("cp.async.wait_group 1;" ::: "memory");
            __syncthreads();
            int nx = slot + 2;
            if (nx < 16)
                k2e_load_slot(sb + (nx % 3) * E_STAGE, strip, nx, b, oc0, tid);
            asm volatile("cp.async.commit_group;" ::: "memory");
            k2e_compute(sb + (slot % 3) * E_STAGE, warp_m, warp_n, lane, acc);
        }
#pragma unroll
        for (int mf = 0; mf < 2; mf++)
#pragma unroll
            for (int rr = 0; rr < 2; rr++) {
                int oc = oc0 + warp_m * 32 + mf * 16 + rr * 8 + r0;
                size_t rowb = ((size_t)b * COUT + oc) * OBR;
#pragma unroll
                for (int nf = 0; nf < 4; nf++) {
#pragma unroll
                    for (int kk = 0; kk < 2; kk++) {
                        int p = warp_n * 32 + (nf >> 1) * 16 + (nf & 1) * 8 + cq * 2 + kk;
#pragma unroll
                        for (int cls = 0; cls < 2; cls++) {
                            float val = acc[cls][mf][nf][rr * 2 + kk];
                            if (strip == 0) {
                                int col = 2 * p + cls;
                                if (col <= 128)
                                    g_obh[(rowb + 128) * OBP + col] = __float2half_rn(val);
                            } else {
                                if (p <= 63)
                                    g_obh[(rowb + 2 * p + cls) * OBP + 128] =
                                        __float2half_rn(val);
                            }
                        }
                    }
                }
            }
    }
}

// ---------------------------------------------------------------------------
// K3: separable 4x4 blur + noise + bias + leaky_relu(0.2)*sqrt(2).
// ---------------------------------------------------------------------------
__global__ __launch_bounds__(256) void k3_blur(const float* __restrict__ noise,
                                               const float* __restrict__ noise_w,
                                               const float* __restrict__ act_b,
                                               float* __restrict__ out) {
    __shared__ __half sraw[35][136];
    __shared__ float tmp[35][128];
    int tid = threadIdx.x;
    int y0 = blockIdx.x * 32;
    int bc = blockIdx.y;
    int oc = bc & 255, b = bc >> 8;
    size_t obc = (size_t)bc * OBR;

    if (tid < 35) *(uint32_t*)&sraw[tid][0] = 0;

    for (int idx = tid; idx < 35 * 66; idx += 256) {
        int i = idx / 66, j = idx - i * 66;
        int ry = y0 - 1 + i;
        uint32_t v = 0;
        if ((unsigned)ry <= 128u && j < 65) {
            v = *(const uint32_t*)&g_obh[(obc + ry) * OBP + 2 * j];
            if (j == 64) v &= 0xFFFFu;
        }
        *(uint32_t*)&sraw[i][2 + 2 * j] = v;
    }
    __syncthreads();

    for (int idx = tid; idx < 35 * 128; idx += 256) {
        int i = idx >> 7, x = idx & 127;
        tmp[i][x] = 0.25f * __half2float(sraw[i][x + 1]) +
                    0.75f * __half2float(sraw[i][x + 2]) +
                    0.75f * __half2float(sraw[i][x + 3]) +
                    0.25f * __half2float(sraw[i][x + 4]);
    }
    __syncthreads();

    float nw = noise_w[0];
    float ab = act_b[oc];
    int xq = (tid & 31) * 4, tyg = tid >> 5;
#pragma unroll
    for (int r = 0; r < 4; r++) {
        int ly = tyg + 8 * r;
        float4 t0 = *(const float4*)&tmp[ly][xq];
        float4 t1 = *(const float4*)&tmp[ly + 1][xq];
        float4 t2 = *(const float4*)&tmp[ly + 2][xq];
        float4 t3 = *(const float4*)&tmp[ly + 3][xq];
        int y = y0 + ly;
        float4 nz = *(const float4*)&noise[((size_t)b * FHW + y) * FHW + xq];
        float4 o;
        o.x = 0.25f * t0.x + 0.75f * t1.x + 0.75f * t2.x + 0.25f * t3.x + nw * nz.x + ab;
        o.y = 0.25f * t0.y + 0.75f * t1.y + 0.75f * t2.y + 0.25f * t3.y + nw * nz.y + ab;
        o.z = 0.25f * t0.z + 0.75f * t1.z + 0.75f * t2.z + 0.25f * t3.z + nw * nz.z + ab;
        o.w = 0.25f * t0.w + 0.75f * t1.w + 0.75f * t2.w + 0.25f * t3.w + nw * nz.w + ab;
        o.x = (o.x > 0.f ? o.x : 0.2f * o.x) * 1.4142135623730951f;
        o.y = (o.y > 0.f ? o.y : 0.2f * o.y) * 1.4142135623730951f;
        o.z = (o.z > 0.f ? o.z : 0.2f * o.z) * 1.4142135623730951f;
        o.w = (o.w > 0.f ? o.w : 0.2f * o.w) * 1.4142135623730951f;
        *(float4*)&out[((size_t)bc * FHW + y) * FHW + xq] = o;
    }
}

// ---------------------------------------------------------------------------
extern "C" void kernel_launch(void* const* d_in, const int* in_sizes, int n_in,
                              void* d_out, int out_size) {
    const float* x       = (const float*)d_in[0];
    const float* style   = (const float*)d_in[1];
    const float* noise   = (const float*)d_in[2];
    const float* weight  = (const float*)d_in[3];
    const float* mod_w   = (const float*)d_in[4];
    const float* mod_b   = (const float*)d_in[5];
    const float* noise_w = (const float*)d_in[6];
    const float* act_b   = (const float*)d_in[7];
    float* out = (float*)d_out;

    cudaFuncSetAttribute(k2_mma, cudaFuncAttributeMaxDynamicSharedMemorySize, K2_SMEM);

    k0_style<<<BN, CIN>>>(style, mod_w, mod_b);
    k_prep<<<10240, 512>>>(weight, x);
    k2_mma<<<dim3(34, 4, BN), 256, K2_SMEM>>>();
    k3_blur<<<dim3(4, 2048), 256>>>(noise, noise_w, act_b, out);
}

// round 13
// speedup vs baseline: 10.5129x; 1.1278x over previous
#include <cuda_runtime.h>
#include <cuda_fp16.h>
#include <cstdint>

#define BN 8
#define CIN 512
#define COUT 256
#define HW 64
#define OBR 129
#define OBP 132
#define FHW 128

// ---------------- scratch (static device globals; no runtime alloc) ----------
__device__ float  g_s[BN * CIN];                           // modulation scales
__device__ __half g_xh[(size_t)BN * HW * HW * CIN];        // x [b][y][x][ic] fp16
// weights reordered: [b][ocq4][ch16][tap'9][kg4][oc64][ic8]  (tap' = c_tap order)
__device__ __align__(128) __half g_wt2[(size_t)BN * 4 * 16 * 9 * 4 * 64 * 8];
__device__ __half g_obh[(size_t)BN * COUT * OBR * OBP];    // conv-transpose out fp16

#define WBLK_HALVES(b, ocq, ch) \
    ((((size_t)((b) * 4 + (ocq)) * 16 + (ch)) * 9) * 2048)

// ---------------- helpers ----------------------------------------------------
__device__ __forceinline__ uint32_t smem_u32(const void* p) {
    uint32_t a;
    asm("{ .reg .u64 t; cvta.to.shared.u64 t, %1; cvt.u32.u64 %0, t; }" : "=r"(a) : "l"(p));
    return a;
}
__device__ __forceinline__ void cp16(uint32_t saddr, const void* g, uint32_t sz) {
    asm volatile("cp.async.cg.shared.global [%0], [%1], 16, %2;"
                 :: "r"(saddr), "l"(g), "r"(sz) : "memory");
}
__device__ __forceinline__ void cpbulk(uint32_t dst, const void* src, uint32_t bytes,
                                       uint32_t mbar) {
    asm volatile("cp.async.bulk.shared::cluster.global.mbarrier::complete_tx::bytes "
                 "[%0], [%1], %2, [%3];"
                 :: "r"(dst), "l"(src), "r"(bytes), "r"(mbar) : "memory");
}
__device__ __forceinline__ void ldsm4(uint32_t* r, uint32_t addr) {
    asm volatile("ldmatrix.sync.aligned.m8n8.x4.shared.b16 {%0,%1,%2,%3}, [%4];"
                 : "=r"(r[0]), "=r"(r[1]), "=r"(r[2]), "=r"(r[3]) : "r"(addr));
}
__device__ __forceinline__ void mma16816(float* d, const uint32_t* a, const uint32_t* b) {
    asm volatile("mma.sync.aligned.m16n8k16.row.col.f32.f16.f16.f32 "
                 "{%0,%1,%2,%3}, {%4,%5,%6,%7}, {%8,%9}, {%0,%1,%2,%3};"
                 : "+f"(d[0]), "+f"(d[1]), "+f"(d[2]), "+f"(d[3])
                 : "r"(a[0]), "r"(a[1]), "r"(a[2]), "r"(a[3]), "r"(b[0]), "r"(b[1]));
}

#define MBARRIER_INIT(addr, cnt) \
    asm volatile("mbarrier.init.shared.b64 [%0], %1;" \
                 :: "r"((uint32_t)(addr)), "r"((uint32_t)(cnt)) : "memory")
#define MBARRIER_EXPECT_TX(addr, tx) \
    asm volatile("mbarrier.arrive.expect_tx.shared.b64 _, [%0], %1;" \
                 :: "r"((uint32_t)(addr)), "r"((uint32_t)(tx)) : "memory")
#define MBARRIER_WAIT_PARITY(addr, parity) do {                                        \
    uint32_t _m = (uint32_t)(addr); uint32_t _p = (uint32_t)(parity); uint32_t _d;     \
    asm volatile("{\n\t.reg .pred p;\n\t"                                              \
        "mbarrier.try_wait.parity.acquire.cta.shared::cta.b64 p, [%1], %2;\n\t"        \
        "selp.b32 %0, 1, 0, p;\n\t}" : "=r"(_d) : "r"(_m), "r"(_p) : "memory");        \
    if (!_d) {                                                                         \
        asm volatile("{\n\t.reg .pred P1;\n\tWL_%=:\n\t"                               \
            "mbarrier.try_wait.parity.acquire.cta.shared::cta.b64 P1, [%0], %1, 0x989680;\n\t" \
            "@P1 bra.uni WD_%=;\n\tbra.uni WL_%=;\n\tWD_%=:\n\t}"                      \
            :: "r"(_m), "r"(_p) : "memory");                                           \
    } } while (0)

// ---------------------------------------------------------------------------
// K0: s[b][ic] = (style[b] . mod_w[ic]) / sqrt(512) + mod_b[ic]
// ---------------------------------------------------------------------------
__global__ void k0_style(const float* __restrict__ style,
                         const float* __restrict__ mod_w,
                         const float* __restrict__ mod_b) {
    int b = blockIdx.x, ic = threadIdx.x;
    __shared__ float st[CIN];
    st[ic] = style[b * CIN + ic] * 0.04419417382415922f;
    __syncthreads();
    const float* mw = mod_w + (size_t)ic * CIN;
    float acc = 0.f;
#pragma unroll 8
    for (int j = 0; j < CIN; j++) acc += st[j] * mw[j];
    g_s[b * CIN + ic] = acc + mod_b[ic];
}

// tap order table (involution: c_tap[c_tap[k]] == k)
__device__ __constant__ int c_tap[9] = {0, 1, 2, 6, 7, 8, 3, 4, 5};

// ---------------------------------------------------------------------------
// K_PREP: merged k1 (modulate+demodulate -> g_wt2 bulk layout, blocks [0,2048))
//         and k_xt (x transpose->fp16, blocks [2048,10240)). 512 threads.
// ---------------------------------------------------------------------------
__global__ __launch_bounds__(512) void k_prep(const float* __restrict__ weight,
                                              const float* __restrict__ x) {
    int blk = blockIdx.x;
    if (blk < 2048) {
        int b = blk >> 8, oc = blk & 255;
        int ic = threadIdx.x;
        float sv = g_s[b * CIN + ic];
        const float sc = 0.014731391274719738f;  // 1/sqrt(512*9)
        float t[9], ss = 0.f;
        const float* wp = weight + ((size_t)oc * CIN + ic) * 9;
#pragma unroll
        for (int k = 0; k < 9; k++) { t[k] = sc * wp[k] * sv; ss += t[k] * t[k]; }
#pragma unroll
        for (int o = 16; o; o >>= 1) ss += __shfl_xor_sync(0xFFFFFFFFu, ss, o);
        __shared__ float red[16];
        if ((ic & 31) == 0) red[ic >> 5] = ss;
        __syncthreads();
        if (ic < 32) {
            float v = (ic < 16) ? red[ic] : 0.f;
#pragma unroll
            for (int o = 8; o; o >>= 1) v += __shfl_xor_sync(0xFFFFFFFFu, v, o);
            if (ic == 0) red[0] = v;
        }
        __syncthreads();
        float dem = rsqrtf(red[0] + 1e-8f);
        size_t base = WBLK_HALVES(b, oc >> 6, ic >> 5);
        int sub = (((ic >> 3) & 3) * 64 + (oc & 63)) * 8 + (ic & 7);
#pragma unroll
        for (int k = 0; k < 9; k++)
            g_wt2[base + (size_t)c_tap[k] * 2048 + sub] = __float2half_rn(t[k] * dem);
    } else {
        int bo = blk - 2048;
        int y = bo & 63, icg = (bo >> 6) & 15, b = bo >> 10;
        int ic0 = icg * 32;
        int tid = threadIdx.x;
        __shared__ float t[32][65];
        {
            int icl = tid >> 4, v = tid & 15;
            float4 w4 = *(const float4*)&x[((size_t)(b * CIN + ic0 + icl) * HW + y) * HW + v * 4];
            t[icl][v * 4 + 0] = w4.x;
            t[icl][v * 4 + 1] = w4.y;
            t[icl][v * 4 + 2] = w4.z;
            t[icl][v * 4 + 3] = w4.w;
        }
        __syncthreads();
        for (int idx = tid; idx < 1024; idx += 512) {
            int xx = idx >> 4, icp = idx & 15;
            __half2 v = __floats2half2_rn(t[icp * 2][xx], t[icp * 2 + 1][xx]);
            *(__half2*)&g_xh[((size_t)(b * HW + y) * HW + xx) * CIN + ic0 + icp * 2] = v;
        }
    }
}

// ---------------------------------------------------------------------------
// K2: implicit-GEMM conv-transpose, HMMA fp16/fp32.
// 256-thread CTAs (M=64 oc, N=128 pos), 2 CTAs/SM. Weights arrive via ONE
// cp.async.bulk per slot (contiguous 24.5/12.3 KB block, mbarrier completion);
// x halo via cp16 groups. 3-stage ring, deep prefetch before compute.
// ---------------------------------------------------------------------------
#define XOFF 24576              // W region: 6 taps * 4 kg * 64 oc * 16B
#define XPITCH 160              // 16B units per kg (153 pix padded)
#define STAGE 34816             // 24576 + 4*160*16
#define K2_SMEM (3 * STAGE + 32)

#define E_XOFF 12288            // edge W region: 3 taps * 4 kg * 64 oc * 16B
#define E_STAGE 16640           // 12288 + 4*68*16

__device__ __constant__ int c_etap[2][3] = {{6, 7, 8}, {2, 5, 8}};

__device__ __forceinline__ void k2_load_slot(
    uint32_t stg, uint32_t mbar, int p, int ch, int b, int ocq,
    int x0, int y0, int tid) {
    int ic0 = ch * 32;
    if (tid == 0) {
        uint32_t wb = p ? 12288u : 24576u;
        MBARRIER_EXPECT_TX(mbar, wb);
        const __half* src = g_wt2 + WBLK_HALVES(b, ocq, ch) + (p ? 6 * 2048 : 0);
        cpbulk(stg, src, wb, mbar);
    }
    for (int j = tid; j < 612; j += 256) {
        int kg = j / 153;
        int pix = j - kg * 153;
        int py = pix / 17, px = pix - py * 17;
        int gy = y0 - 1 + py, gx = x0 - 1 + px;
        bool ok = ((unsigned)gy < 64u) && ((unsigned)gx < 64u);
        uint32_t dst = stg + XOFF + (kg * XPITCH + pix) * 16;
        const __half* src = g_xh +
            (((size_t)(b * HW + (ok ? gy : 0)) * HW + (ok ? gx : 0)) * CIN +
             ic0 + kg * 8);
        cp16(dst, src, ok ? 16u : 0u);
    }
}

template <int P>
__device__ __forceinline__ void k2_compute(
    uint32_t stg, int warp_m, int warp_n, int lane, float acc[2][2][4][4]) {
    constexpr int NT = P ? 3 : 6;
    constexpr int NS = P ? 2 : 4;
    const int TL_CL[2][6] = {{0, 1, 0, 0, 1, 0}, {0, 1, 0, 0, 0, 0}};
    const int TL_SF[2][6] = {{0, 0, 1, 2, 2, 3}, {0, 0, 1, 0, 0, 0}};

    int n_loc = (lane & 7) + ((lane >> 4) << 3);
    int kgB = (lane >> 3) & 1;
    int ocA = lane & 15;
    int kgA = lane >> 4;

#pragma unroll
    for (int kgp = 0; kgp < 2; kgp++) {
        uint32_t bf[NS][2][4];
#pragma unroll
        for (int s = 0; s < NS; s++) {
            int sy = s >> 1, sx = s & 1;
#pragma unroll
            for (int t = 0; t < 2; t++) {
                int pnum = warp_n * 32 + t * 16 + n_loc;
                int pyo = pnum >> 4, pxo = pnum & 15;
                int pix = (pyo + 1 - sy) * 17 + (pxo + 1 - sx);
                ldsm4(bf[s][t], stg + XOFF + ((kgp * 2 + kgB) * XPITCH + pix) * 16);
            }
        }
#pragma unroll
        for (int ti = 0; ti < NT; ti++) {
            int cl = TL_CL[P][ti], h = TL_SF[P][ti];
            uint32_t af[2][4];
#pragma unroll
            for (int mf = 0; mf < 2; mf++)
                ldsm4(af[mf], stg + ((ti * 4 + kgp * 2 + kgA) * 64 +
                                     warp_m * 32 + mf * 16 + ocA) * 16);
#pragma unroll
            for (int mf = 0; mf < 2; mf++)
#pragma unroll
                for (int nf = 0; nf < 4; nf++)
                    mma16816(acc[cl][mf][nf], af[mf], &bf[h][nf >> 1][(nf & 1) * 2]);
        }
    }
}

__device__ __forceinline__ void k2e_load_slot(
    uint32_t stg, uint32_t mbar, int strip, int ch, int b, int ocq, int tid) {
    int ic0 = ch * 32;
    if (tid == 0) {
        MBARRIER_EXPECT_TX(mbar, 12288u);
        // per-tap contiguous 4KB blocks at tap' = c_tap[c_etap[strip][t]]
        const int tp2[2][3] = {{3, 4, 5}, {2, 8, 5}};
        size_t base = WBLK_HALVES(b, ocq, ch);
#pragma unroll
        for (int t = 0; t < 3; t++)
            cpbulk(stg + t * 4096, g_wt2 + base + (size_t)tp2[strip][t] * 2048,
                   4096u, mbar);
    }
    for (int j = tid; j < 272; j += 256) {
        int kg = j / 68;
        int slot = j - kg * 68;
        int ix = slot - 1;
        bool ok = ((unsigned)ix < 64u) && (slot < 66);
        size_t xi = (strip == 0)
            ? ((size_t)(b * HW + 63) * HW + (ok ? ix : 0))
            : ((size_t)(b * HW + (ok ? ix : 0)) * HW + 63);
        uint32_t dst = stg + E_XOFF + (kg * 68 + slot) * 16;
        cp16(dst, g_xh + xi * CIN + ic0 + kg * 8, ok ? 16u : 0u);
    }
}

__device__ __forceinline__ void k2e_compute(
    uint32_t stg, int warp_m, int warp_n, int lane, float acc[2][2][4][4]) {
    const int CL[3] = {0, 1, 0}, SF[3] = {0, 0, 1};
    int n_loc = (lane & 7) + ((lane >> 4) << 3);
    int kgB = (lane >> 3) & 1;
    int ocA = lane & 15;
    int kgA = lane >> 4;
#pragma unroll
    for (int kgp = 0; kgp < 2; kgp++) {
        uint32_t bf[2][2][4];
#pragma unroll
        for (int s = 0; s < 2; s++) {
#pragma unroll
            for (int t = 0; t < 2; t++) {
                int p = warp_n * 32 + t * 16 + n_loc;
                int slot = ((p <= 64) ? p : 65) + 1 - s;
                ldsm4(bf[s][t], stg + E_XOFF + ((kgp * 2 + kgB) * 68 + slot) * 16);
            }
        }
#pragma unroll
        for (int ti = 0; ti < 3; ti++) {
            uint32_t af[2][4];
#pragma unroll
            for (int mf = 0; mf < 2; mf++)
                ldsm4(af[mf], stg + ((ti * 4 + kgp * 2 + kgA) * 64 +
                                     warp_m * 32 + mf * 16 + ocA) * 16);
#pragma unroll
            for (int mf = 0; mf < 2; mf++)
#pragma unroll
                for (int nf = 0; nf < 4; nf++)
                    mma16816(acc[CL[ti]][mf][nf], af[mf], &bf[SF[ti]][nf >> 1][(nf & 1) * 2]);
        }
    }
}

__global__ __launch_bounds__(256, 2) void k2_mma() {
    extern __shared__ char smraw[];
    uint32_t sb = smem_u32(smraw);
    uint32_t mb = sb + 3 * STAGE;        // 3 mbarriers (8B each)
    int tid = threadIdx.x;
    int wid = tid >> 5, lane = tid & 31;
    int warp_m = wid & 1;
    int warp_n = wid >> 1;
    int b = blockIdx.z;
    int ocq = blockIdx.y;
    int oc0 = ocq * 64;
    int bx = blockIdx.x;
    int r0 = lane >> 2, cq = lane & 3;

    if (tid == 0) {
        MBARRIER_INIT(mb + 0, 1);
        MBARRIER_INIT(mb + 8, 1);
        MBARRIER_INIT(mb + 16, 1);
    }
    __syncthreads();

    float acc[2][2][4][4];
#pragma unroll
    for (int c = 0; c < 2; c++)
#pragma unroll
        for (int mf = 0; mf < 2; mf++)
#pragma unroll
            for (int nf = 0; nf < 4; nf++)
#pragma unroll
                for (int k = 0; k < 4; k++) acc[c][mf][nf][k] = 0.f;

    if (bx < 32) {
        int x0 = (bx & 3) * 16, y0 = (bx >> 2) * 8;
        for (int s = 0; s < 2; s++) {
            k2_load_slot(sb + s * STAGE, mb + s * 8, 0, s, b, ocq, x0, y0, tid);
            asm volatile("cp.async.commit_group;" ::: "memory");
        }
        for (int slot = 0; slot < 32; slot++) {
            asm volatile("cp.async.wait_group 1;" ::: "memory");
            MBARRIER_WAIT_PARITY(mb + (slot % 3) * 8, (slot / 3) & 1);
            __syncthreads();
            int nx = slot + 2;
            if (nx < 32)
                k2_load_slot(sb + (nx % 3) * STAGE, mb + (nx % 3) * 8,
                             nx >> 4, nx & 15, b, ocq, x0, y0, tid);
            asm volatile("cp.async.commit_group;" ::: "memory");

            uint32_t stg = sb + (slot % 3) * STAGE;
            if (slot < 16) k2_compute<0>(stg, warp_m, warp_n, lane, acc);
            else           k2_compute<1>(stg, warp_m, warp_n, lane, acc);

            if (slot == 15 || slot == 31) {
                int p = slot >> 4;
#pragma unroll
                for (int mf = 0; mf < 2; mf++)
#pragma unroll
                    for (int rr = 0; rr < 2; rr++) {
                        int oc = oc0 + warp_m * 32 + mf * 16 + rr * 8 + r0;
                        size_t rowb = ((size_t)b * COUT + oc) * OBR;
#pragma unroll
                        for (int nf = 0; nf < 4; nf++) {
                            int m = y0 + warp_n * 2 + (nf >> 1);
                            int n = x0 + (nf & 1) * 8 + cq * 2;
                            int row = 2 * m + p;
                            __half2 lo = __floats2half2_rn(acc[0][mf][nf][rr * 2],
                                                           acc[1][mf][nf][rr * 2]);
                            __half2 hi = __floats2half2_rn(acc[0][mf][nf][rr * 2 + 1],
                                                           acc[1][mf][nf][rr * 2 + 1]);
                            uint2 v = make_uint2(*(uint32_t*)&lo, *(uint32_t*)&hi);
                            *(uint2*)&g_obh[(rowb + row) * OBP + 2 * n] = v;
                        }
                    }
                if (slot == 15) {
#pragma unroll
                    for (int c = 0; c < 2; c++)
#pragma unroll
                        for (int mf = 0; mf < 2; mf++)
#pragma unroll
                            for (int nf = 0; nf < 4; nf++)
#pragma unroll
                                for (int k = 0; k < 4; k++) acc[c][mf][nf][k] = 0.f;
                }
            }
        }
    } else {
        int strip = bx - 32;
        for (int s = 0; s < 2; s++) {
            k2e_load_slot(sb + s * E_STAGE, mb + s * 8, strip, s, b, ocq, tid);
            asm volatile("cp.async.commit_group;" ::: "memory");
        }
        for (int slot = 0; slot < 16; slot++) {
            asm volatile("cp.async.wait_group 1;" ::: "memory");
            MBARRIER_WAIT_PARITY(mb + (slot % 3) * 8, (slot / 3) & 1);
            __syncthreads();
            int nx = slot + 2;
            if (nx < 16)
                k2e_load_slot(sb + (nx % 3) * E_STAGE, mb + (nx % 3) * 8,
                              strip, nx, b, ocq, tid);
            asm volatile("cp.async.commit_group;" ::: "memory");
            k2e_compute(sb + (slot % 3) * E_STAGE, warp_m, warp_n, lane, acc);
        }
#pragma unroll
        for (int mf = 0; mf < 2; mf++)
#pragma unroll
            for (int rr = 0; rr < 2; rr++) {
                int oc = oc0 + warp_m * 32 + mf * 16 + rr * 8 + r0;
                size_t rowb = ((size_t)b * COUT + oc) * OBR;
#pragma unroll
                for (int nf = 0; nf < 4; nf++) {
#pragma unroll
                    for (int kk = 0; kk < 2; kk++) {
                        int p = warp_n * 32 + (nf >> 1) * 16 + (nf & 1) * 8 + cq * 2 + kk;
#pragma unroll
                        for (int cls = 0; cls < 2; cls++) {
                            float val = acc[cls][mf][nf][rr * 2 + kk];
                            if (strip == 0) {
                                int col = 2 * p + cls;
                                if (col <= 128)
                                    g_obh[(rowb + 128) * OBP + col] = __float2half_rn(val);
                            } else {
                                if (p <= 63)
                                    g_obh[(rowb + 2 * p + cls) * OBP + 128] =
                                        __float2half_rn(val);
                            }
                        }
                    }
                }
            }
    }
}

// ---------------------------------------------------------------------------
// K3: separable 4x4 blur + noise + bias + leaky_relu(0.2)*sqrt(2).
// ---------------------------------------------------------------------------
__global__ __launch_bounds__(256) void k3_blur(const float* __restrict__ noise,
                                               const float* __restrict__ noise_w,
                                               const float* __restrict__ act_b,
                                               float* __restrict__ out) {
    __shared__ __half sraw[35][136];
    __shared__ float tmp[35][128];
    int tid = threadIdx.x;
    int y0 = blockIdx.x * 32;
    int bc = blockIdx.y;
    int oc = bc & 255, b = bc >> 8;
    size_t obc = (size_t)bc * OBR;

    if (tid < 35) *(uint32_t*)&sraw[tid][0] = 0;

    for (int idx = tid; idx < 35 * 66; idx += 256) {
        int i = idx / 66, j = idx - i * 66;
        int ry = y0 - 1 + i;
        uint32_t v = 0;
        if ((unsigned)ry <= 128u && j < 65) {
            v = *(const uint32_t*)&g_obh[(obc + ry) * OBP + 2 * j];
            if (j == 64) v &= 0xFFFFu;
        }
        *(uint32_t*)&sraw[i][2 + 2 * j] = v;
    }
    __syncthreads();

    for (int idx = tid; idx < 35 * 128; idx += 256) {
        int i = idx >> 7, x = idx & 127;
        tmp[i][x] = 0.25f * __half2float(sraw[i][x + 1]) +
                    0.75f * __half2float(sraw[i][x + 2]) +
                    0.75f * __half2float(sraw[i][x + 3]) +
                    0.25f * __half2float(sraw[i][x + 4]);
    }
    __syncthreads();

    float nw = noise_w[0];
    float ab = act_b[oc];
    int xq = (tid & 31) * 4, tyg = tid >> 5;
#pragma unroll
    for (int r = 0; r < 4; r++) {
        int ly = tyg + 8 * r;
        float4 t0 = *(const float4*)&tmp[ly][xq];
        float4 t1 = *(const float4*)&tmp[ly + 1][xq];
        float4 t2 = *(const float4*)&tmp[ly + 2][xq];
        float4 t3 = *(const float4*)&tmp[ly + 3][xq];
        int y = y0 + ly;
        float4 nz = *(const float4*)&noise[((size_t)b * FHW + y) * FHW + xq];
        float4 o;
        o.x = 0.25f * t0.x + 0.75f * t1.x + 0.75f * t2.x + 0.25f * t3.x + nw * nz.x + ab;
        o.y = 0.25f * t0.y + 0.75f * t1.y + 0.75f * t2.y + 0.25f * t3.y + nw * nz.y + ab;
        o.z = 0.25f * t0.z + 0.75f * t1.z + 0.75f * t2.z + 0.25f * t3.z + nw * nz.z + ab;
        o.w = 0.25f * t0.w + 0.75f * t1.w + 0.75f * t2.w + 0.25f * t3.w + nw * nz.w + ab;
        o.x = (o.x > 0.f ? o.x : 0.2f * o.x) * 1.4142135623730951f;
        o.y = (o.y > 0.f ? o.y : 0.2f * o.y) * 1.4142135623730951f;
        o.z = (o.z > 0.f ? o.z : 0.2f * o.z) * 1.4142135623730951f;
        o.w = (o.w > 0.f ? o.w : 0.2f * o.w) * 1.4142135623730951f;
        *(float4*)&out[((size_t)bc * FHW + y) * FHW + xq] = o;
    }
}

// ---------------------------------------------------------------------------
extern "C" void kernel_launch(void* const* d_in, const int* in_sizes, int n_in,
                              void* d_out, int out_size) {
    const float* x       = (const float*)d_in[0];
    const float* style   = (const float*)d_in[1];
    const float* noise   = (const float*)d_in[2];
    const float* weight  = (const float*)d_in[3];
    const float* mod_w   = (const float*)d_in[4];
    const float* mod_b   = (const float*)d_in[5];
    const float* noise_w = (const float*)d_in[6];
    const float* act_b   = (const float*)d_in[7];
    float* out = (float*)d_out;

    cudaFuncSetAttribute(k2_mma, cudaFuncAttributeMaxDynamicSharedMemorySize, K2_SMEM);

    k0_style<<<BN, CIN>>>(style, mod_w, mod_b);
    k_prep<<<10240, 512>>>(weight, x);
    k2_mma<<<dim3(34, 4, BN), 256, K2_SMEM>>>();
    k3_blur<<<dim3(4, 2048), 256>>>(noise, noise_w, act_b, out);
}

// round 14
// speedup vs baseline: 11.6874x; 1.1117x over previous
#include <cuda_runtime.h>
#include <cuda_fp16.h>
#include <cstdint>

#define BN 8
#define CIN 512
#define COUT 256
#define HW 64
#define OBR 129
#define OBP 132
#define FHW 128

// ---------------- scratch (static device globals; no runtime alloc) ----------
__device__ float  g_s[BN * CIN];                           // modulation scales
__device__ __half g_xh[(size_t)BN * HW * HW * CIN];        // x [b][y][x][ic] fp16
// weights reordered: [b][ocq4][ch16][tap'9][kg4][oc64][ic8]  (tap' = c_tap order)
__device__ __align__(128) __half g_wt2[(size_t)BN * 4 * 16 * 9 * 4 * 64 * 8];
// pre-gathered x tiles: [b][tile32][ch16] -> 640 x 16B units (kg4 x 160pix), smem-layout-exact
__device__ __align__(128) __half g_xg[(size_t)BN * 32 * 16 * 5120];
// pre-gathered edge strips: [b][strip2][ch16] -> 272 x 16B units (kg4 x 68slots)
__device__ __align__(128) __half g_xge[(size_t)BN * 2 * 16 * 2176];
__device__ __half g_obh[(size_t)BN * COUT * OBR * OBP];    // conv-transpose out fp16

#define WBLK_HALVES(b, ocq, ch) \
    ((((size_t)((b) * 4 + (ocq)) * 16 + (ch)) * 9) * 2048)

// ---------------- helpers ----------------------------------------------------
__device__ __forceinline__ uint32_t smem_u32(const void* p) {
    uint32_t a;
    asm("{ .reg .u64 t; cvta.to.shared.u64 t, %1; cvt.u32.u64 %0, t; }" : "=r"(a) : "l"(p));
    return a;
}
__device__ __forceinline__ void cpbulk(uint32_t dst, const void* src, uint32_t bytes,
                                       uint32_t mbar) {
    asm volatile("cp.async.bulk.shared::cluster.global.mbarrier::complete_tx::bytes "
                 "[%0], [%1], %2, [%3];"
                 :: "r"(dst), "l"(src), "r"(bytes), "r"(mbar) : "memory");
}
__device__ __forceinline__ void ldsm4(uint32_t* r, uint32_t addr) {
    asm volatile("ldmatrix.sync.aligned.m8n8.x4.shared.b16 {%0,%1,%2,%3}, [%4];"
                 : "=r"(r[0]), "=r"(r[1]), "=r"(r[2]), "=r"(r[3]) : "r"(addr));
}
__device__ __forceinline__ void mma16816(float* d, const uint32_t* a, const uint32_t* b) {
    asm volatile("mma.sync.aligned.m16n8k16.row.col.f32.f16.f16.f32 "
                 "{%0,%1,%2,%3}, {%4,%5,%6,%7}, {%8,%9}, {%0,%1,%2,%3};"
                 : "+f"(d[0]), "+f"(d[1]), "+f"(d[2]), "+f"(d[3])
                 : "r"(a[0]), "r"(a[1]), "r"(a[2]), "r"(a[3]), "r"(b[0]), "r"(b[1]));
}

#define MBARRIER_INIT(addr, cnt) \
    asm volatile("mbarrier.init.shared.b64 [%0], %1;" \
                 :: "r"((uint32_t)(addr)), "r"((uint32_t)(cnt)) : "memory")
#define MBARRIER_EXPECT_TX(addr, tx) \
    asm volatile("mbarrier.arrive.expect_tx.shared.b64 _, [%0], %1;" \
                 :: "r"((uint32_t)(addr)), "r"((uint32_t)(tx)) : "memory")
#define MBARRIER_WAIT_PARITY(addr, parity) do {                                        \
    uint32_t _m = (uint32_t)(addr); uint32_t _p = (uint32_t)(parity); uint32_t _d;     \
    asm volatile("{\n\t.reg .pred p;\n\t"                                              \
        "mbarrier.try_wait.parity.acquire.cta.shared::cta.b64 p, [%1], %2;\n\t"        \
        "selp.b32 %0, 1, 0, p;\n\t}" : "=r"(_d) : "r"(_m), "r"(_p) : "memory");        \
    if (!_d) {                                                                         \
        asm volatile("{\n\t.reg .pred P1;\n\tWL_%=:\n\t"                               \
            "mbarrier.try_wait.parity.acquire.cta.shared::cta.b64 P1, [%0], %1, 0x989680;\n\t" \
            "@P1 bra.uni WD_%=;\n\tbra.uni WL_%=;\n\tWD_%=:\n\t}"                      \
            :: "r"(_m), "r"(_p) : "memory");                                           \
    } } while (0)

// ---------------------------------------------------------------------------
// K0: s[b][ic] = (style[b] . mod_w[ic]) / sqrt(512) + mod_b[ic]
// ---------------------------------------------------------------------------
__global__ void k0_style(const float* __restrict__ style,
                         const float* __restrict__ mod_w,
                         const float* __restrict__ mod_b) {
    int b = blockIdx.x, ic = threadIdx.x;
    __shared__ float st[CIN];
    st[ic] = style[b * CIN + ic] * 0.04419417382415922f;
    __syncthreads();
    const float* mw = mod_w + (size_t)ic * CIN;
    float acc = 0.f;
#pragma unroll 8
    for (int j = 0; j < CIN; j++) acc += st[j] * mw[j];
    g_s[b * CIN + ic] = acc + mod_b[ic];
}

// tap order table (involution: c_tap[c_tap[k]] == k)
__device__ __constant__ int c_tap[9] = {0, 1, 2, 6, 7, 8, 3, 4, 5};

// ---------------------------------------------------------------------------
// K_PREP: merged k1 (modulate+demodulate -> g_wt2 bulk layout, blocks [0,2048))
//         and k_xt (x transpose->fp16, blocks [2048,10240)). 512 threads.
// ---------------------------------------------------------------------------
__global__ __launch_bounds__(512) void k_prep(const float* __restrict__ weight,
                                              const float* __restrict__ x) {
    int blk = blockIdx.x;
    if (blk < 2048) {
        int b = blk >> 8, oc = blk & 255;
        int ic = threadIdx.x;
        float sv = g_s[b * CIN + ic];
        const float sc = 0.014731391274719738f;  // 1/sqrt(512*9)
        float t[9], ss = 0.f;
        const float* wp = weight + ((size_t)oc * CIN + ic) * 9;
#pragma unroll
        for (int k = 0; k < 9; k++) { t[k] = sc * wp[k] * sv; ss += t[k] * t[k]; }
#pragma unroll
        for (int o = 16; o; o >>= 1) ss += __shfl_xor_sync(0xFFFFFFFFu, ss, o);
        __shared__ float red[16];
        if ((ic & 31) == 0) red[ic >> 5] = ss;
        __syncthreads();
        if (ic < 32) {
            float v = (ic < 16) ? red[ic] : 0.f;
#pragma unroll
            for (int o = 8; o; o >>= 1) v += __shfl_xor_sync(0xFFFFFFFFu, v, o);
            if (ic == 0) red[0] = v;
        }
        __syncthreads();
        float dem = rsqrtf(red[0] + 1e-8f);
        size_t base = WBLK_HALVES(b, oc >> 6, ic >> 5);
        int sub = (((ic >> 3) & 3) * 64 + (oc & 63)) * 8 + (ic & 7);
#pragma unroll
        for (int k = 0; k < 9; k++)
            g_wt2[base + (size_t)c_tap[k] * 2048 + sub] = __float2half_rn(t[k] * dem);
    } else {
        int bo = blk - 2048;
        int y = bo & 63, icg = (bo >> 6) & 15, b = bo >> 10;
        int ic0 = icg * 32;
        int tid = threadIdx.x;
        __shared__ float t[32][65];
        {
            int icl = tid >> 4, v = tid & 15;
            float4 w4 = *(const float4*)&x[((size_t)(b * CIN + ic0 + icl) * HW + y) * HW + v * 4];
            t[icl][v * 4 + 0] = w4.x;
            t[icl][v * 4 + 1] = w4.y;
            t[icl][v * 4 + 2] = w4.z;
            t[icl][v * 4 + 3] = w4.w;
        }
        __syncthreads();
        for (int idx = tid; idx < 1024; idx += 512) {
            int xx = idx >> 4, icp = idx & 15;
            __half2 v = __floats2half2_rn(t[icp * 2][xx], t[icp * 2 + 1][xx]);
            *(__half2*)&g_xh[((size_t)(b * HW + y) * HW + xx) * CIN + ic0 + icp * 2] = v;
        }
    }
}

// ---------------------------------------------------------------------------
// K_GATHER: pre-gather x halo tiles into bulk-copyable blocks.
// blockIdx.x<32: main tile (smem-exact layout kg*160+pix); ==32: edge strips.
// ---------------------------------------------------------------------------
__global__ __launch_bounds__(256) void k_gather() {
    int b = blockIdx.z, ch = blockIdx.y, t = blockIdx.x;
    int tid = threadIdx.x;
    int ic = ch * 32;
    if (t < 32) {
        int x0 = (t & 3) * 16, y0 = (t >> 2) * 8;
        size_t dstbase = ((size_t)(b * 32 + t) * 16 + ch) * 5120;
        for (int j = tid; j < 640; j += 256) {
            int kg = j / 160, u = j - kg * 160;
            uint4 v = make_uint4(0, 0, 0, 0);
            if (u < 153) {
                int py = u / 17, px = u - py * 17;
                int gy = y0 - 1 + py, gx = x0 - 1 + px;
                if ((unsigned)gy < 64u && (unsigned)gx < 64u)
                    v = *(const uint4*)&g_xh[((size_t)(b * HW + gy) * HW + gx) * CIN +
                                             ic + kg * 8];
            }
            *(uint4*)&g_xg[dstbase + (size_t)j * 8] = v;
        }
    } else {
        for (int j2 = tid; j2 < 544; j2 += 256) {
            int strip = j2 / 272, j = j2 - strip * 272;
            int kg = j / 68, slot = j - kg * 68;
            int ix = slot - 1;
            uint4 v = make_uint4(0, 0, 0, 0);
            if (((unsigned)ix < 64u) && (slot < 66)) {
                size_t xi = (strip == 0)
                    ? ((size_t)(b * HW + 63) * HW + ix)
                    : ((size_t)(b * HW + ix) * HW + 63);
                v = *(const uint4*)&g_xh[xi * CIN + ic + kg * 8];
            }
            *(uint4*)&g_xge[((size_t)(b * 2 + strip) * 16 + ch) * 2176 + (size_t)j * 8] = v;
        }
    }
}

// ---------------------------------------------------------------------------
// K2: implicit-GEMM conv-transpose, HMMA fp16/fp32.
// 256-thread CTAs (M=64 oc, N=128 pos), 2 CTAs/SM. ALL loads via cp.async.bulk
// (2 per slot: weights + pre-gathered x), mbarrier completion, 3-stage ring.
// ---------------------------------------------------------------------------
#define XOFF 24576              // W region: 6 taps * 4 kg * 64 oc * 16B
#define XPITCH 160              // 16B units per kg (153 pix padded)
#define STAGE 34816             // 24576 + 10240
#define K2_SMEM (3 * STAGE + 32)

#define E_XOFF 12288            // edge W region: 3 taps * 4 kg * 64 oc * 16B
#define E_STAGE 16640           // 12288 + 4352

__device__ __forceinline__ void k2_load_slot(
    uint32_t stg, uint32_t mbar, int p, int ch, int b, int ocq, int tile, int tid) {
    if (tid == 0) {
        uint32_t wb = p ? 12288u : 24576u;
        MBARRIER_EXPECT_TX(mbar, wb + 10240u);
        cpbulk(stg, g_wt2 + WBLK_HALVES(b, ocq, ch) + (p ? 6 * 2048 : 0), wb, mbar);
        cpbulk(stg + XOFF,
               g_xg + ((size_t)(b * 32 + tile) * 16 + ch) * 5120, 10240u, mbar);
    }
}

template <int P>
__device__ __forceinline__ void k2_compute(
    uint32_t stg, int warp_m, int warp_n, int lane, float acc[2][2][4][4]) {
    constexpr int NT = P ? 3 : 6;
    constexpr int NS = P ? 2 : 4;
    const int TL_CL[2][6] = {{0, 1, 0, 0, 1, 0}, {0, 1, 0, 0, 0, 0}};
    const int TL_SF[2][6] = {{0, 0, 1, 2, 2, 3}, {0, 0, 1, 0, 0, 0}};

    int n_loc = (lane & 7) + ((lane >> 4) << 3);
    int kgB = (lane >> 3) & 1;
    int ocA = lane & 15;
    int kgA = lane >> 4;

#pragma unroll
    for (int kgp = 0; kgp < 2; kgp++) {
        uint32_t bf[NS][2][4];
#pragma unroll
        for (int s = 0; s < NS; s++) {
            int sy = s >> 1, sx = s & 1;
#pragma unroll
            for (int t = 0; t < 2; t++) {
                int pnum = warp_n * 32 + t * 16 + n_loc;
                int pyo = pnum >> 4, pxo = pnum & 15;
                int pix = (pyo + 1 - sy) * 17 + (pxo + 1 - sx);
                ldsm4(bf[s][t], stg + XOFF + ((kgp * 2 + kgB) * XPITCH + pix) * 16);
            }
        }
#pragma unroll
        for (int ti = 0; ti < NT; ti++) {
            int cl = TL_CL[P][ti], h = TL_SF[P][ti];
            uint32_t af[2][4];
#pragma unroll
            for (int mf = 0; mf < 2; mf++)
                ldsm4(af[mf], stg + ((ti * 4 + kgp * 2 + kgA) * 64 +
                                     warp_m * 32 + mf * 16 + ocA) * 16);
#pragma unroll
            for (int mf = 0; mf < 2; mf++)
#pragma unroll
                for (int nf = 0; nf < 4; nf++)
                    mma16816(acc[cl][mf][nf], af[mf], &bf[h][nf >> 1][(nf & 1) * 2]);
        }
    }
}

__device__ __forceinline__ void k2e_load_slot(
    uint32_t stg, uint32_t mbar, int strip, int ch, int b, int ocq, int tid) {
    if (tid == 0) {
        MBARRIER_EXPECT_TX(mbar, 16640u);
        const int tp2[2][3] = {{3, 4, 5}, {2, 8, 5}};   // c_tap o c_etap
        size_t base = WBLK_HALVES(b, ocq, ch);
#pragma unroll
        for (int t = 0; t < 3; t++)
            cpbulk(stg + t * 4096, g_wt2 + base + (size_t)tp2[strip][t] * 2048,
                   4096u, mbar);
        cpbulk(stg + E_XOFF,
               g_xge + ((size_t)(b * 2 + strip) * 16 + ch) * 2176, 4352u, mbar);
    }
}

__device__ __forceinline__ void k2e_compute(
    uint32_t stg, int warp_m, int warp_n, int lane, float acc[2][2][4][4]) {
    const int CL[3] = {0, 1, 0}, SF[3] = {0, 0, 1};
    int n_loc = (lane & 7) + ((lane >> 4) << 3);
    int kgB = (lane >> 3) & 1;
    int ocA = lane & 15;
    int kgA = lane >> 4;
#pragma unroll
    for (int kgp = 0; kgp < 2; kgp++) {
        uint32_t bf[2][2][4];
#pragma unroll
        for (int s = 0; s < 2; s++) {
#pragma unroll
            for (int t = 0; t < 2; t++) {
                int p = warp_n * 32 + t * 16 + n_loc;
                int slot = ((p <= 64) ? p : 65) + 1 - s;
                ldsm4(bf[s][t], stg + E_XOFF + ((kgp * 2 + kgB) * 68 + slot) * 16);
            }
        }
#pragma unroll
        for (int ti = 0; ti < 3; ti++) {
            uint32_t af[2][4];
#pragma unroll
            for (int mf = 0; mf < 2; mf++)
                ldsm4(af[mf], stg + ((ti * 4 + kgp * 2 + kgA) * 64 +
                                     warp_m * 32 + mf * 16 + ocA) * 16);
#pragma unroll
            for (int mf = 0; mf < 2; mf++)
#pragma unroll
                for (int nf = 0; nf < 4; nf++)
                    mma16816(acc[CL[ti]][mf][nf], af[mf], &bf[SF[ti]][nf >> 1][(nf & 1) * 2]);
        }
    }
}

__global__ __launch_bounds__(256, 2) void k2_mma() {
    extern __shared__ char smraw[];
    uint32_t sb = smem_u32(smraw);
    uint32_t mb = sb + 3 * STAGE;        // 3 mbarriers (8B each)
    int tid = threadIdx.x;
    int wid = tid >> 5, lane = tid & 31;
    int warp_m = wid & 1;
    int warp_n = wid >> 1;
    int b = blockIdx.z;
    int ocq = blockIdx.y;
    int oc0 = ocq * 64;
    int bx = blockIdx.x;
    int r0 = lane >> 2, cq = lane & 3;

    if (tid == 0) {
        MBARRIER_INIT(mb + 0, 1);
        MBARRIER_INIT(mb + 8, 1);
        MBARRIER_INIT(mb + 16, 1);
    }
    __syncthreads();

    float acc[2][2][4][4];
#pragma unroll
    for (int c = 0; c < 2; c++)
#pragma unroll
        for (int mf = 0; mf < 2; mf++)
#pragma unroll
            for (int nf = 0; nf < 4; nf++)
#pragma unroll
                for (int k = 0; k < 4; k++) acc[c][mf][nf][k] = 0.f;

    if (bx < 32) {
        int x0 = (bx & 3) * 16, y0 = (bx >> 2) * 8;
        for (int s = 0; s < 2; s++)
            k2_load_slot(sb + s * STAGE, mb + s * 8, 0, s, b, ocq, bx, tid);
        for (int slot = 0; slot < 32; slot++) {
            MBARRIER_WAIT_PARITY(mb + (slot % 3) * 8, (slot / 3) & 1);
            __syncthreads();
            int nx = slot + 2;
            if (nx < 32)
                k2_load_slot(sb + (nx % 3) * STAGE, mb + (nx % 3) * 8,
                             nx >> 4, nx & 15, b, ocq, bx, tid);

            uint32_t stg = sb + (slot % 3) * STAGE;
            if (slot < 16) k2_compute<0>(stg, warp_m, warp_n, lane, acc);
            else           k2_compute<1>(stg, warp_m, warp_n, lane, acc);

            if (slot == 15 || slot == 31) {
                int p = slot >> 4;
#pragma unroll
                for (int mf = 0; mf < 2; mf++)
#pragma unroll
                    for (int rr = 0; rr < 2; rr++) {
                        int oc = oc0 + warp_m * 32 + mf * 16 + rr * 8 + r0;
                        size_t rowb = ((size_t)b * COUT + oc) * OBR;
#pragma unroll
                        for (int nf = 0; nf < 4; nf++) {
                            int m = y0 + warp_n * 2 + (nf >> 1);
                            int n = x0 + (nf & 1) * 8 + cq * 2;
                            int row = 2 * m + p;
                            __half2 lo = __floats2half2_rn(acc[0][mf][nf][rr * 2],
                                                           acc[1][mf][nf][rr * 2]);
                            __half2 hi = __floats2half2_rn(acc[0][mf][nf][rr * 2 + 1],
                                                           acc[1][mf][nf][rr * 2 + 1]);
                            uint2 v = make_uint2(*(uint32_t*)&lo, *(uint32_t*)&hi);
                            *(uint2*)&g_obh[(rowb + row) * OBP + 2 * n] = v;
                        }
                    }
                if (slot == 15) {
#pragma unroll
                    for (int c = 0; c < 2; c++)
#pragma unroll
                        for (int mf = 0; mf < 2; mf++)
#pragma unroll
                            for (int nf = 0; nf < 4; nf++)
#pragma unroll
                                for (int k = 0; k < 4; k++) acc[c][mf][nf][k] = 0.f;
                }
            }
        }
    } else {
        int strip = bx - 32;
        for (int s = 0; s < 2; s++)
            k2e_load_slot(sb + s * E_STAGE, mb + s * 8, strip, s, b, ocq, tid);
        for (int slot = 0; slot < 16; slot++) {
            MBARRIER_WAIT_PARITY(mb + (slot % 3) * 8, (slot / 3) & 1);
            __syncthreads();
            int nx = slot + 2;
            if (nx < 16)
                k2e_load_slot(sb + (nx % 3) * E_STAGE, mb + (nx % 3) * 8,
                              strip, nx, b, ocq, tid);
            k2e_compute(sb + (slot % 3) * E_STAGE, warp_m, warp_n, lane, acc);
        }
#pragma unroll
        for (int mf = 0; mf < 2; mf++)
#pragma unroll
            for (int rr = 0; rr < 2; rr++) {
                int oc = oc0 + warp_m * 32 + mf * 16 + rr * 8 + r0;
                size_t rowb = ((size_t)b * COUT + oc) * OBR;
#pragma unroll
                for (int nf = 0; nf < 4; nf++) {
#pragma unroll
                    for (int kk = 0; kk < 2; kk++) {
                        int p = warp_n * 32 + (nf >> 1) * 16 + (nf & 1) * 8 + cq * 2 + kk;
#pragma unroll
                        for (int cls = 0; cls < 2; cls++) {
                            float val = acc[cls][mf][nf][rr * 2 + kk];
                            if (strip == 0) {
                                int col = 2 * p + cls;
                                if (col <= 128)
                                    g_obh[(rowb + 128) * OBP + col] = __float2half_rn(val);
                            } else {
                                if (p <= 63)
                                    g_obh[(rowb + 2 * p + cls) * OBP + 128] =
                                        __float2half_rn(val);
                            }
                        }
                    }
                }
            }
    }
}

// ---------------------------------------------------------------------------
// K3: separable 4x4 blur + noise + bias + leaky_relu(0.2)*sqrt(2).
// ---------------------------------------------------------------------------
__global__ __launch_bounds__(256) void k3_blur(const float* __restrict__ noise,
                                               const float* __restrict__ noise_w,
                                               const float* __restrict__ act_b,
                                               float* __restrict__ out) {
    __shared__ __half sraw[35][136];
    __shared__ float tmp[35][128];
    int tid = threadIdx.x;
    int y0 = blockIdx.x * 32;
    int bc = blockIdx.y;
    int oc = bc & 255, b = bc >> 8;
    size_t obc = (size_t)bc * OBR;

    if (tid < 35) *(uint32_t*)&sraw[tid][0] = 0;

    for (int idx = tid; idx < 35 * 66; idx += 256) {
        int i = idx / 66, j = idx - i * 66;
        int ry = y0 - 1 + i;
        uint32_t v = 0;
        if ((unsigned)ry <= 128u && j < 65) {
            v = *(const uint32_t*)&g_obh[(obc + ry) * OBP + 2 * j];
            if (j == 64) v &= 0xFFFFu;
        }
        *(uint32_t*)&sraw[i][2 + 2 * j] = v;
    }
    __syncthreads();

    for (int idx = tid; idx < 35 * 128; idx += 256) {
        int i = idx >> 7, x = idx & 127;
        tmp[i][x] = 0.25f * __half2float(sraw[i][x + 1]) +
                    0.75f * __half2float(sraw[i][x + 2]) +
                    0.75f * __half2float(sraw[i][x + 3]) +
                    0.25f * __half2float(sraw[i][x + 4]);
    }
    __syncthreads();

    float nw = noise_w[0];
    float ab = act_b[oc];
    int xq = (tid & 31) * 4, tyg = tid >> 5;
#pragma unroll
    for (int r = 0; r < 4; r++) {
        int ly = tyg + 8 * r;
        float4 t0 = *(const float4*)&tmp[ly][xq];
        float4 t1 = *(const float4*)&tmp[ly + 1][xq];
        float4 t2 = *(const float4*)&tmp[ly + 2][xq];
        float4 t3 = *(const float4*)&tmp[ly + 3][xq];
        int y = y0 + ly;
        float4 nz = *(const float4*)&noise[((size_t)b * FHW + y) * FHW + xq];
        float4 o;
        o.x = 0.25f * t0.x + 0.75f * t1.x + 0.75f * t2.x + 0.25f * t3.x + nw * nz.x + ab;
        o.y = 0.25f * t0.y + 0.75f * t1.y + 0.75f * t2.y + 0.25f * t3.y + nw * nz.y + ab;
        o.z = 0.25f * t0.z + 0.75f * t1.z + 0.75f * t2.z + 0.25f * t3.z + nw * nz.z + ab;
        o.w = 0.25f * t0.w + 0.75f * t1.w + 0.75f * t2.w + 0.25f * t3.w + nw * nz.w + ab;
        o.x = (o.x > 0.f ? o.x : 0.2f * o.x) * 1.4142135623730951f;
        o.y = (o.y > 0.f ? o.y : 0.2f * o.y) * 1.4142135623730951f;
        o.z = (o.z > 0.f ? o.z : 0.2f * o.z) * 1.4142135623730951f;
        o.w = (o.w > 0.f ? o.w : 0.2f * o.w) * 1.4142135623730951f;
        *(float4*)&out[((size_t)bc * FHW + y) * FHW + xq] = o;
    }
}

// ---------------------------------------------------------------------------
extern "C" void kernel_launch(void* const* d_in, const int* in_sizes, int n_in,
                              void* d_out, int out_size) {
    const float* x       = (const float*)d_in[0];
    const float* style   = (const float*)d_in[1];
    const float* noise   = (const float*)d_in[2];
    const float* weight  = (const float*)d_in[3];
    const float* mod_w   = (const float*)d_in[4];
    const float* mod_b   = (const float*)d_in[5];
    const float* noise_w = (const float*)d_in[6];
    const float* act_b   = (const float*)d_in[7];
    float* out = (float*)d_out;

    cudaFuncSetAttribute(k2_mma, cudaFuncAttributeMaxDynamicSharedMemorySize, K2_SMEM);

    k0_style<<<BN, CIN>>>(style, mod_w, mod_b);
    k_prep<<<10240, 512>>>(weight, x);
    k_gather<<<dim3(33, 16, BN), 256>>>();
    k2_mma<<<dim3(34, 4, BN), 256, K2_SMEM>>>();
    k3_blur<<<dim3(4, 2048), 256>>>(noise, noise_w, act_b, out);
}

// round 15
// speedup vs baseline: 11.9418x; 1.0218x over previous
#include <cuda_runtime.h>
#include <cuda_fp16.h>
#include <cstdint>

#define BN 8
#define CIN 512
#define COUT 256
#define HW 64
#define OBR 129
#define OBP 132
#define FHW 128

// ---------------- scratch (static device globals; no runtime alloc) ----------
__device__ float  g_s[BN * CIN];                           // modulation scales
// weights reordered: [b][ocq4][ch16][tap'9][kg4][oc64][ic8]  (tap' = c_tap order)
__device__ __align__(128) __half g_wt2[(size_t)BN * 4 * 16 * 9 * 4 * 64 * 8];
// pre-gathered x tiles: [b][tile32][ch16] -> 640 x 16B units (kg4 x 160pix), smem-exact.
// Halo/pad slots are NEVER written -> rely on zero-init of device globals.
__device__ __align__(128) __half g_xg[(size_t)BN * 32 * 16 * 5120];
// pre-gathered edge strips: [b][strip2][ch16] -> 272 x 16B units (kg4 x 68slots)
__device__ __align__(128) __half g_xge[(size_t)BN * 2 * 16 * 2176];
__device__ __half g_obh[(size_t)BN * COUT * OBR * OBP];    // conv-transpose out fp16

#define WBLK_HALVES(b, ocq, ch) \
    ((((size_t)((b) * 4 + (ocq)) * 16 + (ch)) * 9) * 2048)

// ---------------- helpers ----------------------------------------------------
__device__ __forceinline__ uint32_t smem_u32(const void* p) {
    uint32_t a;
    asm("{ .reg .u64 t; cvta.to.shared.u64 t, %1; cvt.u32.u64 %0, t; }" : "=r"(a) : "l"(p));
    return a;
}
__device__ __forceinline__ void cpbulk(uint32_t dst, const void* src, uint32_t bytes,
                                       uint32_t mbar) {
    asm volatile("cp.async.bulk.shared::cluster.global.mbarrier::complete_tx::bytes "
                 "[%0], [%1], %2, [%3];"
                 :: "r"(dst), "l"(src), "r"(bytes), "r"(mbar) : "memory");
}
__device__ __forceinline__ void ldsm4(uint32_t* r, uint32_t addr) {
    asm volatile("ldmatrix.sync.aligned.m8n8.x4.shared.b16 {%0,%1,%2,%3}, [%4];"
                 : "=r"(r[0]), "=r"(r[1]), "=r"(r[2]), "=r"(r[3]) : "r"(addr));
}
__device__ __forceinline__ void mma16816(float* d, const uint32_t* a, const uint32_t* b) {
    asm volatile("mma.sync.aligned.m16n8k16.row.col.f32.f16.f16.f32 "
                 "{%0,%1,%2,%3}, {%4,%5,%6,%7}, {%8,%9}, {%0,%1,%2,%3};"
                 : "+f"(d[0]), "+f"(d[1]), "+f"(d[2]), "+f"(d[3])
                 : "r"(a[0]), "r"(a[1]), "r"(a[2]), "r"(a[3]), "r"(b[0]), "r"(b[1]));
}

#define MBARRIER_INIT(addr, cnt) \
    asm volatile("mbarrier.init.shared.b64 [%0], %1;" \
                 :: "r"((uint32_t)(addr)), "r"((uint32_t)(cnt)) : "memory")
#define MBARRIER_EXPECT_TX(addr, tx) \
    asm volatile("mbarrier.arrive.expect_tx.shared.b64 _, [%0], %1;" \
                 :: "r"((uint32_t)(addr)), "r"((uint32_t)(tx)) : "memory")
#define MBARRIER_WAIT_PARITY(addr, parity) do {                                        \
    uint32_t _m = (uint32_t)(addr); uint32_t _p = (uint32_t)(parity); uint32_t _d;     \
    asm volatile("{\n\t.reg .pred p;\n\t"                                              \
        "mbarrier.try_wait.parity.acquire.cta.shared::cta.b64 p, [%1], %2;\n\t"        \
        "selp.b32 %0, 1, 0, p;\n\t}" : "=r"(_d) : "r"(_m), "r"(_p) : "memory");        \
    if (!_d) {                                                                         \
        asm volatile("{\n\t.reg .pred P1;\n\tWL_%=:\n\t"                               \
            "mbarrier.try_wait.parity.acquire.cta.shared::cta.b64 P1, [%0], %1, 0x989680;\n\t" \
            "@P1 bra.uni WD_%=;\n\tbra.uni WL_%=;\n\tWD_%=:\n\t}"                      \
            :: "r"(_m), "r"(_p) : "memory");                                           \
    } } while (0)

// ---------------------------------------------------------------------------
// K0: s[b][ic] = (style[b] . mod_w[ic]) / sqrt(512) + mod_b[ic]
// ---------------------------------------------------------------------------
__global__ void k0_style(const float* __restrict__ style,
                         const float* __restrict__ mod_w,
                         const float* __restrict__ mod_b) {
    int b = blockIdx.x, ic = threadIdx.x;
    __shared__ float st[CIN];
    st[ic] = style[b * CIN + ic] * 0.04419417382415922f;
    __syncthreads();
    const float* mw = mod_w + (size_t)ic * CIN;
    float acc = 0.f;
#pragma unroll 8
    for (int j = 0; j < CIN; j++) acc += st[j] * mw[j];
    g_s[b * CIN + ic] = acc + mod_b[ic];
}

// tap order table (involution: c_tap[c_tap[k]] == k)
__device__ __constant__ int c_tap[9] = {0, 1, 2, 6, 7, 8, 3, 4, 5};

// ---------------------------------------------------------------------------
// K_PREP: blocks [0,2048): modulate+demodulate -> g_wt2 bulk layout.
//         blocks [2048,10240): x transpose + DIRECT scatter into g_xg/g_xge
//         (fused gather; g_xh intermediate eliminated). 512 threads.
// ---------------------------------------------------------------------------
__global__ __launch_bounds__(512) void k_prep(const float* __restrict__ weight,
                                              const float* __restrict__ x) {
    int blk = blockIdx.x;
    if (blk < 2048) {
        int b = blk >> 8, oc = blk & 255;
        int ic = threadIdx.x;
        float sv = g_s[b * CIN + ic];
        const float sc = 0.014731391274719738f;  // 1/sqrt(512*9)
        float t[9], ss = 0.f;
        const float* wp = weight + ((size_t)oc * CIN + ic) * 9;
#pragma unroll
        for (int k = 0; k < 9; k++) { t[k] = sc * wp[k] * sv; ss += t[k] * t[k]; }
#pragma unroll
        for (int o = 16; o; o >>= 1) ss += __shfl_xor_sync(0xFFFFFFFFu, ss, o);
        __shared__ float red[16];
        if ((ic & 31) == 0) red[ic >> 5] = ss;
        __syncthreads();
        if (ic < 32) {
            float v = (ic < 16) ? red[ic] : 0.f;
#pragma unroll
            for (int o = 8; o; o >>= 1) v += __shfl_xor_sync(0xFFFFFFFFu, v, o);
            if (ic == 0) red[0] = v;
        }
        __syncthreads();
        float dem = rsqrtf(red[0] + 1e-8f);
        size_t base = WBLK_HALVES(b, oc >> 6, ic >> 5);
        int sub = (((ic >> 3) & 3) * 64 + (oc & 63)) * 8 + (ic & 7);
#pragma unroll
        for (int k = 0; k < 9; k++)
            g_wt2[base + (size_t)c_tap[k] * 2048 + sub] = __float2half_rn(t[k] * dem);
    } else {
        int bo = blk - 2048;
        int y = bo & 63, icg = (bo >> 6) & 15, b = bo >> 10;
        int ic0 = icg * 32;
        int tid = threadIdx.x;
        __shared__ float t[32][65];
        {
            int icl = tid >> 4, v = tid & 15;
            float4 w4 = *(const float4*)&x[((size_t)(b * CIN + ic0 + icl) * HW + y) * HW + v * 4];
            t[icl][v * 4 + 0] = w4.x;
            t[icl][v * 4 + 1] = w4.y;
            t[icl][v * 4 + 2] = w4.z;
            t[icl][v * 4 + 3] = w4.w;
        }
        __syncthreads();

        // pack 8 halves (ic = ic0+kg*8 .. +8) at column gx
        auto pack8 = [&](int kg, int gx) {
            __half2 h0 = __floats2half2_rn(t[kg * 8 + 0][gx], t[kg * 8 + 1][gx]);
            __half2 h1 = __floats2half2_rn(t[kg * 8 + 2][gx], t[kg * 8 + 3][gx]);
            __half2 h2 = __floats2half2_rn(t[kg * 8 + 4][gx], t[kg * 8 + 5][gx]);
            __half2 h3 = __floats2half2_rn(t[kg * 8 + 6][gx], t[kg * 8 + 7][gx]);
            uint4 r;
            r.x = *(uint32_t*)&h0; r.y = *(uint32_t*)&h1;
            r.z = *(uint32_t*)&h2; r.w = *(uint32_t*)&h3;
            return r;
        };

        // main tiles: row y lands in (ty1, py1) and, when py1==0, also (ty1-1, 8)
        int ty1 = (y + 1) >> 3, py1 = (y + 1) & 7;
#pragma unroll
        for (int cand = 0; cand < 2; cand++) {
            int ty, py;
            if (cand == 0) { if (ty1 > 7) continue; ty = ty1; py = py1; }
            else           { if (py1 != 0 || ty1 == 0) continue; ty = ty1 - 1; py = 8; }
            for (int idx = tid; idx < 272; idx += 512) {
                int kg = idx / 68, j = idx - kg * 68;
                int tx = j / 17, px = j - tx * 17;
                int gx = 16 * tx - 1 + px;
                if (gx < 0) continue;          // j==0 -> halo, stays zero
                int tile = ty * 4 + tx;
                size_t dst = ((size_t)(b * 32 + tile) * 16 + icg) * 5120 +
                             (size_t)(kg * 160 + py * 17 + px) * 8;
                *(uint4*)&g_xg[dst] = pack8(kg, gx);
            }
        }
        // edge strip 1 (out col 128): x col 63, slot = y+1
        if (tid < 4) {
            size_t dst = ((size_t)(b * 2 + 1) * 16 + icg) * 2176 +
                         (size_t)(tid * 68 + y + 1) * 8;
            *(uint4*)&g_xge[dst] = pack8(tid, 63);
        }
        // edge strip 0 (out row 128): x row 63, slots 1..64
        if (y == 63) {
            for (int idx = tid; idx < 256; idx += 512) {
                int kg = idx >> 6, ix = idx & 63;
                size_t dst = ((size_t)(b * 2 + 0) * 16 + icg) * 2176 +
                             (size_t)(kg * 68 + ix + 1) * 8;
                *(uint4*)&g_xge[dst] = pack8(kg, ix);
            }
        }
    }
}

// ---------------------------------------------------------------------------
// K2: implicit-GEMM conv-transpose, HMMA fp16/fp32. (unchanged from R14)
// ---------------------------------------------------------------------------
#define XOFF 24576              // W region: 6 taps * 4 kg * 64 oc * 16B
#define XPITCH 160              // 16B units per kg (153 pix padded)
#define STAGE 34816             // 24576 + 10240
#define K2_SMEM (3 * STAGE + 32)

#define E_XOFF 12288            // edge W region: 3 taps * 4 kg * 64 oc * 16B
#define E_STAGE 16640           // 12288 + 4352

__device__ __forceinline__ void k2_load_slot(
    uint32_t stg, uint32_t mbar, int p, int ch, int b, int ocq, int tile, int tid) {
    if (tid == 0) {
        uint32_t wb = p ? 12288u : 24576u;
        MBARRIER_EXPECT_TX(mbar, wb + 10240u);
        cpbulk(stg, g_wt2 + WBLK_HALVES(b, ocq, ch) + (p ? 6 * 2048 : 0), wb, mbar);
        cpbulk(stg + XOFF,
               g_xg + ((size_t)(b * 32 + tile) * 16 + ch) * 5120, 10240u, mbar);
    }
}

template <int P>
__device__ __forceinline__ void k2_compute(
    uint32_t stg, int warp_m, int warp_n, int lane, float acc[2][2][4][4]) {
    constexpr int NT = P ? 3 : 6;
    constexpr int NS = P ? 2 : 4;
    const int TL_CL[2][6] = {{0, 1, 0, 0, 1, 0}, {0, 1, 0, 0, 0, 0}};
    const int TL_SF[2][6] = {{0, 0, 1, 2, 2, 3}, {0, 0, 1, 0, 0, 0}};

    int n_loc = (lane & 7) + ((lane >> 4) << 3);
    int kgB = (lane >> 3) & 1;
    int ocA = lane & 15;
    int kgA = lane >> 4;

#pragma unroll
    for (int kgp = 0; kgp < 2; kgp++) {
        uint32_t bf[NS][2][4];
#pragma unroll
        for (int s = 0; s < NS; s++) {
            int sy = s >> 1, sx = s & 1;
#pragma unroll
            for (int t = 0; t < 2; t++) {
                int pnum = warp_n * 32 + t * 16 + n_loc;
                int pyo = pnum >> 4, pxo = pnum & 15;
                int pix = (pyo + 1 - sy) * 17 + (pxo + 1 - sx);
                ldsm4(bf[s][t], stg + XOFF + ((kgp * 2 + kgB) * XPITCH + pix) * 16);
            }
        }
#pragma unroll
        for (int ti = 0; ti < NT; ti++) {
            int cl = TL_CL[P][ti], h = TL_SF[P][ti];
            uint32_t af[2][4];
#pragma unroll
            for (int mf = 0; mf < 2; mf++)
                ldsm4(af[mf], stg + ((ti * 4 + kgp * 2 + kgA) * 64 +
                                     warp_m * 32 + mf * 16 + ocA) * 16);
#pragma unroll
            for (int mf = 0; mf < 2; mf++)
#pragma unroll
                for (int nf = 0; nf < 4; nf++)
                    mma16816(acc[cl][mf][nf], af[mf], &bf[h][nf >> 1][(nf & 1) * 2]);
        }
    }
}

__device__ __forceinline__ void k2e_load_slot(
    uint32_t stg, uint32_t mbar, int strip, int ch, int b, int ocq, int tid) {
    if (tid == 0) {
        MBARRIER_EXPECT_TX(mbar, 16640u);
        const int tp2[2][3] = {{3, 4, 5}, {2, 8, 5}};   // c_tap o c_etap
        size_t base = WBLK_HALVES(b, ocq, ch);
#pragma unroll
        for (int t = 0; t < 3; t++)
            cpbulk(stg + t * 4096, g_wt2 + base + (size_t)tp2[strip][t] * 2048,
                   4096u, mbar);
        cpbulk(stg + E_XOFF,
               g_xge + ((size_t)(b * 2 + strip) * 16 + ch) * 2176, 4352u, mbar);
    }
}

__device__ __forceinline__ void k2e_compute(
    uint32_t stg, int warp_m, int warp_n, int lane, float acc[2][2][4][4]) {
    const int CL[3] = {0, 1, 0}, SF[3] = {0, 0, 1};
    int n_loc = (lane & 7) + ((lane >> 4) << 3);
    int kgB = (lane >> 3) & 1;
    int ocA = lane & 15;
    int kgA = lane >> 4;
#pragma unroll
    for (int kgp = 0; kgp < 2; kgp++) {
        uint32_t bf[2][2][4];
#pragma unroll
        for (int s = 0; s < 2; s++) {
#pragma unroll
            for (int t = 0; t < 2; t++) {
                int p = warp_n * 32 + t * 16 + n_loc;
                int slot = ((p <= 64) ? p : 65) + 1 - s;
                ldsm4(bf[s][t], stg + E_XOFF + ((kgp * 2 + kgB) * 68 + slot) * 16);
            }
        }
#pragma unroll
        for (int ti = 0; ti < 3; ti++) {
            uint32_t af[2][4];
#pragma unroll
            for (int mf = 0; mf < 2; mf++)
                ldsm4(af[mf], stg + ((ti * 4 + kgp * 2 + kgA) * 64 +
                                     warp_m * 32 + mf * 16 + ocA) * 16);
#pragma unroll
            for (int mf = 0; mf < 2; mf++)
#pragma unroll
                for (int nf = 0; nf < 4; nf++)
                    mma16816(acc[CL[ti]][mf][nf], af[mf], &bf[SF[ti]][nf >> 1][(nf & 1) * 2]);
        }
    }
}

__global__ __launch_bounds__(256, 2) void k2_mma() {
    extern __shared__ char smraw[];
    uint32_t sb = smem_u32(smraw);
    uint32_t mb = sb + 3 * STAGE;        // 3 mbarriers (8B each)
    int tid = threadIdx.x;
    int wid = tid >> 5, lane = tid & 31;
    int warp_m = wid & 1;
    int warp_n = wid >> 1;
    int b = blockIdx.z;
    int ocq = blockIdx.y;
    int oc0 = ocq * 64;
    int bx = blockIdx.x;
    int r0 = lane >> 2, cq = lane & 3;

    if (tid == 0) {
        MBARRIER_INIT(mb + 0, 1);
        MBARRIER_INIT(mb + 8, 1);
        MBARRIER_INIT(mb + 16, 1);
    }
    __syncthreads();

    float acc[2][2][4][4];
#pragma unroll
    for (int c = 0; c < 2; c++)
#pragma unroll
        for (int mf = 0; mf < 2; mf++)
#pragma unroll
            for (int nf = 0; nf < 4; nf++)
#pragma unroll
                for (int k = 0; k < 4; k++) acc[c][mf][nf][k] = 0.f;

    if (bx < 32) {
        int x0 = (bx & 3) * 16, y0 = (bx >> 2) * 8;
        for (int s = 0; s < 2; s++)
            k2_load_slot(sb + s * STAGE, mb + s * 8, 0, s, b, ocq, bx, tid);
        for (int slot = 0; slot < 32; slot++) {
            MBARRIER_WAIT_PARITY(mb + (slot % 3) * 8, (slot / 3) & 1);
            __syncthreads();
            int nx = slot + 2;
            if (nx < 32)
                k2_load_slot(sb + (nx % 3) * STAGE, mb + (nx % 3) * 8,
                             nx >> 4, nx & 15, b, ocq, bx, tid);

            uint32_t stg = sb + (slot % 3) * STAGE;
            if (slot < 16) k2_compute<0>(stg, warp_m, warp_n, lane, acc);
            else           k2_compute<1>(stg, warp_m, warp_n, lane, acc);

            if (slot == 15 || slot == 31) {
                int p = slot >> 4;
#pragma unroll
                for (int mf = 0; mf < 2; mf++)
#pragma unroll
                    for (int rr = 0; rr < 2; rr++) {
                        int oc = oc0 + warp_m * 32 + mf * 16 + rr * 8 + r0;
                        size_t rowb = ((size_t)b * COUT + oc) * OBR;
#pragma unroll
                        for (int nf = 0; nf < 4; nf++) {
                            int m = y0 + warp_n * 2 + (nf >> 1);
                            int n = x0 + (nf & 1) * 8 + cq * 2;
                            int row = 2 * m + p;
                            __half2 lo = __floats2half2_rn(acc[0][mf][nf][rr * 2],
                                                           acc[1][mf][nf][rr * 2]);
                            __half2 hi = __floats2half2_rn(acc[0][mf][nf][rr * 2 + 1],
                                                           acc[1][mf][nf][rr * 2 + 1]);
                            uint2 v = make_uint2(*(uint32_t*)&lo, *(uint32_t*)&hi);
                            *(uint2*)&g_obh[(rowb + row) * OBP + 2 * n] = v;
                        }
                    }
                if (slot == 15) {
#pragma unroll
                    for (int c = 0; c < 2; c++)
#pragma unroll
                        for (int mf = 0; mf < 2; mf++)
#pragma unroll
                            for (int nf = 0; nf < 4; nf++)
#pragma unroll
                                for (int k = 0; k < 4; k++) acc[c][mf][nf][k] = 0.f;
                }
            }
        }
    } else {
        int strip = bx - 32;
        for (int s = 0; s < 2; s++)
            k2e_load_slot(sb + s * E_STAGE, mb + s * 8, strip, s, b, ocq, tid);
        for (int slot = 0; slot < 16; slot++) {
            MBARRIER_WAIT_PARITY(mb + (slot % 3) * 8, (slot / 3) & 1);
            __syncthreads();
            int nx = slot + 2;
            if (nx < 16)
                k2e_load_slot(sb + (nx % 3) * E_STAGE, mb + (nx % 3) * 8,
                              strip, nx, b, ocq, tid);
            k2e_compute(sb + (slot % 3) * E_STAGE, warp_m, warp_n, lane, acc);
        }
#pragma unroll
        for (int mf = 0; mf < 2; mf++)
#pragma unroll
            for (int rr = 0; rr < 2; rr++) {
                int oc = oc0 + warp_m * 32 + mf * 16 + rr * 8 + r0;
                size_t rowb = ((size_t)b * COUT + oc) * OBR;
#pragma unroll
                for (int nf = 0; nf < 4; nf++) {
#pragma unroll
                    for (int kk = 0; kk < 2; kk++) {
                        int p = warp_n * 32 + (nf >> 1) * 16 + (nf & 1) * 8 + cq * 2 + kk;
#pragma unroll
                        for (int cls = 0; cls < 2; cls++) {
                            float val = acc[cls][mf][nf][rr * 2 + kk];
                            if (strip == 0) {
                                int col = 2 * p + cls;
                                if (col <= 128)
                                    g_obh[(rowb + 128) * OBP + col] = __float2half_rn(val);
                            } else {
                                if (p <= 63)
                                    g_obh[(rowb + 2 * p + cls) * OBP + 128] =
                                        __float2half_rn(val);
                            }
                        }
                    }
                }
            }
    }
}

// ---------------------------------------------------------------------------
// K3: separable 4x4 blur + noise + bias + leaky_relu(0.2)*sqrt(2).
// Register-blocked symmetric horizontal pass: 4 outputs from 7 converts.
// ---------------------------------------------------------------------------
__global__ __launch_bounds__(256) void k3_blur(const float* __restrict__ noise,
                                               const float* __restrict__ noise_w,
                                               const float* __restrict__ act_b,
                                               float* __restrict__ out) {
    __shared__ __half sraw[35][136];
    __shared__ float tmp[35][128];
    int tid = threadIdx.x;
    int y0 = blockIdx.x * 32;
    int bc = blockIdx.y;
    int oc = bc & 255, b = bc >> 8;
    size_t obc = (size_t)bc * OBR;

    if (tid < 35) *(uint32_t*)&sraw[tid][0] = 0;

    for (int idx = tid; idx < 35 * 66; idx += 256) {
        int i = idx / 66, j = idx - i * 66;
        int ry = y0 - 1 + i;
        uint32_t v = 0;
        if ((unsigned)ry <= 128u && j < 65) {
            v = *(const uint32_t*)&g_obh[(obc + ry) * OBP + 2 * j];
            if (j == 64) v &= 0xFFFFu;
        }
        *(uint32_t*)&sraw[i][2 + 2 * j] = v;
    }
    __syncthreads();

    // horizontal: 4 outputs per task; out[x] = 0.25(s[x+1]+s[x+4]) + 0.75(s[x+2]+s[x+3])
    for (int task = tid; task < 35 * 32; task += 256) {
        int i = task >> 5, xb = (task & 31) * 4;
        float s1 = __half2float(sraw[i][xb + 1]);
        float s2 = __half2float(sraw[i][xb + 2]);
        float s3 = __half2float(sraw[i][xb + 3]);
        float s4 = __half2float(sraw[i][xb + 4]);
        float s5 = __half2float(sraw[i][xb + 5]);
        float s6 = __half2float(sraw[i][xb + 6]);
        float s7 = __half2float(sraw[i][xb + 7]);
        tmp[i][xb + 0] = 0.25f * (s1 + s4) + 0.75f * (s2 + s3);
        tmp[i][xb + 1] = 0.25f * (s2 + s5) + 0.75f * (s3 + s4);
        tmp[i][xb + 2] = 0.25f * (s3 + s6) + 0.75f * (s4 + s5);
        tmp[i][xb + 3] = 0.25f * (s4 + s7) + 0.75f * (s5 + s6);
    }
    __syncthreads();

    float nw = noise_w[0];
    float ab = act_b[oc];
    int xq = (tid & 31) * 4, tyg = tid >> 5;
#pragma unroll
    for (int r = 0; r < 4; r++) {
        int ly = tyg + 8 * r;
        float4 t0 = *(const float4*)&tmp[ly][xq];
        float4 t1 = *(const float4*)&tmp[ly + 1][xq];
        float4 t2 = *(const float4*)&tmp[ly + 2][xq];
        float4 t3 = *(const float4*)&tmp[ly + 3][xq];
        int y = y0 + ly;
        float4 nz = *(const float4*)&noise[((size_t)b * FHW + y) * FHW + xq];
        float4 o;
        o.x = 0.25f * (t0.x + t3.x) + 0.75f * (t1.x + t2.x) + nw * nz.x + ab;
        o.y = 0.25f * (t0.y + t3.y) + 0.75f * (t1.y + t2.y) + nw * nz.y + ab;
        o.z = 0.25f * (t0.z + t3.z) + 0.75f * (t1.z + t2.z) + nw * nz.z + ab;
        o.w = 0.25f * (t0.w + t3.w) + 0.75f * (t1.w + t2.w) + nw * nz.w + ab;
        o.x = (o.x > 0.f ? o.x : 0.2f * o.x) * 1.4142135623730951f;
        o.y = (o.y > 0.f ? o.y : 0.2f * o.y) * 1.4142135623730951f;
        o.z = (o.z > 0.f ? o.z : 0.2f * o.z) * 1.4142135623730951f;
        o.w = (o.w > 0.f ? o.w : 0.2f * o.w) * 1.4142135623730951f;
        *(float4*)&out[((size_t)bc * FHW + y) * FHW + xq] = o;
    }
}

// ---------------------------------------------------------------------------
extern "C" void kernel_launch(void* const* d_in, const int* in_sizes, int n_in,
                              void* d_out, int out_size) {
    const float* x       = (const float*)d_in[0];
    const float* style   = (const float*)d_in[1];
    const float* noise   = (const float*)d_in[2];
    const float* weight  = (const float*)d_in[3];
    const float* mod_w   = (const float*)d_in[4];
    const float* mod_b   = (const float*)d_in[5];
    const float* noise_w = (const float*)d_in[6];
    const float* act_b   = (const float*)d_in[7];
    float* out = (float*)d_out;

    cudaFuncSetAttribute(k2_mma, cudaFuncAttributeMaxDynamicSharedMemorySize, K2_SMEM);

    k0_style<<<BN, CIN>>>(style, mod_w, mod_b);
    k_prep<<<10240, 512>>>(weight, x);
    k2_mma<<<dim3(34, 4, BN), 256, K2_SMEM>>>();
    k3_blur<<<dim3(4, 2048), 256>>>(noise, noise_w, act_b, out);
}

// round 17
// speedup vs baseline: 17.6733x; 1.4800x over previous
#include <cuda_runtime.h>
#include <cuda_fp16.h>
#include <cstdint>

#define BN 8
#define CIN 512
#define COUT 256
#define HW 64
#define OBR 129
#define OBP 132
#define FHW 128

// ---------------- scratch (static device globals; no runtime alloc) ----------
__device__ float  g_s[BN * CIN];                           // modulation scales
// weights reordered: [b][ocq4][ch16][tap'9][kg4][oc64][ic8]  (tap' = c_tap order)
__device__ __align__(128) __half g_wt2[(size_t)BN * 4 * 16 * 9 * 4 * 64 * 8];
// pre-gathered x tiles: [b][tile32][ch16] -> 640 x 16B units (kg4 x 160pix), smem-exact.
// Halo/pad slots are NEVER written -> rely on zero-init of device globals.
__device__ __align__(128) __half g_xg[(size_t)BN * 32 * 16 * 5120];
// pre-gathered edge strips: [b][strip2][ch16] -> 272 x 16B units (kg4 x 68slots)
__device__ __align__(128) __half g_xge[(size_t)BN * 2 * 16 * 2176];
__device__ __align__(16) __half g_obh[(size_t)BN * COUT * OBR * OBP];  // conv-t out fp16

#define WBLK_HALVES(b, ocq, ch) \
    ((((size_t)((b) * 4 + (ocq)) * 16 + (ch)) * 9) * 2048)

// ---------------- helpers ----------------------------------------------------
__device__ __forceinline__ uint32_t smem_u32(const void* p) {
    uint32_t a;
    asm("{ .reg .u64 t; cvta.to.shared.u64 t, %1; cvt.u32.u64 %0, t; }" : "=r"(a) : "l"(p));
    return a;
}
__device__ __forceinline__ void cpbulk(uint32_t dst, const void* src, uint32_t bytes,
                                       uint32_t mbar) {
    asm volatile("cp.async.bulk.shared::cluster.global.mbarrier::complete_tx::bytes "
                 "[%0], [%1], %2, [%3];"
                 :: "r"(dst), "l"(src), "r"(bytes), "r"(mbar) : "memory");
}
__device__ __forceinline__ void ldsm4(uint32_t* r, uint32_t addr) {
    asm volatile("ldmatrix.sync.aligned.m8n8.x4.shared.b16 {%0,%1,%2,%3}, [%4];"
                 : "=r"(r[0]), "=r"(r[1]), "=r"(r[2]), "=r"(r[3]) : "r"(addr));
}
__device__ __forceinline__ void mma16816(float* d, const uint32_t* a, const uint32_t* b) {
    asm volatile("mma.sync.aligned.m16n8k16.row.col.f32.f16.f16.f32 "
                 "{%0,%1,%2,%3}, {%4,%5,%6,%7}, {%8,%9}, {%0,%1,%2,%3};"
                 : "+f"(d[0]), "+f"(d[1]), "+f"(d[2]), "+f"(d[3])
                 : "r"(a[0]), "r"(a[1]), "r"(a[2]), "r"(a[3]), "r"(b[0]), "r"(b[1]));
}

#define MBARRIER_INIT(addr, cnt) \
    asm volatile("mbarrier.init.shared.b64 [%0], %1;" \
                 :: "r"((uint32_t)(addr)), "r"((uint32_t)(cnt)) : "memory")
#define MBARRIER_EXPECT_TX(addr, tx) \
    asm volatile("mbarrier.arrive.expect_tx.shared.b64 _, [%0], %1;" \
                 :: "r"((uint32_t)(addr)), "r"((uint32_t)(tx)) : "memory")
#define MBARRIER_WAIT_PARITY(addr, parity) do {                                        \
    uint32_t _m = (uint32_t)(addr); uint32_t _p = (uint32_t)(parity); uint32_t _d;     \
    asm volatile("{\n\t.reg .pred p;\n\t"                                              \
        "mbarrier.try_wait.parity.acquire.cta.shared::cta.b64 p, [%1], %2;\n\t"        \
        "selp.b32 %0, 1, 0, p;\n\t}" : "=r"(_d) : "r"(_m), "r"(_p) : "memory");        \
    if (!_d) {                                                                         \
        asm volatile("{\n\t.reg .pred P1;\n\tWL_%=:\n\t"                               \
            "mbarrier.try_wait.parity.acquire.cta.shared::cta.b64 P1, [%0], %1, 0x989680;\n\t" \
            "@P1 bra.uni WD_%=;\n\tbra.uni WL_%=;\n\tWD_%=:\n\t}"                      \
            :: "r"(_m), "r"(_p) : "memory");                                           \
    } } while (0)

// ---------------------------------------------------------------------------
// K0 v2: s[b][ic] = (style[b] . mod_w[ic]) / sqrt(512) + mod_b[ic]
// grid (16 icg, 8 b), 256 thr; warp computes 4 ic via coalesced row reads.
// ---------------------------------------------------------------------------
__global__ __launch_bounds__(256) void k0_style(const float* __restrict__ style,
                                                const float* __restrict__ mod_w,
                                                const float* __restrict__ mod_b) {
    int icg = blockIdx.x, b = blockIdx.y;
    int tid = threadIdx.x, wid = tid >> 5, lane = tid & 31;
    __shared__ float st[CIN];
    for (int j = tid; j < CIN; j += 256)
        st[j] = style[b * CIN + j] * 0.04419417382415922f;
    __syncthreads();
#pragma unroll
    for (int u = 0; u < 4; u++) {
        int ic = icg * 32 + wid * 4 + u;
        const float* mw = mod_w + (size_t)ic * CIN;
        float acc = 0.f;
#pragma unroll 4
        for (int j = lane; j < CIN; j += 32) acc += st[j] * mw[j];
#pragma unroll
        for (int o = 16; o; o >>= 1) acc += __shfl_xor_sync(0xFFFFFFFFu, acc, o);
        if (lane == 0) g_s[b * CIN + ic] = acc + mod_b[ic];
    }
}

// tap order table (involution: c_tap[c_tap[k]] == k)
__device__ __constant__ int c_tap[9] = {0, 1, 2, 6, 7, 8, 3, 4, 5};

// ---------------------------------------------------------------------------
// K_PREP: blocks [0,2048): modulate+demodulate -> g_wt2 bulk layout.
//         blocks [2048,10240): x transpose + DIRECT scatter into g_xg/g_xge.
// ---------------------------------------------------------------------------
__global__ __launch_bounds__(512) void k_prep(const float* __restrict__ weight,
                                              const float* __restrict__ x) {
    int blk = blockIdx.x;
    if (blk < 2048) {
        int b = blk >> 8, oc = blk & 255;
        int ic = threadIdx.x;
        float sv = g_s[b * CIN + ic];
        const float sc = 0.014731391274719738f;  // 1/sqrt(512*9)
        float t[9], ss = 0.f;
        const float* wp = weight + ((size_t)oc * CIN + ic) * 9;
#pragma unroll
        for (int k = 0; k < 9; k++) { t[k] = sc * wp[k] * sv; ss += t[k] * t[k]; }
#pragma unroll
        for (int o = 16; o; o >>= 1) ss += __shfl_xor_sync(0xFFFFFFFFu, ss, o);
        __shared__ float red[16];
        if ((ic & 31) == 0) red[ic >> 5] = ss;
        __syncthreads();
        if (ic < 32) {
            float v = (ic < 16) ? red[ic] : 0.f;
#pragma unroll
            for (int o = 8; o; o >>= 1) v += __shfl_xor_sync(0xFFFFFFFFu, v, o);
            if (ic == 0) red[0] = v;
        }
        __syncthreads();
        float dem = rsqrtf(red[0] + 1e-8f);
        size_t base = WBLK_HALVES(b, oc >> 6, ic >> 5);
        int sub = (((ic >> 3) & 3) * 64 + (oc & 63)) * 8 + (ic & 7);
#pragma unroll
        for (int k = 0; k < 9; k++)
            g_wt2[base + (size_t)c_tap[k] * 2048 + sub] = __float2half_rn(t[k] * dem);
    } else {
        int bo = blk - 2048;
        int y = bo & 63, icg = (bo >> 6) & 15, b = bo >> 10;
        int ic0 = icg * 32;
        int tid = threadIdx.x;
        __shared__ float t[32][65];
        {
            int icl = tid >> 4, v = tid & 15;
            float4 w4 = *(const float4*)&x[((size_t)(b * CIN + ic0 + icl) * HW + y) * HW + v * 4];
            t[icl][v * 4 + 0] = w4.x;
            t[icl][v * 4 + 1] = w4.y;
            t[icl][v * 4 + 2] = w4.z;
            t[icl][v * 4 + 3] = w4.w;
        }
        __syncthreads();

        auto pack8 = [&](int kg, int gx) {
            __half2 h0 = __floats2half2_rn(t[kg * 8 + 0][gx], t[kg * 8 + 1][gx]);
            __half2 h1 = __floats2half2_rn(t[kg * 8 + 2][gx], t[kg * 8 + 3][gx]);
            __half2 h2 = __floats2half2_rn(t[kg * 8 + 4][gx], t[kg * 8 + 5][gx]);
            __half2 h3 = __floats2half2_rn(t[kg * 8 + 6][gx], t[kg * 8 + 7][gx]);
            uint4 r;
            r.x = *(uint32_t*)&h0; r.y = *(uint32_t*)&h1;
            r.z = *(uint32_t*)&h2; r.w = *(uint32_t*)&h3;
            return r;
        };

        int ty1 = (y + 1) >> 3, py1 = (y + 1) & 7;
#pragma unroll
        for (int cand = 0; cand < 2; cand++) {
            int ty, py;
            if (cand == 0) { if (ty1 > 7) continue; ty = ty1; py = py1; }
            else           { if (py1 != 0 || ty1 == 0) continue; ty = ty1 - 1; py = 8; }
            for (int idx = tid; idx < 272; idx += 512) {
                int kg = idx / 68, j = idx - kg * 68;
                int tx = j / 17, px = j - tx * 17;
                int gx = 16 * tx - 1 + px;
                if (gx < 0) continue;
                int tile = ty * 4 + tx;
                size_t dst = ((size_t)(b * 32 + tile) * 16 + icg) * 5120 +
                             (size_t)(kg * 160 + py * 17 + px) * 8;
                *(uint4*)&g_xg[dst] = pack8(kg, gx);
            }
        }
        if (tid < 4) {
            size_t dst = ((size_t)(b * 2 + 1) * 16 + icg) * 2176 +
                         (size_t)(tid * 68 + y + 1) * 8;
            *(uint4*)&g_xge[dst] = pack8(tid, 63);
        }
        if (y == 63) {
            for (int idx = tid; idx < 256; idx += 512) {
                int kg = idx >> 6, ix = idx & 63;
                size_t dst = ((size_t)(b * 2 + 0) * 16 + icg) * 2176 +
                             (size_t)(kg * 68 + ix + 1) * 8;
                *(uint4*)&g_xge[dst] = pack8(kg, ix);
            }
        }
    }
}

// ---------------------------------------------------------------------------
// K2: implicit-GEMM conv-transpose, HMMA fp16/fp32. (unchanged)
// ---------------------------------------------------------------------------
#define XOFF 24576
#define XPITCH 160
#define STAGE 34816
#define K2_SMEM (3 * STAGE + 32)

#define E_XOFF 12288
#define E_STAGE 16640

__device__ __forceinline__ void k2_load_slot(
    uint32_t stg, uint32_t mbar, int p, int ch, int b, int ocq, int tile, int tid) {
    if (tid == 0) {
        uint32_t wb = p ? 12288u : 24576u;
        MBARRIER_EXPECT_TX(mbar, wb + 10240u);
        cpbulk(stg, g_wt2 + WBLK_HALVES(b, ocq, ch) + (p ? 6 * 2048 : 0), wb, mbar);
        cpbulk(stg + XOFF,
               g_xg + ((size_t)(b * 32 + tile) * 16 + ch) * 5120, 10240u, mbar);
    }
}

template <int P>
__device__ __forceinline__ void k2_compute(
    uint32_t stg, int warp_m, int warp_n, int lane, float acc[2][2][4][4]) {
    constexpr int NT = P ? 3 : 6;
    constexpr int NS = P ? 2 : 4;
    const int TL_CL[2][6] = {{0, 1, 0, 0, 1, 0}, {0, 1, 0, 0, 0, 0}};
    const int TL_SF[2][6] = {{0, 0, 1, 2, 2, 3}, {0, 0, 1, 0, 0, 0}};

    int n_loc = (lane & 7) + ((lane >> 4) << 3);
    int kgB = (lane >> 3) & 1;
    int ocA = lane & 15;
    int kgA = lane >> 4;

#pragma unroll
    for (int kgp = 0; kgp < 2; kgp++) {
        uint32_t bf[NS][2][4];
#pragma unroll
        for (int s = 0; s < NS; s++) {
            int sy = s >> 1, sx = s & 1;
#pragma unroll
            for (int t = 0; t < 2; t++) {
                int pnum = warp_n * 32 + t * 16 + n_loc;
                int pyo = pnum >> 4, pxo = pnum & 15;
                int pix = (pyo + 1 - sy) * 17 + (pxo + 1 - sx);
                ldsm4(bf[s][t], stg + XOFF + ((kgp * 2 + kgB) * XPITCH + pix) * 16);
            }
        }
#pragma unroll
        for (int ti = 0; ti < NT; ti++) {
            int cl = TL_CL[P][ti], h = TL_SF[P][ti];
            uint32_t af[2][4];
#pragma unroll
            for (int mf = 0; mf < 2; mf++)
                ldsm4(af[mf], stg + ((ti * 4 + kgp * 2 + kgA) * 64 +
                                     warp_m * 32 + mf * 16 + ocA) * 16);
#pragma unroll
            for (int mf = 0; mf < 2; mf++)
#pragma unroll
                for (int nf = 0; nf < 4; nf++)
                    mma16816(acc[cl][mf][nf], af[mf], &bf[h][nf >> 1][(nf & 1) * 2]);
        }
    }
}

__device__ __forceinline__ void k2e_load_slot(
    uint32_t stg, uint32_t mbar, int strip, int ch, int b, int ocq, int tid) {
    if (tid == 0) {
        MBARRIER_EXPECT_TX(mbar, 16640u);
        const int tp2[2][3] = {{3, 4, 5}, {2, 8, 5}};   // c_tap o c_etap
        size_t base = WBLK_HALVES(b, ocq, ch);
#pragma unroll
        for (int t = 0; t < 3; t++)
            cpbulk(stg + t * 4096, g_wt2 + base + (size_t)tp2[strip][t] * 2048,
                   4096u, mbar);
        cpbulk(stg + E_XOFF,
               g_xge + ((size_t)(b * 2 + strip) * 16 + ch) * 2176, 4352u, mbar);
    }
}

__device__ __forceinline__ void k2e_compute(
    uint32_t stg, int warp_m, int warp_n, int lane, float acc[2][2][4][4]) {
    const int CL[3] = {0, 1, 0}, SF[3] = {0, 0, 1};
    int n_loc = (lane & 7) + ((lane >> 4) << 3);
    int kgB = (lane >> 3) & 1;
    int ocA = lane & 15;
    int kgA = lane >> 4;
#pragma unroll
    for (int kgp = 0; kgp < 2; kgp++) {
        uint32_t bf[2][2][4];
#pragma unroll
        for (int s = 0; s < 2; s++) {
#pragma unroll
            for (int t = 0; t < 2; t++) {
                int p = warp_n * 32 + t * 16 + n_loc;
                int slot = ((p <= 64) ? p : 65) + 1 - s;
                ldsm4(bf[s][t], stg + E_XOFF + ((kgp * 2 + kgB) * 68 + slot) * 16);
            }
        }
#pragma unroll
        for (int ti = 0; ti < 3; ti++) {
            uint32_t af[2][4];
#pragma unroll
            for (int mf = 0; mf < 2; mf++)
                ldsm4(af[mf], stg + ((ti * 4 + kgp * 2 + kgA) * 64 +
                                     warp_m * 32 + mf * 16 + ocA) * 16);
#pragma unroll
            for (int mf = 0; mf < 2; mf++)
#pragma unroll
                for (int nf = 0; nf < 4; nf++)
                    mma16816(acc[CL[ti]][mf][nf], af[mf], &bf[SF[ti]][nf >> 1][(nf & 1) * 2]);
        }
    }
}

__global__ __launch_bounds__(256, 2) void k2_mma() {
    extern __shared__ char smraw[];
    uint32_t sb = smem_u32(smraw);
    uint32_t mb = sb + 3 * STAGE;
    int tid = threadIdx.x;
    int wid = tid >> 5, lane = tid & 31;
    int warp_m = wid & 1;
    int warp_n = wid >> 1;
    int b = blockIdx.z;
    int ocq = blockIdx.y;
    int oc0 = ocq * 64;
    int bx = blockIdx.x;
    int r0 = lane >> 2, cq = lane & 3;

    if (tid == 0) {
        MBARRIER_INIT(mb + 0, 1);
        MBARRIER_INIT(mb + 8, 1);
        MBARRIER_INIT(mb + 16, 1);
    }
    __syncthreads();

    float acc[2][2][4][4];
#pragma unroll
    for (int c = 0; c < 2; c++)
#pragma unroll
        for (int mf = 0; mf < 2; mf++)
#pragma unroll
            for (int nf = 0; nf < 4; nf++)
#pragma unroll
                for (int k = 0; k < 4; k++) acc[c][mf][nf][k] = 0.f;

    if (bx < 32) {
        int x0 = (bx & 3) * 16, y0 = (bx >> 2) * 8;
        for (int s = 0; s < 2; s++)
            k2_load_slot(sb + s * STAGE, mb + s * 8, 0, s, b, ocq, bx, tid);
        for (int slot = 0; slot < 32; slot++) {
            MBARRIER_WAIT_PARITY(mb + (slot % 3) * 8, (slot / 3) & 1);
            __syncthreads();
            int nx = slot + 2;
            if (nx < 32)
                k2_load_slot(sb + (nx % 3) * STAGE, mb + (nx % 3) * 8,
                             nx >> 4, nx & 15, b, ocq, bx, tid);

            uint32_t stg = sb + (slot % 3) * STAGE;
            if (slot < 16) k2_compute<0>(stg, warp_m, warp_n, lane, acc);
            else           k2_compute<1>(stg, warp_m, warp_n, lane, acc);

            if (slot == 15 || slot == 31) {
                int p = slot >> 4;
#pragma unroll
                for (int mf = 0; mf < 2; mf++)
#pragma unroll
                    for (int rr = 0; rr < 2; rr++) {
                        int oc = oc0 + warp_m * 32 + mf * 16 + rr * 8 + r0;
                        size_t rowb = ((size_t)b * COUT + oc) * OBR;
#pragma unroll
                        for (int nf = 0; nf < 4; nf++) {
                            int m = y0 + warp_n * 2 + (nf >> 1);
                            int n = x0 + (nf & 1) * 8 + cq * 2;
                            int row = 2 * m + p;
                            __half2 lo = __floats2half2_rn(acc[0][mf][nf][rr * 2],
                                                           acc[1][mf][nf][rr * 2]);
                            __half2 hi = __floats2half2_rn(acc[0][mf][nf][rr * 2 + 1],
                                                           acc[1][mf][nf][rr * 2 + 1]);
                            uint2 v = make_uint2(*(uint32_t*)&lo, *(uint32_t*)&hi);
                            *(uint2*)&g_obh[(rowb + row) * OBP + 2 * n] = v;
                        }
                    }
                if (slot == 15) {
#pragma unroll
                    for (int c = 0; c < 2; c++)
#pragma unroll
                        for (int mf = 0; mf < 2; mf++)
#pragma unroll
                            for (int nf = 0; nf < 4; nf++)
#pragma unroll
                                for (int k = 0; k < 4; k++) acc[c][mf][nf][k] = 0.f;
                }
            }
        }
    } else {
        int strip = bx - 32;
        for (int s = 0; s < 2; s++)
            k2e_load_slot(sb + s * E_STAGE, mb + s * 8, strip, s, b, ocq, tid);
        for (int slot = 0; slot < 16; slot++) {
            MBARRIER_WAIT_PARITY(mb + (slot % 3) * 8, (slot / 3) & 1);
            __syncthreads();
            int nx = slot + 2;
            if (nx < 16)
                k2e_load_slot(sb + (nx % 3) * E_STAGE, mb + (nx % 3) * 8,
                              strip, nx, b, ocq, tid);
            k2e_compute(sb + (slot % 3) * E_STAGE, warp_m, warp_n, lane, acc);
        }
#pragma unroll
        for (int mf = 0; mf < 2; mf++)
#pragma unroll
            for (int rr = 0; rr < 2; rr++) {
                int oc = oc0 + warp_m * 32 + mf * 16 + rr * 8 + r0;
                size_t rowb = ((size_t)b * COUT + oc) * OBR;
#pragma unroll
                for (int nf = 0; nf < 4; nf++) {
#pragma unroll
                    for (int kk = 0; kk < 2; kk++) {
                        int p = warp_n * 32 + (nf >> 1) * 16 + (nf & 1) * 8 + cq * 2 + kk;
#pragma unroll
                        for (int cls = 0; cls < 2; cls++) {
                            float val = acc[cls][mf][nf][rr * 2 + kk];
                            if (strip == 0) {
                                int col = 2 * p + cls;
                                if (col <= 128)
                                    g_obh[(rowb + 128) * OBP + col] = __float2half_rn(val);
                            } else {
                                if (p <= 63)
                                    g_obh[(rowb + 2 * p + cls) * OBP + 128] =
                                        __float2half_rn(val);
                            }
                        }
                    }
                }
            }
    }
}

// ---------------------------------------------------------------------------
// K3: separable 4x4 blur + noise + bias + leaky_relu(0.2)*sqrt(2).
// uint2 (8B) row loads; sraw/tmp are 16B-aligned (required for uint2/float4).
// sraw half index = rx + 4.
// ---------------------------------------------------------------------------
__global__ __launch_bounds__(256) void k3_blur(const float* __restrict__ noise,
                                               const float* __restrict__ noise_w,
                                               const float* __restrict__ act_b,
                                               float* __restrict__ out) {
    __shared__ __align__(16) __half sraw[35][140];
    __shared__ __align__(16) float tmp[35][128];
    int tid = threadIdx.x;
    int y0 = blockIdx.x * 32;
    int bc = blockIdx.y;
    int oc = bc & 255, b = bc >> 8;
    size_t obc = (size_t)bc * OBR;

    if (tid < 35) *(uint2*)&sraw[tid][0] = make_uint2(0, 0);  // halo rx=-4..-1

    // 33 uint2 per row: cols 4j .. 4j+3 (j=32 keeps col 128, zeros 129..131)
    for (int idx = tid; idx < 35 * 33; idx += 256) {
        int i = idx / 33, j = idx - i * 33;
        int ry = y0 - 1 + i;
        uint2 v = make_uint2(0, 0);
        if ((unsigned)ry <= 128u) {
            v = *(const uint2*)&g_obh[(obc + ry) * OBP + 4 * j];
            if (j == 32) { v.x &= 0xFFFFu; v.y = 0; }
        }
        *(uint2*)&sraw[i][4 + 4 * j] = v;
    }
    __syncthreads();

    // horizontal: out col x <- rx = x-1..x+2 = sraw idx x+3..x+6
    for (int task = tid; task < 35 * 32; task += 256) {
        int i = task >> 5, xb = (task & 31) * 4;
        float s1 = __half2float(sraw[i][xb + 3]);
        float s2 = __half2float(sraw[i][xb + 4]);
        float s3 = __half2float(sraw[i][xb + 5]);
        float s4 = __half2float(sraw[i][xb + 6]);
        float s5 = __half2float(sraw[i][xb + 7]);
        float s6 = __half2float(sraw[i][xb + 8]);
        float s7 = __half2float(sraw[i][xb + 9]);
        tmp[i][xb + 0] = 0.25f * (s1 + s4) + 0.75f * (s2 + s3);
        tmp[i][xb + 1] = 0.25f * (s2 + s5) + 0.75f * (s3 + s4);
        tmp[i][xb + 2] = 0.25f * (s3 + s6) + 0.75f * (s4 + s5);
        tmp[i][xb + 3] = 0.25f * (s4 + s7) + 0.75f * (s5 + s6);
    }
    __syncthreads();

    float nw = noise_w[0];
    float ab = act_b[oc];
    int xq = (tid & 31) * 4, tyg = tid >> 5;
#pragma unroll
    for (int r = 0; r < 4; r++) {
        int ly = tyg + 8 * r;
        float4 t0 = *(const float4*)&tmp[ly][xq];
        float4 t1 = *(const float4*)&tmp[ly + 1][xq];
        float4 t2 = *(const float4*)&tmp[ly + 2][xq];
        float4 t3 = *(const float4*)&tmp[ly + 3][xq];
        int y = y0 + ly;
        float4 nz = *(const float4*)&noise[((size_t)b * FHW + y) * FHW + xq];
        float4 o;
        o.x = 0.25f * (t0.x + t3.x) + 0.75f * (t1.x + t2.x) + nw * nz.x + ab;
        o.y = 0.25f * (t0.y + t3.y) + 0.75f * (t1.y + t2.y) + nw * nz.y + ab;
        o.z = 0.25f * (t0.z + t3.z) + 0.75f * (t1.z + t2.z) + nw * nz.z + ab;
        o.w = 0.25f * (t0.w + t3.w) + 0.75f * (t1.w + t2.w) + nw * nz.w + ab;
        o.x = (o.x > 0.f ? o.x : 0.2f * o.x) * 1.4142135623730951f;
        o.y = (o.y > 0.f ? o.y : 0.2f * o.y) * 1.4142135623730951f;
        o.z = (o.z > 0.f ? o.z : 0.2f * o.z) * 1.4142135623730951f;
        o.w = (o.w > 0.f ? o.w : 0.2f * o.w) * 1.4142135623730951f;
        *(float4*)&out[((size_t)bc * FHW + y) * FHW + xq] = o;
    }
}

// ---------------------------------------------------------------------------
extern "C" void kernel_launch(void* const* d_in, const int* in_sizes, int n_in,
                              void* d_out, int out_size) {
    const float* x       = (const float*)d_in[0];
    const float* style   = (const float*)d_in[1];
    const float* noise   = (const float*)d_in[2];
    const float* weight  = (const float*)d_in[3];
    const float* mod_w   = (const float*)d_in[4];
    const float* mod_b   = (const float*)d_in[5];
    const float* noise_w = (const float*)d_in[6];
    const float* act_b   = (const float*)d_in[7];
    float* out = (float*)d_out;

    cudaFuncSetAttribute(k2_mma, cudaFuncAttributeMaxDynamicSharedMemorySize, K2_SMEM);

    k0_style<<<dim3(16, BN), 256>>>(style, mod_w, mod_b);
    k_prep<<<10240, 512>>>(weight, x);
    k2_mma<<<dim3(34, 4, BN), 256, K2_SMEM>>>();
    k3_blur<<<dim3(4, 2048), 256>>>(noise, noise_w, act_b, out);
}